// round 8
// baseline (speedup 1.0000x reference)
#include <cuda_runtime.h>
#include <cuda_bf16.h>
#include <cstdint>
#include <cstddef>

#define N_U 100000
#define N_I 50000
#define DD  64
#define QQ  5
#define NNZ_E 1000000
#define BB  512

typedef unsigned long long ull;

// ------------------------- scratch (device globals) -------------------------
__device__ __align__(16) float g_Z[(size_t)(N_U + N_I) * DD];    // Zu1, Zi1
__device__ __align__(16) float g_Ef[(size_t)(N_U + N_I) * DD];   // Euf, Eif (final E, aligned)
__device__ __align__(16) float g_small[2304];  // Mu(320) Mi(320) su(512) si(1024) sc(8)
__device__ __align__(16) float g_G[3 * BB * DD];   // Gu(512) + Gi(1024) rows, x5-folded

#define OFF_MU 0
#define OFF_MI 320
#define OFF_SU 640
#define OFF_SI 1152
#define OFF_SC 2176

// ------------------------------ helpers -------------------------------------
__device__ __forceinline__ ull ffma2(ull a, ull b, ull c) {
    ull d;
    asm("fma.rn.f32x2 %0, %1, %2, %3;" : "=l"(d) : "l"(a), "l"(b), "l"(c));
    return d;
}
__device__ __forceinline__ ull pack_dup(float a) {
    ull r; unsigned u = __float_as_uint(a);
    asm("mov.b64 %0, {%1, %1};" : "=l"(r) : "r"(u));
    return r;
}
__device__ __forceinline__ float warp_sum(float v) {
    #pragma unroll
    for (int o = 16; o; o >>= 1) v += __shfl_xor_sync(0xffffffffu, v, o);
    return v;
}

// --------------------------------- SpMM --------------------------------------
// both directions in one launch; 4 edges/thread, front-batched gathers (MLP=4)
__global__ void spmm_dual(const float* __restrict__ vals,
                          const int* __restrict__ rows,
                          const int* __restrict__ cols,
                          const float* __restrict__ Xu,
                          const float* __restrict__ Xi,
                          float* __restrict__ Yu,
                          float* __restrict__ Yi) {
    const int half = gridDim.x >> 1;
    const bool dirU = blockIdx.x < half;
    const int bid = dirU ? blockIdx.x : blockIdx.x - half;
    const int t = bid * blockDim.x + threadIdx.x;
    const int e = t >> 4, lane = t & 15;
    const int E4 = NNZ_E / 4;
    if (e >= E4) return;
    const int* src = dirU ? cols : rows;
    const int* dst = dirU ? rows : cols;
    const float* X = dirU ? Xi : Xu;
    float* Y = dirU ? Yu : Yi;

    int e0 = e, e1 = e + E4, e2 = e + 2 * E4, e3 = e + 3 * E4;
    float v0 = __ldg(vals + e0), v1 = __ldg(vals + e1);
    float v2 = __ldg(vals + e2), v3 = __ldg(vals + e3);
    int c0 = __ldg(src + e0), c1 = __ldg(src + e1);
    int c2 = __ldg(src + e2), c3 = __ldg(src + e3);
    int r0 = __ldg(dst + e0), r1 = __ldg(dst + e1);
    int r2 = __ldg(dst + e2), r3 = __ldg(dst + e3);
    float4 x0 = ((const float4*)(X + (size_t)c0 * DD))[lane];
    float4 x1 = ((const float4*)(X + (size_t)c1 * DD))[lane];
    float4 x2 = ((const float4*)(X + (size_t)c2 * DD))[lane];
    float4 x3 = ((const float4*)(X + (size_t)c3 * DD))[lane];
    atomicAdd(((float4*)(Y + (size_t)r0 * DD)) + lane,
              make_float4(v0 * x0.x, v0 * x0.y, v0 * x0.z, v0 * x0.w));
    atomicAdd(((float4*)(Y + (size_t)r1 * DD)) + lane,
              make_float4(v1 * x1.x, v1 * x1.y, v1 * x1.z, v1 * x1.w));
    atomicAdd(((float4*)(Y + (size_t)r2 * DD)) + lane,
              make_float4(v2 * x2.x, v2 * x2.y, v2 * x2.z, v2 * x2.w));
    atomicAdd(((float4*)(Y + (size_t)r3 * DD)) + lane,
              make_float4(v3 * x3.x, v3 * x3.y, v3 * x3.z, v3 * x3.w));
}

// ------------------------- prep: Ef = E0+Z1 ; M, reg -------------------------
__global__ void prep_kernel(const float* __restrict__ E0,
                            const float* __restrict__ Z1,
                            const float* __restrict__ P, int n_rows,
                            float* __restrict__ Ef,
                            float* __restrict__ Macc,
                            float* __restrict__ regAcc) {
    int d = threadIdx.x & 63;
    int grp = threadIdx.x >> 6;                 // 0..3
    float m0 = 0, m1 = 0, m2 = 0, m3 = 0, m4 = 0, racc = 0;
    for (int r = blockIdx.x * 4 + grp; r < n_rows; r += gridDim.x * 4) {
        size_t off = (size_t)r * DD + d;
        float e0 = E0[off];
        float t  = e0 + Z1[off];
        Ef[off] = t;
        racc = fmaf(e0, e0, racc);
        m0 = fmaf(__ldg(P + r), t, m0);
        m1 = fmaf(__ldg(P + (size_t)n_rows + r), t, m1);
        m2 = fmaf(__ldg(P + 2 * (size_t)n_rows + r), t, m2);
        m3 = fmaf(__ldg(P + 3 * (size_t)n_rows + r), t, m3);
        m4 = fmaf(__ldg(P + 4 * (size_t)n_rows + r), t, m4);
    }
    __shared__ float sm[4][QQ][DD];
    sm[grp][0][d] = m0; sm[grp][1][d] = m1; sm[grp][2][d] = m2;
    sm[grp][3][d] = m3; sm[grp][4][d] = m4;
    __syncthreads();
    if (grp == 0) {
        #pragma unroll
        for (int q = 0; q < QQ; q++)
            atomicAdd(&Macc[q * DD + d],
                      sm[0][q][d] + sm[1][q][d] + sm[2][q][d] + sm[3][q][d]);
    }
    racc = warp_sum(racc);
    if ((threadIdx.x & 31) == 0) atomicAdd(regAcc, racc);
}

// -------------------- copy aligned Ef -> misaligned d_out --------------------
__global__ void copyout_kernel(const float* __restrict__ Ef,
                               float* __restrict__ Eout, size_t n4) {
    size_t i = (size_t)blockIdx.x * blockDim.x + threadIdx.x;
    if (i >= n4) return;
    float4 v = ((const float4*)Ef)[i];
    float* o = Eout + i * 4;
    o[0] = v.x; o[1] = v.y; o[2] = v.z; o[3] = v.w;
}

// ------------------------------ G selection ----------------------------------
__global__ void gsel_kernel(const int* __restrict__ uids,
                            const int* __restrict__ pos,
                            const int* __restrict__ neg,
                            const float* __restrict__ Eu0,
                            const float* __restrict__ Ei0,
                            const float* __restrict__ mu_s,
                            const float* __restrict__ mi_s,
                            const float* __restrict__ Mu,
                            const float* __restrict__ Mi,
                            float* __restrict__ G) {
    int b = blockIdx.x, d = threadIdx.x;
    const float* E0; const float* ms; const float* M; int id;
    if (b < 512)       { E0 = Eu0; ms = mu_s; M = Mu; id = uids[b]; }
    else if (b < 1024) { E0 = Ei0; ms = mi_s; M = Mi; id = pos[b - 512]; }
    else               { E0 = Ei0; ms = mi_s; M = Mi; id = neg[b - 1024]; }
    float v = E0[(size_t)id * DD + d];
    #pragma unroll
    for (int q = 0; q < QQ; q++)
        v = fmaf(ms[(size_t)id * QQ + q], M[q * DD + d], v);
    G[b * DD + d] = 5.0f * v;
}

// ---------------- SIMT logits: 128x128 tiled GEMM + exp + row-sum ------------
// smem: Gd (dup f32x2) [64k][128m] = 64KB ; Ep (col pairs (n, n+64)) [64k][64] = 32KB
// mainloop: b = 4x LDS.64 (conflict-free), g = 4x LDS.128 (broadcast).
#define SMEM_LG (96 * 1024)
__global__ __launch_bounds__(256, 2)
void logits_simt(const float* __restrict__ G, int Mtiles,
                 const float* __restrict__ Ef, int N,
                 float* __restrict__ S) {
    extern __shared__ char smc[];
    ull* Gd = (ull*)smc;                 // [k*128 + m], value duplicated
    ull* Ep = (ull*)(smc + 65536);       // [k*64 + c], lo=E[n0+c], hi=E[n0+c+64]
    const int tid = threadIdx.x;
    const int mt = blockIdx.x % Mtiles;
    const long n0 = (long)(blockIdx.x / Mtiles) * 128;

    #pragma unroll
    for (int it = 0; it < 8; it++) {
        int idx = it * 256 + tid;
        int kc = idx >> 7, row = idx & 127;
        float4 g = *(const float4*)(G + ((size_t)(mt * 128 + row)) * DD + kc * 4);
        Gd[(kc * 4 + 0) * 128 + row] = pack_dup(g.x);
        Gd[(kc * 4 + 1) * 128 + row] = pack_dup(g.y);
        Gd[(kc * 4 + 2) * 128 + row] = pack_dup(g.z);
        Gd[(kc * 4 + 3) * 128 + row] = pack_dup(g.w);
    }
    float* Epf = (float*)Ep;
    #pragma unroll
    for (int it = 0; it < 8; it++) {
        int idx = it * 256 + tid;
        int kc = idx >> 7, row = idx & 127;
        long n = n0 + row;
        float4 e = make_float4(0.f, 0.f, 0.f, 0.f);
        if (n < N) e = *(const float4*)(Ef + n * DD + kc * 4);
        int c = row & 63, hi = row >> 6;
        Epf[((kc * 4 + 0) * 64 + c) * 2 + hi] = e.x;
        Epf[((kc * 4 + 1) * 64 + c) * 2 + hi] = e.y;
        Epf[((kc * 4 + 2) * 64 + c) * 2 + hi] = e.z;
        Epf[((kc * 4 + 3) * 64 + c) * 2 + hi] = e.w;
    }
    __syncthreads();

    const int tx = tid & 15, ty = tid >> 4;
    ull acc[8][4];
    #pragma unroll
    for (int i = 0; i < 8; i++)
        #pragma unroll
        for (int j = 0; j < 4; j++) acc[i][j] = 0ull;

    const ull* gp = Gd + ty * 8;
    const ull* ep = Ep + tx;
    #pragma unroll 4
    for (int k = 0; k < 64; k++) {
        ull b0 = ep[0], b1 = ep[16], b2 = ep[32], b3 = ep[48];
        // g: same addresses as before, but 4x LDS.128 instead of 8x LDS.64
        ulonglong2 g01 = *(const ulonglong2*)(gp + 0);
        ulonglong2 g23 = *(const ulonglong2*)(gp + 2);
        ulonglong2 g45 = *(const ulonglong2*)(gp + 4);
        ulonglong2 g67 = *(const ulonglong2*)(gp + 6);
        ull g[8] = { g01.x, g01.y, g23.x, g23.y, g45.x, g45.y, g67.x, g67.y };
        #pragma unroll
        for (int i = 0; i < 8; i++) {
            acc[i][0] = ffma2(g[i], b0, acc[i][0]);
            acc[i][1] = ffma2(g[i], b1, acc[i][1]);
            acc[i][2] = ffma2(g[i], b2, acc[i][2]);
            acc[i][3] = ffma2(g[i], b3, acc[i][3]);
        }
        gp += 128; ep += 64;
    }

    // epilogue: exp (MUFU.EX2 via __expf) + row-sum (logits already x5 via G)
    bool full = (n0 + 128 <= N);
    #pragma unroll
    for (int i = 0; i < 8; i++) {
        float s = 0.f;
        #pragma unroll
        for (int j = 0; j < 4; j++) {
            float lo = __uint_as_float((unsigned)acc[i][j]);
            float hi = __uint_as_float((unsigned)(acc[i][j] >> 32));
            if (full) {
                s += __expf(lo) + __expf(hi);
            } else {
                long n = n0 + tx + 16 * j;
                if (n < N)      s += __expf(lo);
                if (n + 64 < N) s += __expf(hi);
            }
        }
        s += __shfl_xor_sync(0xffffffffu, s, 1);
        s += __shfl_xor_sync(0xffffffffu, s, 2);
        s += __shfl_xor_sync(0xffffffffu, s, 4);
        s += __shfl_xor_sync(0xffffffffu, s, 8);
        if (tx == 0) atomicAdd(&S[mt * 128 + ty * 8 + i], s);
    }
}

// -------------------- pos / BPR / extra-loss (warp-per-task) -----------------
__global__ void small_loss_kernel(const int* __restrict__ uids,
                                  const int* __restrict__ pos,
                                  const int* __restrict__ neg,
                                  const float* __restrict__ Eu,
                                  const float* __restrict__ Ei,
                                  const float* __restrict__ Gu,
                                  const float* __restrict__ Gi,
                                  const int* __restrict__ unpop,
                                  const int* __restrict__ popi,
                                  float* __restrict__ sc) {
    int gtid = blockIdx.x * blockDim.x + threadIdx.x;
    int wid = gtid >> 5, lane = gtid & 31;
    if (wid < 512) {                       // pos_u
        int b = wid, u = uids[b];
        float s = Gu[b * DD + lane] * Eu[(size_t)u * DD + lane]
                + Gu[b * DD + 32 + lane] * Eu[(size_t)u * DD + 32 + lane];
        s = warp_sum(s);
        if (lane == 0) atomicAdd(&sc[1], fminf(fmaxf(s, -5.0f), 5.0f));
    } else if (wid < 1536) {               // pos_i
        int b = wid - 512;
        int id = (b < 512) ? pos[b] : neg[b - 512];
        float s = Gi[b * DD + lane] * Ei[(size_t)id * DD + lane]
                + Gi[b * DD + 32 + lane] * Ei[(size_t)id * DD + 32 + lane];
        s = warp_sum(s);
        if (lane == 0) atomicAdd(&sc[2], fminf(fmaxf(s, -5.0f), 5.0f));
    } else if (wid < 2048) {               // BPR
        int b = wid - 1536, u = uids[b], p = pos[b], nn = neg[b];
        float eu0 = Eu[(size_t)u * DD + lane], eu1 = Eu[(size_t)u * DD + 32 + lane];
        float sp = eu0 * Ei[(size_t)p * DD + lane]  + eu1 * Ei[(size_t)p * DD + 32 + lane];
        float sn = eu0 * Ei[(size_t)nn * DD + lane] + eu1 * Ei[(size_t)nn * DD + 32 + lane];
        sp = warp_sum(sp);
        sn = warp_sum(sn);
        if (lane == 0) {
            float x = sp - sn;
            float t = (x > 0.f) ? log1pf(expf(-x)) : (-x + log1pf(expf(x)));
            atomicAdd(&sc[3], t);
        }
    } else {                               // extra-loss pairs
        int p = wid - 2048;
        if (p >= 64 * 8 * 32) return;
        int ig = p >> 8, rem = p & 255, ui = rem >> 5, pi = rem & 31;
        int a = unpop[ig * 8 + ui];
        int c = popi[ig * 32 + pi];
        float d0 = Ei[(size_t)a * DD + lane] - Ei[(size_t)c * DD + lane];
        float d1 = Ei[(size_t)a * DD + 32 + lane] - Ei[(size_t)c * DD + 32 + lane];
        float s = warp_sum(d0 * d0 + d1 * d1);
        if (lane == 0) atomicAdd(&sc[4], sqrtf(s));
    }
}

// ------------------------------ weight L2 reg --------------------------------
__global__ void reg_w_kernel(const float* __restrict__ W1,
                             const float* __restrict__ b1,
                             const float* __restrict__ W2,
                             const float* __restrict__ b2,
                             float* __restrict__ acc) {
    int t = blockIdx.x * blockDim.x + threadIdx.x;
    int total = gridDim.x * blockDim.x;
    float s = 0.f;
    for (int i = t; i < 768 * 64; i += total) {
        float a = W1[i]; s = fmaf(a, a, s);
        float c = W2[i]; s = fmaf(c, c, s);
    }
    if (t < 64) {
        float a = b1[t]; s = fmaf(a, a, s);
        float c = b2[t]; s = fmaf(c, c, s);
    }
    s = warp_sum(s);
    if ((threadIdx.x & 31) == 0) atomicAdd(acc, s);
}

// -------------------------------- finalize -----------------------------------
__global__ void finalize_kernel(const float* __restrict__ su,
                                const float* __restrict__ si,
                                const float* __restrict__ sc,
                                float* __restrict__ out) {
    __shared__ float s_lu[16], s_li[16];
    int tid = threadIdx.x;   // 512 threads
    float lu = logf(su[tid] + 1e-8f);
    float li = logf(si[tid] + 1e-8f) + logf(si[tid + 512] + 1e-8f);
    lu = warp_sum(lu);
    li = warp_sum(li);
    if ((tid & 31) == 0) { s_lu[tid >> 5] = lu; s_li[tid >> 5] = li; }
    __syncthreads();
    if (tid == 0) {
        float LU = 0.f, LI = 0.f;
        #pragma unroll
        for (int w = 0; w < 16; w++) { LU += s_lu[w]; LI += s_li[w]; }
        float neg_score = LU / 512.f + LI / 1024.f;
        float pos_score = sc[1] / 512.f + sc[2] / 1024.f;
        float loss_s = -pos_score + neg_score;
        float loss_r = sc[3] / 512.f;
        float loss_reg = 1e-7f * sc[0];
        float extra = sc[4] * (1.f / 32.f);
        float loss = loss_r + 0.2f * loss_s + loss_reg + 0.01f * extra;
        out[0] = loss;
        out[1] = loss_r;
        out[2] = 0.2f * loss_s;
    }
}

// ------------------------------- launcher ------------------------------------
extern "C" void kernel_launch(void* const* d_in, const int* in_sizes, int n_in,
                              void* d_out, int out_size) {
    const int*   uids     = (const int*)d_in[0];
    const int*   pos      = (const int*)d_in[1];
    const int*   neg      = (const int*)d_in[2];
    const int*   adj_rows = (const int*)d_in[3];
    const int*   adj_cols = (const int*)d_in[4];
    const float* adj_vals = (const float*)d_in[5];
    const float* E_u_0    = (const float*)d_in[6];
    const float* E_i_0    = (const float*)d_in[7];
    const float* u_mul_s  = (const float*)d_in[8];
    const float* vt       = (const float*)d_in[9];
    const float* v_mul_s  = (const float*)d_in[10];
    const float* ut       = (const float*)d_in[11];
    const float* W_api    = (const float*)d_in[12];
    const float* b_api    = (const float*)d_in[13];
    const float* W_mashup = (const float*)d_in[14];
    const float* b_mashup = (const float*)d_in[15];
    const float* pos_api  = (const float*)d_in[16];
    const float* neg_api  = (const float*)d_in[17];
    const float* mashup   = (const float*)d_in[18];
    const int*   unpop    = (const int*)d_in[19];
    const int*   popi     = (const int*)d_in[20];

    float* out = (float*)d_out;
    const size_t EMB = (size_t)512 * 768;
    float* out_mashup = out + 3;
    float* out_posapi = out + 3 + EMB;
    float* out_negapi = out + 3 + 2 * EMB;
    float* Eu_out = out + 3 + 3 * EMB;   // Ei_out contiguous after

    float *Zb, *Efb, *Sm, *G;
    cudaGetSymbolAddress((void**)&Zb,  g_Z);
    cudaGetSymbolAddress((void**)&Efb, g_Ef);
    cudaGetSymbolAddress((void**)&Sm,  g_small);
    cudaGetSymbolAddress((void**)&G,   g_G);

    float* Zu1 = Zb;
    float* Zi1 = Zu1 + (size_t)N_U * DD;
    float* Euf = Efb;
    float* Eif = Euf + (size_t)N_U * DD;
    float* Mu = Sm + OFF_MU;
    float* Mi = Sm + OFF_MI;
    float* su = Sm + OFF_SU;
    float* si = Sm + OFF_SI;
    float* sc = Sm + OFF_SC;
    float* Gu = G;
    float* Gi = G + (size_t)BB * DD;

    cudaMemsetAsync(Zb, 0, (size_t)(N_U + N_I) * DD * 4);
    cudaMemsetAsync(Sm, 0, 2304 * 4);

    cudaMemcpyAsync(out_mashup, mashup, EMB * 4, cudaMemcpyDeviceToDevice);
    cudaMemcpyAsync(out_posapi, pos_api, EMB * 4, cudaMemcpyDeviceToDevice);
    cudaMemcpyAsync(out_negapi, neg_api, EMB * 4, cudaMemcpyDeviceToDevice);

    const int spmm_blocks = 2 * (((NNZ_E / 4) * 16 + 255) / 256);
    spmm_dual<<<spmm_blocks, 256>>>(adj_vals, adj_rows, adj_cols,
                                    E_u_0, E_i_0, Zu1, Zi1);
    prep_kernel<<<2048, 256>>>(E_u_0, Zu1, ut, N_U, Euf, Mi, sc);
    prep_kernel<<<1024, 256>>>(E_i_0, Zi1, vt, N_I, Eif, Mu, sc);
    spmm_dual<<<spmm_blocks, 256>>>(adj_vals, adj_rows, adj_cols,
                                    Zu1, Zi1, Euf, Eif);

    reg_w_kernel<<<64, 256>>>(W_api, b_api, W_mashup, b_mashup, sc);
    gsel_kernel<<<1536, 64>>>(uids, pos, neg, E_u_0, E_i_0,
                              u_mul_s, v_mul_s, Mu, Mi, G);

    cudaFuncSetAttribute(logits_simt,
                         cudaFuncAttributeMaxDynamicSharedMemorySize, SMEM_LG);
    const int ntu = (N_U + 127) / 128;   // 782
    const int nti = (N_I + 127) / 128;   // 391
    logits_simt<<<4 * ntu, 256, SMEM_LG>>>(Gu, 4, Euf, N_U, su);
    logits_simt<<<8 * nti, 256, SMEM_LG>>>(Gi, 8, Eif, N_I, si);

    small_loss_kernel<<<2304, 256>>>(uids, pos, neg, Euf, Eif, Gu, Gi,
                                     unpop, popi, sc);

    const size_t n4 = (size_t)(N_U + N_I) * DD / 4;
    copyout_kernel<<<(int)((n4 + 255) / 256), 256>>>(Efb, Eu_out, n4);

    finalize_kernel<<<1, 512>>>(su, si, sc, out);
}

// round 11
// speedup vs baseline: 1.8294x; 1.8294x over previous
#include <cuda_runtime.h>
#include <cuda_bf16.h>
#include <cstdint>
#include <cstddef>

#define N_U 100000
#define N_I 50000
#define DD  64
#define QQ  5
#define NNZ_E 1000000
#define BB  512

typedef unsigned long long ull;

// ------------------------- scratch (device globals) -------------------------
__device__ __align__(16) float g_Z[(size_t)(N_U + N_I) * DD];    // Zu1, Zi1
__device__ __align__(16) float g_Ef[(size_t)(N_U + N_I) * DD];   // Euf, Eif (final E, fp32)
__device__ __align__(16) __nv_bfloat16 g_Eb[(size_t)(N_U + N_I) * DD];  // bf16 E
__device__ __align__(16) float g_small[2304];  // Mu(320) Mi(320) su(512) si(1024) sc(8)
__device__ __align__(16) float g_G[3 * BB * DD];            // fp32 G (x5), for small_loss
__device__ __align__(16) __nv_bfloat16 g_Gb[3 * BB * DD];   // bf16 G (x5), for mma

#define OFF_MU 0
#define OFF_MI 320
#define OFF_SU 640
#define OFF_SI 1152
#define OFF_SC 2176

// ------------------------------ helpers -------------------------------------
__device__ __forceinline__ float warp_sum(float v) {
    #pragma unroll
    for (int o = 16; o; o >>= 1) v += __shfl_xor_sync(0xffffffffu, v, o);
    return v;
}
__device__ __forceinline__ uint32_t smem_u32(const void* p) {
    uint32_t a;
    asm("{ .reg .u64 t; cvta.to.shared.u64 t, %1; cvt.u32.u64 %0, t; }" : "=r"(a) : "l"(p));
    return a;
}
__device__ __forceinline__ void ldmx4(unsigned& r0, unsigned& r1,
                                      unsigned& r2, unsigned& r3, uint32_t addr) {
    asm volatile("ldmatrix.sync.aligned.m8n8.x4.shared.b16 {%0,%1,%2,%3}, [%4];"
                 : "=r"(r0), "=r"(r1), "=r"(r2), "=r"(r3) : "r"(addr));
}
__device__ __forceinline__ void mma16816(float* d, const unsigned* a, const unsigned* b) {
    asm volatile("mma.sync.aligned.m16n8k16.row.col.f32.bf16.bf16.f32 "
                 "{%0,%1,%2,%3}, {%4,%5,%6,%7}, {%8,%9}, {%0,%1,%2,%3};"
                 : "+f"(d[0]), "+f"(d[1]), "+f"(d[2]), "+f"(d[3])
                 : "r"(a[0]), "r"(a[1]), "r"(a[2]), "r"(a[3]), "r"(b[0]), "r"(b[1]));
}

// --------------------------- SpMM (dual direction) ----------------------------
__global__ void spmm_dual(const float* __restrict__ vals,
                          const int* __restrict__ rows,
                          const int* __restrict__ cols,
                          const float* __restrict__ Xu,
                          const float* __restrict__ Xi,
                          float* __restrict__ Yu,
                          float* __restrict__ Yi) {
    const int half = gridDim.x >> 1;
    const bool dirU = blockIdx.x < half;
    const int bid = dirU ? blockIdx.x : blockIdx.x - half;
    const int t = bid * blockDim.x + threadIdx.x;
    const int e = t >> 4, lane = t & 15;
    const int E4 = NNZ_E / 4;
    if (e >= E4) return;
    const int* src = dirU ? cols : rows;
    const int* dst = dirU ? rows : cols;
    const float* X = dirU ? Xi : Xu;
    float* Y = dirU ? Yu : Yi;

    int e0 = e, e1 = e + E4, e2 = e + 2 * E4, e3 = e + 3 * E4;
    float v0 = __ldg(vals + e0), v1 = __ldg(vals + e1);
    float v2 = __ldg(vals + e2), v3 = __ldg(vals + e3);
    int c0 = __ldg(src + e0), c1 = __ldg(src + e1);
    int c2 = __ldg(src + e2), c3 = __ldg(src + e3);
    int r0 = __ldg(dst + e0), r1 = __ldg(dst + e1);
    int r2 = __ldg(dst + e2), r3 = __ldg(dst + e3);
    float4 x0 = ((const float4*)(X + (size_t)c0 * DD))[lane];
    float4 x1 = ((const float4*)(X + (size_t)c1 * DD))[lane];
    float4 x2 = ((const float4*)(X + (size_t)c2 * DD))[lane];
    float4 x3 = ((const float4*)(X + (size_t)c3 * DD))[lane];
    atomicAdd(((float4*)(Y + (size_t)r0 * DD)) + lane,
              make_float4(v0 * x0.x, v0 * x0.y, v0 * x0.z, v0 * x0.w));
    atomicAdd(((float4*)(Y + (size_t)r1 * DD)) + lane,
              make_float4(v1 * x1.x, v1 * x1.y, v1 * x1.z, v1 * x1.w));
    atomicAdd(((float4*)(Y + (size_t)r2 * DD)) + lane,
              make_float4(v2 * x2.x, v2 * x2.y, v2 * x2.z, v2 * x2.w));
    atomicAdd(((float4*)(Y + (size_t)r3 * DD)) + lane,
              make_float4(v3 * x3.x, v3 * x3.y, v3 * x3.z, v3 * x3.w));
}

// ---------------- prep (both u and i): Ef = E0+Z1 ; M, reg --------------------
__global__ void prep_both(const float* __restrict__ Eu0,
                          const float* __restrict__ Ei0,
                          const float* __restrict__ Zu1,
                          const float* __restrict__ Zi1,
                          const float* __restrict__ Put,
                          const float* __restrict__ Pvt,
                          float* __restrict__ Euf,
                          float* __restrict__ Eif,
                          float* __restrict__ Mi,
                          float* __restrict__ Mu,
                          float* __restrict__ regAcc) {
    const bool isU = blockIdx.x < 2048;
    const int vbid = isU ? blockIdx.x : blockIdx.x - 2048;
    const int vgrid = isU ? 2048 : 1024;
    const int n_rows = isU ? N_U : N_I;
    const float* E0 = isU ? Eu0 : Ei0;
    const float* Z1 = isU ? Zu1 : Zi1;
    const float* P  = isU ? Put : Pvt;
    float* Ef = isU ? Euf : Eif;
    float* Macc = isU ? Mi : Mu;

    int d = threadIdx.x & 63;
    int grp = threadIdx.x >> 6;                 // 0..3
    float m0 = 0, m1 = 0, m2 = 0, m3 = 0, m4 = 0, racc = 0;
    for (int r = vbid * 4 + grp; r < n_rows; r += vgrid * 4) {
        size_t off = (size_t)r * DD + d;
        float e0 = E0[off];
        float t  = e0 + Z1[off];
        Ef[off] = t;
        racc = fmaf(e0, e0, racc);
        m0 = fmaf(__ldg(P + r), t, m0);
        m1 = fmaf(__ldg(P + (size_t)n_rows + r), t, m1);
        m2 = fmaf(__ldg(P + 2 * (size_t)n_rows + r), t, m2);
        m3 = fmaf(__ldg(P + 3 * (size_t)n_rows + r), t, m3);
        m4 = fmaf(__ldg(P + 4 * (size_t)n_rows + r), t, m4);
    }
    __shared__ float sm[4][QQ][DD];
    sm[grp][0][d] = m0; sm[grp][1][d] = m1; sm[grp][2][d] = m2;
    sm[grp][3][d] = m3; sm[grp][4][d] = m4;
    __syncthreads();
    if (grp == 0) {
        #pragma unroll
        for (int q = 0; q < QQ; q++)
            atomicAdd(&Macc[q * DD + d],
                      sm[0][q][d] + sm[1][q][d] + sm[2][q][d] + sm[3][q][d]);
    }
    racc = warp_sum(racc);
    if ((threadIdx.x & 31) == 0) atomicAdd(regAcc, racc);
}

// -------- copyout + convert: Ef -> misaligned d_out fp32 AND bf16 copy --------
__global__ void copyout_conv(const float* __restrict__ Ef,
                             float* __restrict__ Eout,
                             __nv_bfloat16* __restrict__ Eb, size_t n4) {
    size_t i = (size_t)blockIdx.x * blockDim.x + threadIdx.x;
    if (i >= n4) return;
    float4 v = ((const float4*)Ef)[i];
    float* o = Eout + i * 4;
    o[0] = v.x; o[1] = v.y; o[2] = v.z; o[3] = v.w;
    __nv_bfloat162 lo = __floats2bfloat162_rn(v.x, v.y);
    __nv_bfloat162 hi = __floats2bfloat162_rn(v.z, v.w);
    ((__nv_bfloat162*)(Eb + i * 4))[0] = lo;
    ((__nv_bfloat162*)(Eb + i * 4))[1] = hi;
}

// ------------------------------ G selection ----------------------------------
__global__ void gsel_kernel(const int* __restrict__ uids,
                            const int* __restrict__ pos,
                            const int* __restrict__ neg,
                            const float* __restrict__ Eu0,
                            const float* __restrict__ Ei0,
                            const float* __restrict__ mu_s,
                            const float* __restrict__ mi_s,
                            const float* __restrict__ Mu,
                            const float* __restrict__ Mi,
                            float* __restrict__ G,
                            __nv_bfloat16* __restrict__ Gb) {
    int b = blockIdx.x, d = threadIdx.x;
    const float* E0; const float* ms; const float* M; int id;
    if (b < 512)       { E0 = Eu0; ms = mu_s; M = Mu; id = uids[b]; }
    else if (b < 1024) { E0 = Ei0; ms = mi_s; M = Mi; id = pos[b - 512]; }
    else               { E0 = Ei0; ms = mi_s; M = Mi; id = neg[b - 1024]; }
    float v = E0[(size_t)id * DD + d];
    #pragma unroll
    for (int q = 0; q < QQ; q++)
        v = fmaf(ms[(size_t)id * QQ + q], M[q * DD + d], v);
    float v5 = 5.0f * v;
    G[b * DD + d] = v5;
    Gb[b * DD + d] = __float2bfloat16(v5);
}

// --------- tensor-core logits: bf16 mma.16816 GEMM + exp + row-sum -----------
// CTA tile 128m x 128n x K=64. 8 warps (4m x 2n); warp tile 32m x 64n.
// smem pitch 72 bf16 (144B) -> conflict-free ldmatrix.
#define SMEM_MMA (2 * 128 * 144)
__global__ __launch_bounds__(256, 2)
void logits_mma(const __nv_bfloat16* __restrict__ Gb, int Mtiles,
                const __nv_bfloat16* __restrict__ Eb, int N,
                float* __restrict__ S) {
    extern __shared__ char smc[];
    const uint32_t sA = smem_u32(smc);
    const uint32_t sB = sA + 128 * 144;
    const int tid = threadIdx.x;
    const int mt = blockIdx.x % Mtiles;
    const long n0 = (long)(blockIdx.x / Mtiles) * 128;

    // A tile: G rows [mt*128, +128), 64 bf16 (= 8 uint4 chunks) each
    #pragma unroll
    for (int it = 0; it < 4; it++) {
        int idx = it * 256 + tid;          // 0..1023
        int row = idx >> 3, c = idx & 7;
        uint4 v = *(const uint4*)(Gb + ((size_t)(mt * 128 + row)) * DD + c * 8);
        *(uint4*)(smc + row * 144 + c * 16) = v;
    }
    // B tile: E rows [n0, n0+128), zero-padded
    #pragma unroll
    for (int it = 0; it < 4; it++) {
        int idx = it * 256 + tid;
        int row = idx >> 3, c = idx & 7;
        long n = n0 + row;
        uint4 v = make_uint4(0, 0, 0, 0);
        if (n < N) v = *(const uint4*)(Eb + n * DD + c * 8);
        *(uint4*)(smc + 128 * 144 + row * 144 + c * 16) = v;
    }
    __syncthreads();

    const int wid = tid >> 5, lane = tid & 31;
    const int wm = (wid & 3) * 32;       // warp m base
    const int wn = (wid >> 2) * 64;      // warp n base

    float d[2][8][4];
    #pragma unroll
    for (int mi = 0; mi < 2; mi++)
        #pragma unroll
        for (int ni = 0; ni < 8; ni++)
            #pragma unroll
            for (int j = 0; j < 4; j++) d[mi][ni][j] = 0.f;

    // ldmatrix lane address components
    const int lrowA = (lane & 7) + ((lane & 8) ? 8 : 0);
    const int lcolA = (lane & 16) ? 8 : 0;
    const int lrowB = (lane & 7) + ((lane & 16) ? 8 : 0);
    const int lcolB = (lane & 8) ? 8 : 0;

    #pragma unroll
    for (int ks = 0; ks < 4; ks++) {
        const int k0 = ks * 16;
        unsigned a[2][4];
        #pragma unroll
        for (int mi = 0; mi < 2; mi++) {
            uint32_t addr = sA + (wm + mi * 16 + lrowA) * 144 + (k0 + lcolA) * 2;
            ldmx4(a[mi][0], a[mi][1], a[mi][2], a[mi][3], addr);
        }
        #pragma unroll
        for (int np = 0; np < 4; np++) {           // pairs of n-tiles
            unsigned b[4];
            uint32_t addr = sB + (wn + np * 16 + lrowB) * 144 + (k0 + lcolB) * 2;
            ldmx4(b[0], b[1], b[2], b[3], addr);
            #pragma unroll
            for (int mi = 0; mi < 2; mi++) {
                mma16816(d[mi][np * 2 + 0], a[mi], b + 0);
                mma16816(d[mi][np * 2 + 1], a[mi], b + 2);
            }
        }
    }

    // epilogue: exp + row-sum. D frag: d0,d1 = row lane/4, cols 2(lane%4)+{0,1};
    // d2,d3 = row lane/4 + 8, same cols.
    const bool full = (n0 + 128 <= N);
    const int r4 = lane >> 2;
    #pragma unroll
    for (int mi = 0; mi < 2; mi++) {
        float slo = 0.f, shi = 0.f;
        #pragma unroll
        for (int ni = 0; ni < 8; ni++) {
            if (full) {
                slo += __expf(d[mi][ni][0]) + __expf(d[mi][ni][1]);
                shi += __expf(d[mi][ni][2]) + __expf(d[mi][ni][3]);
            } else {
                long c = n0 + wn + ni * 8 + (lane & 3) * 2;
                if (c < N)     { slo += __expf(d[mi][ni][0]); shi += __expf(d[mi][ni][2]); }
                if (c + 1 < N) { slo += __expf(d[mi][ni][1]); shi += __expf(d[mi][ni][3]); }
            }
        }
        slo += __shfl_xor_sync(0xffffffffu, slo, 1);
        slo += __shfl_xor_sync(0xffffffffu, slo, 2);
        shi += __shfl_xor_sync(0xffffffffu, shi, 1);
        shi += __shfl_xor_sync(0xffffffffu, shi, 2);
        if ((lane & 3) == 0) {
            atomicAdd(&S[mt * 128 + wm + mi * 16 + r4], slo);
            atomicAdd(&S[mt * 128 + wm + mi * 16 + 8 + r4], shi);
        }
    }
}

// -------------------- pos / BPR / extra-loss (warp-per-task) -----------------
__global__ void small_loss_kernel(const int* __restrict__ uids,
                                  const int* __restrict__ pos,
                                  const int* __restrict__ neg,
                                  const float* __restrict__ Eu,
                                  const float* __restrict__ Ei,
                                  const float* __restrict__ Gu,
                                  const float* __restrict__ Gi,
                                  const int* __restrict__ unpop,
                                  const int* __restrict__ popi,
                                  float* __restrict__ sc) {
    int gtid = blockIdx.x * blockDim.x + threadIdx.x;
    int wid = gtid >> 5, lane = gtid & 31;
    if (wid < 512) {                       // pos_u
        int b = wid, u = uids[b];
        float s = Gu[b * DD + lane] * Eu[(size_t)u * DD + lane]
                + Gu[b * DD + 32 + lane] * Eu[(size_t)u * DD + 32 + lane];
        s = warp_sum(s);
        if (lane == 0) atomicAdd(&sc[1], fminf(fmaxf(s, -5.0f), 5.0f));
    } else if (wid < 1536) {               // pos_i
        int b = wid - 512;
        int id = (b < 512) ? pos[b] : neg[b - 512];
        float s = Gi[b * DD + lane] * Ei[(size_t)id * DD + lane]
                + Gi[b * DD + 32 + lane] * Ei[(size_t)id * DD + 32 + lane];
        s = warp_sum(s);
        if (lane == 0) atomicAdd(&sc[2], fminf(fmaxf(s, -5.0f), 5.0f));
    } else if (wid < 2048) {               // BPR
        int b = wid - 1536, u = uids[b], p = pos[b], nn = neg[b];
        float eu0 = Eu[(size_t)u * DD + lane], eu1 = Eu[(size_t)u * DD + 32 + lane];
        float sp = eu0 * Ei[(size_t)p * DD + lane]  + eu1 * Ei[(size_t)p * DD + 32 + lane];
        float sn = eu0 * Ei[(size_t)nn * DD + lane] + eu1 * Ei[(size_t)nn * DD + 32 + lane];
        sp = warp_sum(sp);
        sn = warp_sum(sn);
        if (lane == 0) {
            float x = sp - sn;
            float t = (x > 0.f) ? log1pf(expf(-x)) : (-x + log1pf(expf(x)));
            atomicAdd(&sc[3], t);
        }
    } else {                               // extra-loss pairs
        int p = wid - 2048;
        if (p >= 64 * 8 * 32) return;
        int ig = p >> 8, rem = p & 255, ui = rem >> 5, pi = rem & 31;
        int a = unpop[ig * 8 + ui];
        int c = popi[ig * 32 + pi];
        float d0 = Ei[(size_t)a * DD + lane] - Ei[(size_t)c * DD + lane];
        float d1 = Ei[(size_t)a * DD + 32 + lane] - Ei[(size_t)c * DD + 32 + lane];
        float s = warp_sum(d0 * d0 + d1 * d1);
        if (lane == 0) atomicAdd(&sc[4], sqrtf(s));
    }
}

// ------------------------------ weight L2 reg --------------------------------
__global__ void reg_w_kernel(const float* __restrict__ W1,
                             const float* __restrict__ b1,
                             const float* __restrict__ W2,
                             const float* __restrict__ b2,
                             float* __restrict__ acc) {
    int t = blockIdx.x * blockDim.x + threadIdx.x;
    int total = gridDim.x * blockDim.x;
    float s = 0.f;
    for (int i = t; i < 768 * 64; i += total) {
        float a = W1[i]; s = fmaf(a, a, s);
        float c = W2[i]; s = fmaf(c, c, s);
    }
    if (t < 64) {
        float a = b1[t]; s = fmaf(a, a, s);
        float c = b2[t]; s = fmaf(c, c, s);
    }
    s = warp_sum(s);
    if ((threadIdx.x & 31) == 0) atomicAdd(acc, s);
}

// -------------------------------- finalize -----------------------------------
__global__ void finalize_kernel(const float* __restrict__ su,
                                const float* __restrict__ si,
                                const float* __restrict__ sc,
                                float* __restrict__ out) {
    __shared__ float s_lu[16], s_li[16];
    int tid = threadIdx.x;   // 512 threads
    float lu = logf(su[tid] + 1e-8f);
    float li = logf(si[tid] + 1e-8f) + logf(si[tid + 512] + 1e-8f);
    lu = warp_sum(lu);
    li = warp_sum(li);
    if ((tid & 31) == 0) { s_lu[tid >> 5] = lu; s_li[tid >> 5] = li; }
    __syncthreads();
    if (tid == 0) {
        float LU = 0.f, LI = 0.f;
        #pragma unroll
        for (int w = 0; w < 16; w++) { LU += s_lu[w]; LI += s_li[w]; }
        float neg_score = LU / 512.f + LI / 1024.f;
        float pos_score = sc[1] / 512.f + sc[2] / 1024.f;
        float loss_s = -pos_score + neg_score;
        float loss_r = sc[3] / 512.f;
        float loss_reg = 1e-7f * sc[0];
        float extra = sc[4] * (1.f / 32.f);
        float loss = loss_r + 0.2f * loss_s + loss_reg + 0.01f * extra;
        out[0] = loss;
        out[1] = loss_r;
        out[2] = 0.2f * loss_s;
    }
}

// ------------------------------- launcher ------------------------------------
extern "C" void kernel_launch(void* const* d_in, const int* in_sizes, int n_in,
                              void* d_out, int out_size) {
    const int*   uids     = (const int*)d_in[0];
    const int*   pos      = (const int*)d_in[1];
    const int*   neg      = (const int*)d_in[2];
    const int*   adj_rows = (const int*)d_in[3];
    const int*   adj_cols = (const int*)d_in[4];
    const float* adj_vals = (const float*)d_in[5];
    const float* E_u_0    = (const float*)d_in[6];
    const float* E_i_0    = (const float*)d_in[7];
    const float* u_mul_s  = (const float*)d_in[8];
    const float* vt       = (const float*)d_in[9];
    const float* v_mul_s  = (const float*)d_in[10];
    const float* ut       = (const float*)d_in[11];
    const float* W_api    = (const float*)d_in[12];
    const float* b_api    = (const float*)d_in[13];
    const float* W_mashup = (const float*)d_in[14];
    const float* b_mashup = (const float*)d_in[15];
    const float* pos_api  = (const float*)d_in[16];
    const float* neg_api  = (const float*)d_in[17];
    const float* mashup   = (const float*)d_in[18];
    const int*   unpop    = (const int*)d_in[19];
    const int*   popi     = (const int*)d_in[20];

    float* out = (float*)d_out;
    const size_t EMB = (size_t)512 * 768;
    float* out_mashup = out + 3;
    float* out_posapi = out + 3 + EMB;
    float* out_negapi = out + 3 + 2 * EMB;
    float* Eu_out = out + 3 + 3 * EMB;   // Ei_out contiguous after

    float *Zb, *Efb, *Sm, *G;
    __nv_bfloat16 *Eb, *Gb;
    cudaGetSymbolAddress((void**)&Zb,  g_Z);
    cudaGetSymbolAddress((void**)&Efb, g_Ef);
    cudaGetSymbolAddress((void**)&Eb,  g_Eb);
    cudaGetSymbolAddress((void**)&Sm,  g_small);
    cudaGetSymbolAddress((void**)&G,   g_G);
    cudaGetSymbolAddress((void**)&Gb,  g_Gb);

    float* Zu1 = Zb;
    float* Zi1 = Zu1 + (size_t)N_U * DD;
    float* Euf = Efb;
    float* Eif = Euf + (size_t)N_U * DD;
    __nv_bfloat16* Eub = Eb;
    __nv_bfloat16* Eib = Eub + (size_t)N_U * DD;
    float* Mu = Sm + OFF_MU;
    float* Mi = Sm + OFF_MI;
    float* su = Sm + OFF_SU;
    float* si = Sm + OFF_SI;
    float* sc = Sm + OFF_SC;
    float* Gu = G;
    float* Gi = G + (size_t)BB * DD;
    __nv_bfloat16* Gub = Gb;
    __nv_bfloat16* Gib = Gub + (size_t)BB * DD;

    cudaFuncSetAttribute(logits_mma,
                         cudaFuncAttributeMaxDynamicSharedMemorySize, SMEM_MMA);

    cudaMemsetAsync(Zb, 0, (size_t)(N_U + N_I) * DD * 4);
    cudaMemsetAsync(Sm, 0, 2304 * 4);

    cudaMemcpyAsync(out_mashup, mashup, EMB * 4, cudaMemcpyDeviceToDevice);
    cudaMemcpyAsync(out_posapi, pos_api, EMB * 4, cudaMemcpyDeviceToDevice);
    cudaMemcpyAsync(out_negapi, neg_api, EMB * 4, cudaMemcpyDeviceToDevice);

    const int spmm_blocks = 2 * (((NNZ_E / 4) * 16 + 255) / 256);
    // layer 1: Z1 = A*(E0)
    spmm_dual<<<spmm_blocks, 256>>>(adj_vals, adj_rows, adj_cols,
                                    E_u_0, E_i_0, Zu1, Zi1);
    // Ef = E0 + Z1 ; M reductions ; embedding L2 reg  (both sides, one launch)
    prep_both<<<3072, 256>>>(E_u_0, E_i_0, Zu1, Zi1, ut, vt,
                             Euf, Eif, Mi, Mu, sc);
    // layer 2: Ef += A*(Z1)
    spmm_dual<<<spmm_blocks, 256>>>(adj_vals, adj_rows, adj_cols,
                                    Zu1, Zi1, Euf, Eif);

    reg_w_kernel<<<64, 256>>>(W_api, b_api, W_mashup, b_mashup, sc);
    gsel_kernel<<<1536, 64>>>(uids, pos, neg, E_u_0, E_i_0,
                              u_mul_s, v_mul_s, Mu, Mi, G, Gb);

    // copy E to (misaligned) d_out + produce bf16 E
    const size_t n4 = (size_t)(N_U + N_I) * DD / 4;
    copyout_conv<<<(int)((n4 + 255) / 256), 256>>>(Efb, Eu_out, Eb, n4);

    // tensor-core logits
    const int ntu = (N_U + 127) / 128;   // 782
    const int nti = (N_I + 127) / 128;   // 391
    logits_mma<<<4 * ntu, 256, SMEM_MMA>>>(Gub, 4, Eub, N_U, su);
    logits_mma<<<8 * nti, 256, SMEM_MMA>>>(Gib, 8, Eib, N_I, si);

    small_loss_kernel<<<2304, 256>>>(uids, pos, neg, Euf, Eif, Gu, Gi,
                                     unpop, popi, sc);

    finalize_kernel<<<1, 512>>>(su, si, sc, out);
}

// round 12
// speedup vs baseline: 1.9539x; 1.0680x over previous
#include <cuda_runtime.h>
#include <cuda_bf16.h>
#include <cstdint>
#include <cstddef>

#define N_U 100000
#define N_I 50000
#define NR  (N_U + N_I)
#define DD  64
#define QQ  5
#define NNZ_E 1000000
#define BB  512
#define SCAN_BS 256
#define SCAN_NB ((NR + SCAN_BS - 1) / SCAN_BS)   // 586

typedef unsigned long long ull;

// ------------------------- scratch (device globals) -------------------------
__device__ __align__(16) float g_Z[(size_t)NR * DD];             // Zu1, Zi1
__device__ __align__(16) float g_Ef[(size_t)NR * DD];            // Euf, Eif (final E)
__device__ __align__(16) __nv_bfloat16 g_Eb[(size_t)NR * DD];    // bf16 E
__device__ __align__(16) float g_small[2304];  // Mu(320) Mi(320) su(512) si(1024) sc(8)
__device__ __align__(16) float g_G[3 * BB * DD];
__device__ __align__(16) __nv_bfloat16 g_Gb[3 * BB * DD];
// CSR scratch
__device__ int   g_cnt[NR];
__device__ int   g_rp[NR + 1];
__device__ int   g_off[NR];
__device__ int   g_bsum[1024];
__device__ __align__(16) int   g_ecol[2 * NNZ_E];
__device__ __align__(16) float g_eval[2 * NNZ_E];

#define OFF_MU 0
#define OFF_MI 320
#define OFF_SU 640
#define OFF_SI 1152
#define OFF_SC 2176

// ------------------------------ helpers -------------------------------------
__device__ __forceinline__ float warp_sum(float v) {
    #pragma unroll
    for (int o = 16; o; o >>= 1) v += __shfl_xor_sync(0xffffffffu, v, o);
    return v;
}
__device__ __forceinline__ int warp_sum_i(int v) {
    #pragma unroll
    for (int o = 16; o; o >>= 1) v += __shfl_xor_sync(0xffffffffu, v, o);
    return v;
}
__device__ __forceinline__ uint32_t smem_u32(const void* p) {
    uint32_t a;
    asm("{ .reg .u64 t; cvta.to.shared.u64 t, %1; cvt.u32.u64 %0, t; }" : "=r"(a) : "l"(p));
    return a;
}
__device__ __forceinline__ void ldmx4(unsigned& r0, unsigned& r1,
                                      unsigned& r2, unsigned& r3, uint32_t addr) {
    asm volatile("ldmatrix.sync.aligned.m8n8.x4.shared.b16 {%0,%1,%2,%3}, [%4];"
                 : "=r"(r0), "=r"(r1), "=r"(r2), "=r"(r3) : "r"(addr));
}
__device__ __forceinline__ void mma16816(float* d, const unsigned* a, const unsigned* b) {
    asm volatile("mma.sync.aligned.m16n8k16.row.col.f32.bf16.bf16.f32 "
                 "{%0,%1,%2,%3}, {%4,%5,%6,%7}, {%8,%9}, {%0,%1,%2,%3};"
                 : "+f"(d[0]), "+f"(d[1]), "+f"(d[2]), "+f"(d[3])
                 : "r"(a[0]), "r"(a[1]), "r"(a[2]), "r"(a[3]), "r"(b[0]), "r"(b[1]));
}

// ------------------------------ CSR build ------------------------------------
__global__ void hist_k(const int* __restrict__ rows, const int* __restrict__ cols,
                       int* __restrict__ cnt) {
    int t = blockIdx.x * blockDim.x + threadIdx.x;
    if (t < NNZ_E) atomicAdd(&cnt[__ldg(rows + t)], 1);
    else if (t < 2 * NNZ_E) atomicAdd(&cnt[N_U + __ldg(cols + (t - NNZ_E))], 1);
}

__global__ void scan1_k(const int* __restrict__ cnt, int* __restrict__ bsum) {
    __shared__ int sh[8];
    int i = blockIdx.x * SCAN_BS + threadIdx.x;
    int v = (i < NR) ? cnt[i] : 0;
    v = warp_sum_i(v);
    if ((threadIdx.x & 31) == 0) sh[threadIdx.x >> 5] = v;
    __syncthreads();
    if (threadIdx.x == 0) {
        int t = 0;
        #pragma unroll
        for (int w = 0; w < 8; w++) t += sh[w];
        bsum[blockIdx.x] = t;
    }
}

__global__ void scan2_k(int* __restrict__ bsum) {    // 1 block, 1024 threads
    __shared__ int sh[1024];
    int tid = threadIdx.x;
    int v = (tid < SCAN_NB) ? bsum[tid] : 0;
    sh[tid] = v;
    __syncthreads();
    for (int o = 1; o < 1024; o <<= 1) {
        int t = (tid >= o) ? sh[tid - o] : 0;
        __syncthreads();
        sh[tid] += t;
        __syncthreads();
    }
    if (tid < SCAN_NB) bsum[tid] = sh[tid] - v;      // exclusive
}

__global__ void scan3_k(const int* __restrict__ cnt, const int* __restrict__ bsum,
                        int* __restrict__ rp, int* __restrict__ off) {
    __shared__ int sh[SCAN_BS];
    int tid = threadIdx.x;
    int i = blockIdx.x * SCAN_BS + tid;
    int v = (i < NR) ? cnt[i] : 0;
    sh[tid] = v;
    __syncthreads();
    for (int o = 1; o < SCAN_BS; o <<= 1) {
        int t = (tid >= o) ? sh[tid - o] : 0;
        __syncthreads();
        sh[tid] += t;
        __syncthreads();
    }
    int excl = sh[tid] - v + bsum[blockIdx.x];
    if (i < NR) { rp[i] = excl; off[i] = excl; }
    if (i == NR - 1) rp[NR] = excl + v;
}

__global__ void scatter_k(const int* __restrict__ rows, const int* __restrict__ cols,
                          const float* __restrict__ vals,
                          int* __restrict__ off, int* __restrict__ ecol,
                          float* __restrict__ eval) {
    int t = blockIdx.x * blockDim.x + threadIdx.x;
    int r, c; float v;
    if (t < NNZ_E) {
        r = __ldg(rows + t); c = __ldg(cols + t); v = __ldg(vals + t);
    } else if (t < 2 * NNZ_E) {
        int e = t - NNZ_E;
        r = N_U + __ldg(cols + e); c = __ldg(rows + e); v = __ldg(vals + e);
    } else return;
    int slot = atomicAdd(&off[r], 1);
    ecol[slot] = c; eval[slot] = v;
}

// ------------------------ CSR SpMM: warp per dest row -------------------------
// layer1: Yu = A @ Xi, Yi = A^T @ Xu (accum=0, overwrite)
// layer2: Yu += A @ Xi, Yi += A^T @ Xu (accum=1: Y pre-holds E0+Z1)
__global__ void spmm_csr_k(const int* __restrict__ rp,
                           const int* __restrict__ ecol,
                           const float* __restrict__ eval,
                           const float* __restrict__ Xu,
                           const float* __restrict__ Xi,
                           float* __restrict__ Yu,
                           float* __restrict__ Yi, int accum) {
    int w = (blockIdx.x * blockDim.x + threadIdx.x) >> 5;
    int lane = threadIdx.x & 31;
    if (w >= NR) return;
    const float* X; float* Y;
    if (w < N_U) { X = Xi; Y = Yu + (size_t)w * DD; }
    else         { X = Xu; Y = Yi + (size_t)(w - N_U) * DD; }
    int e = __ldg(rp + w), e1 = __ldg(rp + w + 1);
    float2 acc = make_float2(0.f, 0.f);
    for (; e + 1 < e1; e += 2) {
        int c0 = __ldg(ecol + e), c1 = __ldg(ecol + e + 1);
        float v0 = __ldg(eval + e), v1 = __ldg(eval + e + 1);
        float2 x0 = *(const float2*)(X + (size_t)c0 * DD + lane * 2);
        float2 x1 = *(const float2*)(X + (size_t)c1 * DD + lane * 2);
        acc.x = fmaf(v0, x0.x, acc.x); acc.y = fmaf(v0, x0.y, acc.y);
        acc.x = fmaf(v1, x1.x, acc.x); acc.y = fmaf(v1, x1.y, acc.y);
    }
    if (e < e1) {
        int c0 = __ldg(ecol + e); float v0 = __ldg(eval + e);
        float2 x0 = *(const float2*)(X + (size_t)c0 * DD + lane * 2);
        acc.x = fmaf(v0, x0.x, acc.x); acc.y = fmaf(v0, x0.y, acc.y);
    }
    float2* yp = (float2*)Y + lane;
    if (accum) { float2 o = *yp; acc.x += o.x; acc.y += o.y; }
    *yp = acc;
}

// ---------------- prep (both u and i): Ef = E0+Z1 ; M, reg --------------------
__global__ void prep_both(const float* __restrict__ Eu0,
                          const float* __restrict__ Ei0,
                          const float* __restrict__ Zu1,
                          const float* __restrict__ Zi1,
                          const float* __restrict__ Put,
                          const float* __restrict__ Pvt,
                          float* __restrict__ Euf,
                          float* __restrict__ Eif,
                          float* __restrict__ Mi,
                          float* __restrict__ Mu,
                          float* __restrict__ regAcc) {
    const bool isU = blockIdx.x < 2048;
    const int vbid = isU ? blockIdx.x : blockIdx.x - 2048;
    const int vgrid = isU ? 2048 : 1024;
    const int n_rows = isU ? N_U : N_I;
    const float* E0 = isU ? Eu0 : Ei0;
    const float* Z1 = isU ? Zu1 : Zi1;
    const float* P  = isU ? Put : Pvt;
    float* Ef = isU ? Euf : Eif;
    float* Macc = isU ? Mi : Mu;

    int d = threadIdx.x & 63;
    int grp = threadIdx.x >> 6;                 // 0..3
    float m0 = 0, m1 = 0, m2 = 0, m3 = 0, m4 = 0, racc = 0;
    for (int r = vbid * 4 + grp; r < n_rows; r += vgrid * 4) {
        size_t off = (size_t)r * DD + d;
        float e0 = E0[off];
        float t  = e0 + Z1[off];
        Ef[off] = t;
        racc = fmaf(e0, e0, racc);
        m0 = fmaf(__ldg(P + r), t, m0);
        m1 = fmaf(__ldg(P + (size_t)n_rows + r), t, m1);
        m2 = fmaf(__ldg(P + 2 * (size_t)n_rows + r), t, m2);
        m3 = fmaf(__ldg(P + 3 * (size_t)n_rows + r), t, m3);
        m4 = fmaf(__ldg(P + 4 * (size_t)n_rows + r), t, m4);
    }
    __shared__ float sm[4][QQ][DD];
    sm[grp][0][d] = m0; sm[grp][1][d] = m1; sm[grp][2][d] = m2;
    sm[grp][3][d] = m3; sm[grp][4][d] = m4;
    __syncthreads();
    if (grp == 0) {
        #pragma unroll
        for (int q = 0; q < QQ; q++)
            atomicAdd(&Macc[q * DD + d],
                      sm[0][q][d] + sm[1][q][d] + sm[2][q][d] + sm[3][q][d]);
    }
    racc = warp_sum(racc);
    if ((threadIdx.x & 31) == 0) atomicAdd(regAcc, racc);
}

// -------- copyout + convert: Ef -> misaligned d_out fp32 AND bf16 copy --------
__global__ void copyout_conv(const float* __restrict__ Ef,
                             float* __restrict__ Eout,
                             __nv_bfloat16* __restrict__ Eb, size_t n4) {
    size_t i = (size_t)blockIdx.x * blockDim.x + threadIdx.x;
    if (i >= n4) return;
    float4 v = ((const float4*)Ef)[i];
    float* o = Eout + i * 4;
    o[0] = v.x; o[1] = v.y; o[2] = v.z; o[3] = v.w;
    __nv_bfloat162 lo = __floats2bfloat162_rn(v.x, v.y);
    __nv_bfloat162 hi = __floats2bfloat162_rn(v.z, v.w);
    ((__nv_bfloat162*)(Eb + i * 4))[0] = lo;
    ((__nv_bfloat162*)(Eb + i * 4))[1] = hi;
}

// ------------------------------ G selection ----------------------------------
__global__ void gsel_kernel(const int* __restrict__ uids,
                            const int* __restrict__ pos,
                            const int* __restrict__ neg,
                            const float* __restrict__ Eu0,
                            const float* __restrict__ Ei0,
                            const float* __restrict__ mu_s,
                            const float* __restrict__ mi_s,
                            const float* __restrict__ Mu,
                            const float* __restrict__ Mi,
                            float* __restrict__ G,
                            __nv_bfloat16* __restrict__ Gb) {
    int b = blockIdx.x, d = threadIdx.x;
    const float* E0; const float* ms; const float* M; int id;
    if (b < 512)       { E0 = Eu0; ms = mu_s; M = Mu; id = uids[b]; }
    else if (b < 1024) { E0 = Ei0; ms = mi_s; M = Mi; id = pos[b - 512]; }
    else               { E0 = Ei0; ms = mi_s; M = Mi; id = neg[b - 1024]; }
    float v = E0[(size_t)id * DD + d];
    #pragma unroll
    for (int q = 0; q < QQ; q++)
        v = fmaf(ms[(size_t)id * QQ + q], M[q * DD + d], v);
    float v5 = 5.0f * v;
    G[b * DD + d] = v5;
    Gb[b * DD + d] = __float2bfloat16(v5);
}

// --------- tensor-core logits: bf16 mma.16816 GEMM + exp + row-sum -----------
#define SMEM_MMA (2 * 128 * 144)
__global__ __launch_bounds__(256, 2)
void logits_mma(const __nv_bfloat16* __restrict__ Gb, int Mtiles,
                const __nv_bfloat16* __restrict__ Eb, int N,
                float* __restrict__ S) {
    extern __shared__ char smc[];
    const uint32_t sA = smem_u32(smc);
    const uint32_t sB = sA + 128 * 144;
    const int tid = threadIdx.x;
    const int mt = blockIdx.x % Mtiles;
    const long n0 = (long)(blockIdx.x / Mtiles) * 128;

    #pragma unroll
    for (int it = 0; it < 4; it++) {
        int idx = it * 256 + tid;          // 0..1023
        int row = idx >> 3, c = idx & 7;
        uint4 v = *(const uint4*)(Gb + ((size_t)(mt * 128 + row)) * DD + c * 8);
        *(uint4*)(smc + row * 144 + c * 16) = v;
    }
    #pragma unroll
    for (int it = 0; it < 4; it++) {
        int idx = it * 256 + tid;
        int row = idx >> 3, c = idx & 7;
        long n = n0 + row;
        uint4 v = make_uint4(0, 0, 0, 0);
        if (n < N) v = *(const uint4*)(Eb + n * DD + c * 8);
        *(uint4*)(smc + 128 * 144 + row * 144 + c * 16) = v;
    }
    __syncthreads();

    const int wid = tid >> 5, lane = tid & 31;
    const int wm = (wid & 3) * 32;
    const int wn = (wid >> 2) * 64;

    float d[2][8][4];
    #pragma unroll
    for (int mi = 0; mi < 2; mi++)
        #pragma unroll
        for (int ni = 0; ni < 8; ni++)
            #pragma unroll
            for (int j = 0; j < 4; j++) d[mi][ni][j] = 0.f;

    const int lrowA = (lane & 7) + ((lane & 8) ? 8 : 0);
    const int lcolA = (lane & 16) ? 8 : 0;
    const int lrowB = (lane & 7) + ((lane & 16) ? 8 : 0);
    const int lcolB = (lane & 8) ? 8 : 0;

    #pragma unroll
    for (int ks = 0; ks < 4; ks++) {
        const int k0 = ks * 16;
        unsigned a[2][4];
        #pragma unroll
        for (int mi = 0; mi < 2; mi++) {
            uint32_t addr = sA + (wm + mi * 16 + lrowA) * 144 + (k0 + lcolA) * 2;
            ldmx4(a[mi][0], a[mi][1], a[mi][2], a[mi][3], addr);
        }
        #pragma unroll
        for (int np = 0; np < 4; np++) {
            unsigned b[4];
            uint32_t addr = sB + (wn + np * 16 + lrowB) * 144 + (k0 + lcolB) * 2;
            ldmx4(b[0], b[1], b[2], b[3], addr);
            #pragma unroll
            for (int mi = 0; mi < 2; mi++) {
                mma16816(d[mi][np * 2 + 0], a[mi], b + 0);
                mma16816(d[mi][np * 2 + 1], a[mi], b + 2);
            }
        }
    }

    const bool full = (n0 + 128 <= N);
    const int r4 = lane >> 2;
    #pragma unroll
    for (int mi = 0; mi < 2; mi++) {
        float slo = 0.f, shi = 0.f;
        #pragma unroll
        for (int ni = 0; ni < 8; ni++) {
            if (full) {
                slo += __expf(d[mi][ni][0]) + __expf(d[mi][ni][1]);
                shi += __expf(d[mi][ni][2]) + __expf(d[mi][ni][3]);
            } else {
                long c = n0 + wn + ni * 8 + (lane & 3) * 2;
                if (c < N)     { slo += __expf(d[mi][ni][0]); shi += __expf(d[mi][ni][2]); }
                if (c + 1 < N) { slo += __expf(d[mi][ni][1]); shi += __expf(d[mi][ni][3]); }
            }
        }
        slo += __shfl_xor_sync(0xffffffffu, slo, 1);
        slo += __shfl_xor_sync(0xffffffffu, slo, 2);
        shi += __shfl_xor_sync(0xffffffffu, shi, 1);
        shi += __shfl_xor_sync(0xffffffffu, shi, 2);
        if ((lane & 3) == 0) {
            atomicAdd(&S[mt * 128 + wm + mi * 16 + r4], slo);
            atomicAdd(&S[mt * 128 + wm + mi * 16 + 8 + r4], shi);
        }
    }
}

// -------------------- pos / BPR / extra-loss (warp-per-task) -----------------
__global__ void small_loss_kernel(const int* __restrict__ uids,
                                  const int* __restrict__ pos,
                                  const int* __restrict__ neg,
                                  const float* __restrict__ Eu,
                                  const float* __restrict__ Ei,
                                  const float* __restrict__ Gu,
                                  const float* __restrict__ Gi,
                                  const int* __restrict__ unpop,
                                  const int* __restrict__ popi,
                                  float* __restrict__ sc) {
    int gtid = blockIdx.x * blockDim.x + threadIdx.x;
    int wid = gtid >> 5, lane = gtid & 31;
    if (wid < 512) {                       // pos_u
        int b = wid, u = uids[b];
        float s = Gu[b * DD + lane] * Eu[(size_t)u * DD + lane]
                + Gu[b * DD + 32 + lane] * Eu[(size_t)u * DD + 32 + lane];
        s = warp_sum(s);
        if (lane == 0) atomicAdd(&sc[1], fminf(fmaxf(s, -5.0f), 5.0f));
    } else if (wid < 1536) {               // pos_i
        int b = wid - 512;
        int id = (b < 512) ? pos[b] : neg[b - 512];
        float s = Gi[b * DD + lane] * Ei[(size_t)id * DD + lane]
                + Gi[b * DD + 32 + lane] * Ei[(size_t)id * DD + 32 + lane];
        s = warp_sum(s);
        if (lane == 0) atomicAdd(&sc[2], fminf(fmaxf(s, -5.0f), 5.0f));
    } else if (wid < 2048) {               // BPR
        int b = wid - 1536, u = uids[b], p = pos[b], nn = neg[b];
        float eu0 = Eu[(size_t)u * DD + lane], eu1 = Eu[(size_t)u * DD + 32 + lane];
        float sp = eu0 * Ei[(size_t)p * DD + lane]  + eu1 * Ei[(size_t)p * DD + 32 + lane];
        float sn = eu0 * Ei[(size_t)nn * DD + lane] + eu1 * Ei[(size_t)nn * DD + 32 + lane];
        sp = warp_sum(sp);
        sn = warp_sum(sn);
        if (lane == 0) {
            float x = sp - sn;
            float t = (x > 0.f) ? log1pf(expf(-x)) : (-x + log1pf(expf(x)));
            atomicAdd(&sc[3], t);
        }
    } else {                               // extra-loss pairs
        int p = wid - 2048;
        if (p >= 64 * 8 * 32) return;
        int ig = p >> 8, rem = p & 255, ui = rem >> 5, pi = rem & 31;
        int a = unpop[ig * 8 + ui];
        int c = popi[ig * 32 + pi];
        float d0 = Ei[(size_t)a * DD + lane] - Ei[(size_t)c * DD + lane];
        float d1 = Ei[(size_t)a * DD + 32 + lane] - Ei[(size_t)c * DD + 32 + lane];
        float s = warp_sum(d0 * d0 + d1 * d1);
        if (lane == 0) atomicAdd(&sc[4], sqrtf(s));
    }
}

// ------------------------------ weight L2 reg --------------------------------
__global__ void reg_w_kernel(const float* __restrict__ W1,
                             const float* __restrict__ b1,
                             const float* __restrict__ W2,
                             const float* __restrict__ b2,
                             float* __restrict__ acc) {
    int t = blockIdx.x * blockDim.x + threadIdx.x;
    int total = gridDim.x * blockDim.x;
    float s = 0.f;
    for (int i = t; i < 768 * 64; i += total) {
        float a = W1[i]; s = fmaf(a, a, s);
        float c = W2[i]; s = fmaf(c, c, s);
    }
    if (t < 64) {
        float a = b1[t]; s = fmaf(a, a, s);
        float c = b2[t]; s = fmaf(c, c, s);
    }
    s = warp_sum(s);
    if ((threadIdx.x & 31) == 0) atomicAdd(acc, s);
}

// -------------------------------- finalize -----------------------------------
__global__ void finalize_kernel(const float* __restrict__ su,
                                const float* __restrict__ si,
                                const float* __restrict__ sc,
                                float* __restrict__ out) {
    __shared__ float s_lu[16], s_li[16];
    int tid = threadIdx.x;   // 512 threads
    float lu = logf(su[tid] + 1e-8f);
    float li = logf(si[tid] + 1e-8f) + logf(si[tid + 512] + 1e-8f);
    lu = warp_sum(lu);
    li = warp_sum(li);
    if ((tid & 31) == 0) { s_lu[tid >> 5] = lu; s_li[tid >> 5] = li; }
    __syncthreads();
    if (tid == 0) {
        float LU = 0.f, LI = 0.f;
        #pragma unroll
        for (int w = 0; w < 16; w++) { LU += s_lu[w]; LI += s_li[w]; }
        float neg_score = LU / 512.f + LI / 1024.f;
        float pos_score = sc[1] / 512.f + sc[2] / 1024.f;
        float loss_s = -pos_score + neg_score;
        float loss_r = sc[3] / 512.f;
        float loss_reg = 1e-7f * sc[0];
        float extra = sc[4] * (1.f / 32.f);
        float loss = loss_r + 0.2f * loss_s + loss_reg + 0.01f * extra;
        out[0] = loss;
        out[1] = loss_r;
        out[2] = 0.2f * loss_s;
    }
}

// ------------------------------- launcher ------------------------------------
extern "C" void kernel_launch(void* const* d_in, const int* in_sizes, int n_in,
                              void* d_out, int out_size) {
    const int*   uids     = (const int*)d_in[0];
    const int*   pos      = (const int*)d_in[1];
    const int*   neg      = (const int*)d_in[2];
    const int*   adj_rows = (const int*)d_in[3];
    const int*   adj_cols = (const int*)d_in[4];
    const float* adj_vals = (const float*)d_in[5];
    const float* E_u_0    = (const float*)d_in[6];
    const float* E_i_0    = (const float*)d_in[7];
    const float* u_mul_s  = (const float*)d_in[8];
    const float* vt       = (const float*)d_in[9];
    const float* v_mul_s  = (const float*)d_in[10];
    const float* ut       = (const float*)d_in[11];
    const float* W_api    = (const float*)d_in[12];
    const float* b_api    = (const float*)d_in[13];
    const float* W_mashup = (const float*)d_in[14];
    const float* b_mashup = (const float*)d_in[15];
    const float* pos_api  = (const float*)d_in[16];
    const float* neg_api  = (const float*)d_in[17];
    const float* mashup   = (const float*)d_in[18];
    const int*   unpop    = (const int*)d_in[19];
    const int*   popi     = (const int*)d_in[20];

    float* out = (float*)d_out;
    const size_t EMB = (size_t)512 * 768;
    float* out_mashup = out + 3;
    float* out_posapi = out + 3 + EMB;
    float* out_negapi = out + 3 + 2 * EMB;
    float* Eu_out = out + 3 + 3 * EMB;

    float *Zb, *Efb, *Sm, *G, *evalp;
    __nv_bfloat16 *Eb, *Gb;
    int *cnt, *rp, *off, *bsum, *ecol;
    cudaGetSymbolAddress((void**)&Zb,   g_Z);
    cudaGetSymbolAddress((void**)&Efb,  g_Ef);
    cudaGetSymbolAddress((void**)&Eb,   g_Eb);
    cudaGetSymbolAddress((void**)&Sm,   g_small);
    cudaGetSymbolAddress((void**)&G,    g_G);
    cudaGetSymbolAddress((void**)&Gb,   g_Gb);
    cudaGetSymbolAddress((void**)&cnt,  g_cnt);
    cudaGetSymbolAddress((void**)&rp,   g_rp);
    cudaGetSymbolAddress((void**)&off,  g_off);
    cudaGetSymbolAddress((void**)&bsum, g_bsum);
    cudaGetSymbolAddress((void**)&ecol, g_ecol);
    cudaGetSymbolAddress((void**)&evalp, g_eval);

    float* Zu1 = Zb;
    float* Zi1 = Zu1 + (size_t)N_U * DD;
    float* Euf = Efb;
    float* Eif = Euf + (size_t)N_U * DD;
    __nv_bfloat16* Eub = Eb;
    __nv_bfloat16* Eib = Eub + (size_t)N_U * DD;
    float* Mu = Sm + OFF_MU;
    float* Mi = Sm + OFF_MI;
    float* su = Sm + OFF_SU;
    float* si = Sm + OFF_SI;
    float* sc = Sm + OFF_SC;
    float* Gu = G;
    float* Gi = G + (size_t)BB * DD;
    __nv_bfloat16* Gub = Gb;
    __nv_bfloat16* Gib = Gub + (size_t)BB * DD;

    cudaFuncSetAttribute(logits_mma,
                         cudaFuncAttributeMaxDynamicSharedMemorySize, SMEM_MMA);

    cudaMemsetAsync(cnt, 0, NR * 4);
    cudaMemsetAsync(Sm, 0, 2304 * 4);

    cudaMemcpyAsync(out_mashup, mashup, EMB * 4, cudaMemcpyDeviceToDevice);
    cudaMemcpyAsync(out_posapi, pos_api, EMB * 4, cudaMemcpyDeviceToDevice);
    cudaMemcpyAsync(out_negapi, neg_api, EMB * 4, cudaMemcpyDeviceToDevice);

    // ---- CSR build (u rows then i rows, concatenated edge array) ----
    const int e2_blocks = (2 * NNZ_E + 255) / 256;
    hist_k<<<e2_blocks, 256>>>(adj_rows, adj_cols, cnt);
    scan1_k<<<SCAN_NB, SCAN_BS>>>(cnt, bsum);
    scan2_k<<<1, 1024>>>(bsum);
    scan3_k<<<SCAN_NB, SCAN_BS>>>(cnt, bsum, rp, off);
    scatter_k<<<e2_blocks, 256>>>(adj_rows, adj_cols, adj_vals, off, ecol, evalp);

    // ---- layer 1: Z1 = A @ E0 (warp-per-row gather) ----
    const int csr_blocks = (NR * 32 + 255) / 256;
    spmm_csr_k<<<csr_blocks, 256>>>(rp, ecol, evalp, E_u_0, E_i_0, Zu1, Zi1, 0);
    // Ef = E0 + Z1 ; M reductions ; embedding L2 reg
    prep_both<<<3072, 256>>>(E_u_0, E_i_0, Zu1, Zi1, ut, vt,
                             Euf, Eif, Mi, Mu, sc);
    // ---- layer 2: Ef += A @ Z1 ----
    spmm_csr_k<<<csr_blocks, 256>>>(rp, ecol, evalp, Zu1, Zi1, Euf, Eif, 1);

    reg_w_kernel<<<192, 256>>>(W_api, b_api, W_mashup, b_mashup, sc);
    gsel_kernel<<<1536, 64>>>(uids, pos, neg, E_u_0, E_i_0,
                              u_mul_s, v_mul_s, Mu, Mi, G, Gb);

    const size_t n4 = (size_t)NR * DD / 4;
    copyout_conv<<<(int)((n4 + 255) / 256), 256>>>(Efb, Eu_out, Eb, n4);

    const int ntu = (N_U + 127) / 128;   // 782
    const int nti = (N_I + 127) / 128;   // 391
    logits_mma<<<4 * ntu, 256, SMEM_MMA>>>(Gub, 4, Eub, N_U, su);
    logits_mma<<<8 * nti, 256, SMEM_MMA>>>(Gib, 8, Eib, N_I, si);

    small_loss_kernel<<<2304, 256>>>(uids, pos, neg, Euf, Eif, Gu, Gi,
                                     unpop, popi, sc);

    finalize_kernel<<<1, 512>>>(su, si, sc, out);
}

// round 13
// speedup vs baseline: 1.9715x; 1.0090x over previous
#include <cuda_runtime.h>
#include <cuda_bf16.h>
#include <cstdint>
#include <cstddef>

#define N_U 100000
#define N_I 50000
#define NR  (N_U + N_I)
#define DD  64
#define QQ  5
#define NNZ_E 1000000
#define BB  512
#define SCAN_BS 256
#define SCAN_NB ((NR + SCAN_BS - 1) / SCAN_BS)   // 586

typedef unsigned long long ull;

// ------------------------- scratch (device globals) -------------------------
__device__ __align__(16) float g_Z[(size_t)NR * DD];             // Zu1, Zi1
__device__ __align__(16) float g_Ef[(size_t)NR * DD];            // Euf, Eif (final E)
__device__ __align__(16) __nv_bfloat16 g_Eb[(size_t)NR * DD];    // bf16 E
__device__ __align__(16) float g_small[2304];  // Mu(320) Mi(320) su(512) si(1024) sc(8)
__device__ __align__(16) float g_G[3 * BB * DD];
__device__ __align__(16) __nv_bfloat16 g_Gb[3 * BB * DD];
// CSR scratch
__device__ int   g_cnt[NR];
__device__ int   g_rp[NR + 1];
__device__ int   g_off[NR];
__device__ int   g_bsum[1024];
__device__ __align__(16) int   g_ecol[2 * NNZ_E];
__device__ __align__(16) float g_eval[2 * NNZ_E];

#define OFF_MU 0
#define OFF_MI 320
#define OFF_SU 640
#define OFF_SI 1152
#define OFF_SC 2176

// ------------------------------ helpers -------------------------------------
__device__ __forceinline__ float warp_sum(float v) {
    #pragma unroll
    for (int o = 16; o; o >>= 1) v += __shfl_xor_sync(0xffffffffu, v, o);
    return v;
}
__device__ __forceinline__ int warp_sum_i(int v) {
    #pragma unroll
    for (int o = 16; o; o >>= 1) v += __shfl_xor_sync(0xffffffffu, v, o);
    return v;
}
__device__ __forceinline__ uint32_t smem_u32(const void* p) {
    uint32_t a;
    asm("{ .reg .u64 t; cvta.to.shared.u64 t, %1; cvt.u32.u64 %0, t; }" : "=r"(a) : "l"(p));
    return a;
}
__device__ __forceinline__ void ldmx4(unsigned& r0, unsigned& r1,
                                      unsigned& r2, unsigned& r3, uint32_t addr) {
    asm volatile("ldmatrix.sync.aligned.m8n8.x4.shared.b16 {%0,%1,%2,%3}, [%4];"
                 : "=r"(r0), "=r"(r1), "=r"(r2), "=r"(r3) : "r"(addr));
}
__device__ __forceinline__ void mma16816(float* d, const unsigned* a, const unsigned* b) {
    asm volatile("mma.sync.aligned.m16n8k16.row.col.f32.bf16.bf16.f32 "
                 "{%0,%1,%2,%3}, {%4,%5,%6,%7}, {%8,%9}, {%0,%1,%2,%3};"
                 : "+f"(d[0]), "+f"(d[1]), "+f"(d[2]), "+f"(d[3])
                 : "r"(a[0]), "r"(a[1]), "r"(a[2]), "r"(a[3]), "r"(b[0]), "r"(b[1]));
}

// ------------------------------ CSR build ------------------------------------
__global__ void hist_k(const int* __restrict__ rows, const int* __restrict__ cols,
                       int* __restrict__ cnt) {
    int t = blockIdx.x * blockDim.x + threadIdx.x;
    if (t < NNZ_E) atomicAdd(&cnt[__ldg(rows + t)], 1);
    else if (t < 2 * NNZ_E) atomicAdd(&cnt[N_U + __ldg(cols + (t - NNZ_E))], 1);
}

__global__ void scan1_k(const int* __restrict__ cnt, int* __restrict__ bsum) {
    __shared__ int sh[8];
    int i = blockIdx.x * SCAN_BS + threadIdx.x;
    int v = (i < NR) ? cnt[i] : 0;
    v = warp_sum_i(v);
    if ((threadIdx.x & 31) == 0) sh[threadIdx.x >> 5] = v;
    __syncthreads();
    if (threadIdx.x == 0) {
        int t = 0;
        #pragma unroll
        for (int w = 0; w < 8; w++) t += sh[w];
        bsum[blockIdx.x] = t;
    }
}

__global__ void scan2_k(int* __restrict__ bsum) {    // 1 block, 1024 threads
    __shared__ int sh[1024];
    int tid = threadIdx.x;
    int v = (tid < SCAN_NB) ? bsum[tid] : 0;
    sh[tid] = v;
    __syncthreads();
    for (int o = 1; o < 1024; o <<= 1) {
        int t = (tid >= o) ? sh[tid - o] : 0;
        __syncthreads();
        sh[tid] += t;
        __syncthreads();
    }
    if (tid < SCAN_NB) bsum[tid] = sh[tid] - v;      // exclusive
}

__global__ void scan3_k(const int* __restrict__ cnt, const int* __restrict__ bsum,
                        int* __restrict__ rp, int* __restrict__ off) {
    __shared__ int sh[SCAN_BS];
    int tid = threadIdx.x;
    int i = blockIdx.x * SCAN_BS + tid;
    int v = (i < NR) ? cnt[i] : 0;
    sh[tid] = v;
    __syncthreads();
    for (int o = 1; o < SCAN_BS; o <<= 1) {
        int t = (tid >= o) ? sh[tid - o] : 0;
        __syncthreads();
        sh[tid] += t;
        __syncthreads();
    }
    int excl = sh[tid] - v + bsum[blockIdx.x];
    if (i < NR) { rp[i] = excl; off[i] = excl; }
    if (i == NR - 1) rp[NR] = excl + v;
}

__global__ void scatter_k(const int* __restrict__ rows, const int* __restrict__ cols,
                          const float* __restrict__ vals,
                          int* __restrict__ off, int* __restrict__ ecol,
                          float* __restrict__ eval) {
    int t = blockIdx.x * blockDim.x + threadIdx.x;
    int r, c; float v;
    if (t < NNZ_E) {
        r = __ldg(rows + t); c = __ldg(cols + t); v = __ldg(vals + t);
    } else if (t < 2 * NNZ_E) {
        int e = t - NNZ_E;
        r = N_U + __ldg(cols + e); c = __ldg(rows + e); v = __ldg(vals + e);
    } else return;
    int slot = atomicAdd(&off[r], 1);
    ecol[slot] = c; eval[slot] = v;
}

// ------------------------ CSR SpMM layer1: warp per row -----------------------
__global__ void spmm_csr_k(const int* __restrict__ rp,
                           const int* __restrict__ ecol,
                           const float* __restrict__ eval,
                           const float* __restrict__ Xu,
                           const float* __restrict__ Xi,
                           float* __restrict__ Z) {
    int w = (blockIdx.x * blockDim.x + threadIdx.x) >> 5;
    int lane = threadIdx.x & 31;
    if (w >= NR) return;
    const float* X = (w < N_U) ? Xi : Xu;
    int e = __ldg(rp + w), e1 = __ldg(rp + w + 1);
    float2 acc = make_float2(0.f, 0.f);
    for (; e + 3 < e1; e += 4) {
        int c0 = __ldg(ecol + e),     c1 = __ldg(ecol + e + 1);
        int c2 = __ldg(ecol + e + 2), c3 = __ldg(ecol + e + 3);
        float v0 = __ldg(eval + e),     v1 = __ldg(eval + e + 1);
        float v2 = __ldg(eval + e + 2), v3 = __ldg(eval + e + 3);
        float2 x0 = *(const float2*)(X + (size_t)c0 * DD + lane * 2);
        float2 x1 = *(const float2*)(X + (size_t)c1 * DD + lane * 2);
        float2 x2 = *(const float2*)(X + (size_t)c2 * DD + lane * 2);
        float2 x3 = *(const float2*)(X + (size_t)c3 * DD + lane * 2);
        acc.x = fmaf(v0, x0.x, acc.x); acc.y = fmaf(v0, x0.y, acc.y);
        acc.x = fmaf(v1, x1.x, acc.x); acc.y = fmaf(v1, x1.y, acc.y);
        acc.x = fmaf(v2, x2.x, acc.x); acc.y = fmaf(v2, x2.y, acc.y);
        acc.x = fmaf(v3, x3.x, acc.x); acc.y = fmaf(v3, x3.y, acc.y);
    }
    for (; e < e1; e++) {
        int c0 = __ldg(ecol + e); float v0 = __ldg(eval + e);
        float2 x0 = *(const float2*)(X + (size_t)c0 * DD + lane * 2);
        acc.x = fmaf(v0, x0.x, acc.x); acc.y = fmaf(v0, x0.y, acc.y);
    }
    *((float2*)(Z + (size_t)w * DD) + lane) = acc;
}

// ---- CSR SpMM layer2 fused with output: Ef += A@Z1; write Eout + bf16 Eb ----
__global__ void spmm_csr_out_k(const int* __restrict__ rp,
                               const int* __restrict__ ecol,
                               const float* __restrict__ eval,
                               const float* __restrict__ Zu,
                               const float* __restrict__ Zi,
                               float* __restrict__ Ef,      // pre-holds E0+Z1
                               float* __restrict__ Eout,    // misaligned d_out
                               __nv_bfloat16* __restrict__ Eb) {
    int w = (blockIdx.x * blockDim.x + threadIdx.x) >> 5;
    int lane = threadIdx.x & 31;
    if (w >= NR) return;
    const float* X = (w < N_U) ? Zi : Zu;
    int e = __ldg(rp + w), e1 = __ldg(rp + w + 1);
    float2 acc = make_float2(0.f, 0.f);
    for (; e + 3 < e1; e += 4) {
        int c0 = __ldg(ecol + e),     c1 = __ldg(ecol + e + 1);
        int c2 = __ldg(ecol + e + 2), c3 = __ldg(ecol + e + 3);
        float v0 = __ldg(eval + e),     v1 = __ldg(eval + e + 1);
        float v2 = __ldg(eval + e + 2), v3 = __ldg(eval + e + 3);
        float2 x0 = *(const float2*)(X + (size_t)c0 * DD + lane * 2);
        float2 x1 = *(const float2*)(X + (size_t)c1 * DD + lane * 2);
        float2 x2 = *(const float2*)(X + (size_t)c2 * DD + lane * 2);
        float2 x3 = *(const float2*)(X + (size_t)c3 * DD + lane * 2);
        acc.x = fmaf(v0, x0.x, acc.x); acc.y = fmaf(v0, x0.y, acc.y);
        acc.x = fmaf(v1, x1.x, acc.x); acc.y = fmaf(v1, x1.y, acc.y);
        acc.x = fmaf(v2, x2.x, acc.x); acc.y = fmaf(v2, x2.y, acc.y);
        acc.x = fmaf(v3, x3.x, acc.x); acc.y = fmaf(v3, x3.y, acc.y);
    }
    for (; e < e1; e++) {
        int c0 = __ldg(ecol + e); float v0 = __ldg(eval + e);
        float2 x0 = *(const float2*)(X + (size_t)c0 * DD + lane * 2);
        acc.x = fmaf(v0, x0.x, acc.x); acc.y = fmaf(v0, x0.y, acc.y);
    }
    size_t base = (size_t)w * DD + lane * 2;
    float2 old = *(const float2*)(Ef + base);
    acc.x += old.x; acc.y += old.y;
    *(float2*)(Ef + base) = acc;                 // final fp32 E (aligned scratch)
    Eout[base] = acc.x;                          // misaligned d_out copy
    Eout[base + 1] = acc.y;
    *(__nv_bfloat162*)(Eb + base) = __floats2bfloat162_rn(acc.x, acc.y);
}

// ---------------- prep (both u and i): Ef = E0+Z1 ; M, reg --------------------
__global__ void prep_both(const float* __restrict__ Eu0,
                          const float* __restrict__ Ei0,
                          const float* __restrict__ Zu1,
                          const float* __restrict__ Zi1,
                          const float* __restrict__ Put,
                          const float* __restrict__ Pvt,
                          float* __restrict__ Euf,
                          float* __restrict__ Eif,
                          float* __restrict__ Mi,
                          float* __restrict__ Mu,
                          float* __restrict__ regAcc) {
    const bool isU = blockIdx.x < 2048;
    const int vbid = isU ? blockIdx.x : blockIdx.x - 2048;
    const int vgrid = isU ? 2048 : 1024;
    const int n_rows = isU ? N_U : N_I;
    const float* E0 = isU ? Eu0 : Ei0;
    const float* Z1 = isU ? Zu1 : Zi1;
    const float* P  = isU ? Put : Pvt;
    float* Ef = isU ? Euf : Eif;
    float* Macc = isU ? Mi : Mu;

    int d = threadIdx.x & 63;
    int grp = threadIdx.x >> 6;                 // 0..3
    float m0 = 0, m1 = 0, m2 = 0, m3 = 0, m4 = 0, racc = 0;
    for (int r = vbid * 4 + grp; r < n_rows; r += vgrid * 4) {
        size_t off = (size_t)r * DD + d;
        float e0 = E0[off];
        float t  = e0 + Z1[off];
        Ef[off] = t;
        racc = fmaf(e0, e0, racc);
        m0 = fmaf(__ldg(P + r), t, m0);
        m1 = fmaf(__ldg(P + (size_t)n_rows + r), t, m1);
        m2 = fmaf(__ldg(P + 2 * (size_t)n_rows + r), t, m2);
        m3 = fmaf(__ldg(P + 3 * (size_t)n_rows + r), t, m3);
        m4 = fmaf(__ldg(P + 4 * (size_t)n_rows + r), t, m4);
    }
    __shared__ float sm[4][QQ][DD];
    sm[grp][0][d] = m0; sm[grp][1][d] = m1; sm[grp][2][d] = m2;
    sm[grp][3][d] = m3; sm[grp][4][d] = m4;
    __syncthreads();
    if (grp == 0) {
        #pragma unroll
        for (int q = 0; q < QQ; q++)
            atomicAdd(&Macc[q * DD + d],
                      sm[0][q][d] + sm[1][q][d] + sm[2][q][d] + sm[3][q][d]);
    }
    racc = warp_sum(racc);
    if ((threadIdx.x & 31) == 0) atomicAdd(regAcc, racc);
}

// ------------------------------ G selection ----------------------------------
__global__ void gsel_kernel(const int* __restrict__ uids,
                            const int* __restrict__ pos,
                            const int* __restrict__ neg,
                            const float* __restrict__ Eu0,
                            const float* __restrict__ Ei0,
                            const float* __restrict__ mu_s,
                            const float* __restrict__ mi_s,
                            const float* __restrict__ Mu,
                            const float* __restrict__ Mi,
                            float* __restrict__ G,
                            __nv_bfloat16* __restrict__ Gb) {
    int b = blockIdx.x, d = threadIdx.x;
    const float* E0; const float* ms; const float* M; int id;
    if (b < 512)       { E0 = Eu0; ms = mu_s; M = Mu; id = uids[b]; }
    else if (b < 1024) { E0 = Ei0; ms = mi_s; M = Mi; id = pos[b - 512]; }
    else               { E0 = Ei0; ms = mi_s; M = Mi; id = neg[b - 1024]; }
    float v = E0[(size_t)id * DD + d];
    #pragma unroll
    for (int q = 0; q < QQ; q++)
        v = fmaf(ms[(size_t)id * QQ + q], M[q * DD + d], v);
    float v5 = 5.0f * v;
    G[b * DD + d] = v5;
    Gb[b * DD + d] = __float2bfloat16(v5);
}

// --------- tensor-core logits: bf16 mma.16816 GEMM + exp + row-sum -----------
// one launch for both sides; blockIdx < ublocks -> user side
#define SMEM_MMA (2 * 128 * 144)
__global__ __launch_bounds__(256, 2)
void logits_mma(const __nv_bfloat16* __restrict__ Gbu,
                const __nv_bfloat16* __restrict__ Gbi,
                const __nv_bfloat16* __restrict__ Ebu,
                const __nv_bfloat16* __restrict__ Ebi,
                float* __restrict__ Su, float* __restrict__ Si,
                int ublocks) {
    extern __shared__ char smc[];
    const uint32_t sA = smem_u32(smc);
    const uint32_t sB = sA + 128 * 144;
    const int tid = threadIdx.x;

    const bool isU = ((int)blockIdx.x < ublocks);
    const int bid = isU ? blockIdx.x : blockIdx.x - ublocks;
    const int Mtiles = isU ? 4 : 8;
    const int N = isU ? N_U : N_I;
    const __nv_bfloat16* Gb = isU ? Gbu : Gbi;
    const __nv_bfloat16* Eb = isU ? Ebu : Ebi;
    float* S = isU ? Su : Si;
    const int mt = bid % Mtiles;
    const long n0 = (long)(bid / Mtiles) * 128;

    #pragma unroll
    for (int it = 0; it < 4; it++) {
        int idx = it * 256 + tid;          // 0..1023
        int row = idx >> 3, c = idx & 7;
        uint4 v = *(const uint4*)(Gb + ((size_t)(mt * 128 + row)) * DD + c * 8);
        *(uint4*)(smc + row * 144 + c * 16) = v;
    }
    #pragma unroll
    for (int it = 0; it < 4; it++) {
        int idx = it * 256 + tid;
        int row = idx >> 3, c = idx & 7;
        long n = n0 + row;
        uint4 v = make_uint4(0, 0, 0, 0);
        if (n < N) v = *(const uint4*)(Eb + n * DD + c * 8);
        *(uint4*)(smc + 128 * 144 + row * 144 + c * 16) = v;
    }
    __syncthreads();

    const int wid = tid >> 5, lane = tid & 31;
    const int wm = (wid & 3) * 32;
    const int wn = (wid >> 2) * 64;

    float d[2][8][4];
    #pragma unroll
    for (int mi = 0; mi < 2; mi++)
        #pragma unroll
        for (int ni = 0; ni < 8; ni++)
            #pragma unroll
            for (int j = 0; j < 4; j++) d[mi][ni][j] = 0.f;

    const int lrowA = (lane & 7) + ((lane & 8) ? 8 : 0);
    const int lcolA = (lane & 16) ? 8 : 0;
    const int lrowB = (lane & 7) + ((lane & 16) ? 8 : 0);
    const int lcolB = (lane & 8) ? 8 : 0;

    #pragma unroll
    for (int ks = 0; ks < 4; ks++) {
        const int k0 = ks * 16;
        unsigned a[2][4];
        #pragma unroll
        for (int mi = 0; mi < 2; mi++) {
            uint32_t addr = sA + (wm + mi * 16 + lrowA) * 144 + (k0 + lcolA) * 2;
            ldmx4(a[mi][0], a[mi][1], a[mi][2], a[mi][3], addr);
        }
        #pragma unroll
        for (int np = 0; np < 4; np++) {
            unsigned b[4];
            uint32_t addr = sB + (wn + np * 16 + lrowB) * 144 + (k0 + lcolB) * 2;
            ldmx4(b[0], b[1], b[2], b[3], addr);
            #pragma unroll
            for (int mi = 0; mi < 2; mi++) {
                mma16816(d[mi][np * 2 + 0], a[mi], b + 0);
                mma16816(d[mi][np * 2 + 1], a[mi], b + 2);
            }
        }
    }

    const bool full = (n0 + 128 <= N);
    const int r4 = lane >> 2;
    #pragma unroll
    for (int mi = 0; mi < 2; mi++) {
        float slo = 0.f, shi = 0.f;
        #pragma unroll
        for (int ni = 0; ni < 8; ni++) {
            if (full) {
                slo += __expf(d[mi][ni][0]) + __expf(d[mi][ni][1]);
                shi += __expf(d[mi][ni][2]) + __expf(d[mi][ni][3]);
            } else {
                long c = n0 + wn + ni * 8 + (lane & 3) * 2;
                if (c < N)     { slo += __expf(d[mi][ni][0]); shi += __expf(d[mi][ni][2]); }
                if (c + 1 < N) { slo += __expf(d[mi][ni][1]); shi += __expf(d[mi][ni][3]); }
            }
        }
        slo += __shfl_xor_sync(0xffffffffu, slo, 1);
        slo += __shfl_xor_sync(0xffffffffu, slo, 2);
        shi += __shfl_xor_sync(0xffffffffu, shi, 1);
        shi += __shfl_xor_sync(0xffffffffu, shi, 2);
        if ((lane & 3) == 0) {
            atomicAdd(&S[mt * 128 + wm + mi * 16 + r4], slo);
            atomicAdd(&S[mt * 128 + wm + mi * 16 + 8 + r4], shi);
        }
    }
}

// -------------------- pos / BPR / extra-loss (warp-per-task) -----------------
__global__ void small_loss_kernel(const int* __restrict__ uids,
                                  const int* __restrict__ pos,
                                  const int* __restrict__ neg,
                                  const float* __restrict__ Eu,
                                  const float* __restrict__ Ei,
                                  const float* __restrict__ Gu,
                                  const float* __restrict__ Gi,
                                  const int* __restrict__ unpop,
                                  const int* __restrict__ popi,
                                  float* __restrict__ sc) {
    int gtid = blockIdx.x * blockDim.x + threadIdx.x;
    int wid = gtid >> 5, lane = gtid & 31;
    if (wid < 512) {                       // pos_u
        int b = wid, u = uids[b];
        float s = Gu[b * DD + lane] * Eu[(size_t)u * DD + lane]
                + Gu[b * DD + 32 + lane] * Eu[(size_t)u * DD + 32 + lane];
        s = warp_sum(s);
        if (lane == 0) atomicAdd(&sc[1], fminf(fmaxf(s, -5.0f), 5.0f));
    } else if (wid < 1536) {               // pos_i
        int b = wid - 512;
        int id = (b < 512) ? pos[b] : neg[b - 512];
        float s = Gi[b * DD + lane] * Ei[(size_t)id * DD + lane]
                + Gi[b * DD + 32 + lane] * Ei[(size_t)id * DD + 32 + lane];
        s = warp_sum(s);
        if (lane == 0) atomicAdd(&sc[2], fminf(fmaxf(s, -5.0f), 5.0f));
    } else if (wid < 2048) {               // BPR
        int b = wid - 1536, u = uids[b], p = pos[b], nn = neg[b];
        float eu0 = Eu[(size_t)u * DD + lane], eu1 = Eu[(size_t)u * DD + 32 + lane];
        float sp = eu0 * Ei[(size_t)p * DD + lane]  + eu1 * Ei[(size_t)p * DD + 32 + lane];
        float sn = eu0 * Ei[(size_t)nn * DD + lane] + eu1 * Ei[(size_t)nn * DD + 32 + lane];
        sp = warp_sum(sp);
        sn = warp_sum(sn);
        if (lane == 0) {
            float x = sp - sn;
            float t = (x > 0.f) ? log1pf(expf(-x)) : (-x + log1pf(expf(x)));
            atomicAdd(&sc[3], t);
        }
    } else {                               // extra-loss pairs
        int p = wid - 2048;
        if (p >= 64 * 8 * 32) return;
        int ig = p >> 8, rem = p & 255, ui = rem >> 5, pi = rem & 31;
        int a = unpop[ig * 8 + ui];
        int c = popi[ig * 32 + pi];
        float d0 = Ei[(size_t)a * DD + lane] - Ei[(size_t)c * DD + lane];
        float d1 = Ei[(size_t)a * DD + 32 + lane] - Ei[(size_t)c * DD + 32 + lane];
        float s = warp_sum(d0 * d0 + d1 * d1);
        if (lane == 0) atomicAdd(&sc[4], sqrtf(s));
    }
}

// ------------------------------ weight L2 reg --------------------------------
__global__ void reg_w_kernel(const float* __restrict__ W1,
                             const float* __restrict__ b1,
                             const float* __restrict__ W2,
                             const float* __restrict__ b2,
                             float* __restrict__ acc) {
    int t = blockIdx.x * blockDim.x + threadIdx.x;
    int total = gridDim.x * blockDim.x;
    float s = 0.f;
    for (int i = t; i < 768 * 64; i += total) {
        float a = W1[i]; s = fmaf(a, a, s);
        float c = W2[i]; s = fmaf(c, c, s);
    }
    if (t < 64) {
        float a = b1[t]; s = fmaf(a, a, s);
        float c = b2[t]; s = fmaf(c, c, s);
    }
    s = warp_sum(s);
    if ((threadIdx.x & 31) == 0) atomicAdd(acc, s);
}

// -------------------------------- finalize -----------------------------------
__global__ void finalize_kernel(const float* __restrict__ su,
                                const float* __restrict__ si,
                                const float* __restrict__ sc,
                                float* __restrict__ out) {
    __shared__ float s_lu[16], s_li[16];
    int tid = threadIdx.x;   // 512 threads
    float lu = logf(su[tid] + 1e-8f);
    float li = logf(si[tid] + 1e-8f) + logf(si[tid + 512] + 1e-8f);
    lu = warp_sum(lu);
    li = warp_sum(li);
    if ((tid & 31) == 0) { s_lu[tid >> 5] = lu; s_li[tid >> 5] = li; }
    __syncthreads();
    if (tid == 0) {
        float LU = 0.f, LI = 0.f;
        #pragma unroll
        for (int w = 0; w < 16; w++) { LU += s_lu[w]; LI += s_li[w]; }
        float neg_score = LU / 512.f + LI / 1024.f;
        float pos_score = sc[1] / 512.f + sc[2] / 1024.f;
        float loss_s = -pos_score + neg_score;
        float loss_r = sc[3] / 512.f;
        float loss_reg = 1e-7f * sc[0];
        float extra = sc[4] * (1.f / 32.f);
        float loss = loss_r + 0.2f * loss_s + loss_reg + 0.01f * extra;
        out[0] = loss;
        out[1] = loss_r;
        out[2] = 0.2f * loss_s;
    }
}

// ------------------------------- launcher ------------------------------------
extern "C" void kernel_launch(void* const* d_in, const int* in_sizes, int n_in,
                              void* d_out, int out_size) {
    const int*   uids     = (const int*)d_in[0];
    const int*   pos      = (const int*)d_in[1];
    const int*   neg      = (const int*)d_in[2];
    const int*   adj_rows = (const int*)d_in[3];
    const int*   adj_cols = (const int*)d_in[4];
    const float* adj_vals = (const float*)d_in[5];
    const float* E_u_0    = (const float*)d_in[6];
    const float* E_i_0    = (const float*)d_in[7];
    const float* u_mul_s  = (const float*)d_in[8];
    const float* vt       = (const float*)d_in[9];
    const float* v_mul_s  = (const float*)d_in[10];
    const float* ut       = (const float*)d_in[11];
    const float* W_api    = (const float*)d_in[12];
    const float* b_api    = (const float*)d_in[13];
    const float* W_mashup = (const float*)d_in[14];
    const float* b_mashup = (const float*)d_in[15];
    const float* pos_api  = (const float*)d_in[16];
    const float* neg_api  = (const float*)d_in[17];
    const float* mashup   = (const float*)d_in[18];
    const int*   unpop    = (const int*)d_in[19];
    const int*   popi     = (const int*)d_in[20];

    float* out = (float*)d_out;
    const size_t EMB = (size_t)512 * 768;
    float* out_mashup = out + 3;
    float* out_posapi = out + 3 + EMB;
    float* out_negapi = out + 3 + 2 * EMB;
    float* Eu_out = out + 3 + 3 * EMB;

    float *Zb, *Efb, *Sm, *G, *evalp;
    __nv_bfloat16 *Eb, *Gb;
    int *cnt, *rp, *off, *bsum, *ecol;
    cudaGetSymbolAddress((void**)&Zb,   g_Z);
    cudaGetSymbolAddress((void**)&Efb,  g_Ef);
    cudaGetSymbolAddress((void**)&Eb,   g_Eb);
    cudaGetSymbolAddress((void**)&Sm,   g_small);
    cudaGetSymbolAddress((void**)&G,    g_G);
    cudaGetSymbolAddress((void**)&Gb,   g_Gb);
    cudaGetSymbolAddress((void**)&cnt,  g_cnt);
    cudaGetSymbolAddress((void**)&rp,   g_rp);
    cudaGetSymbolAddress((void**)&off,  g_off);
    cudaGetSymbolAddress((void**)&bsum, g_bsum);
    cudaGetSymbolAddress((void**)&ecol, g_ecol);
    cudaGetSymbolAddress((void**)&evalp, g_eval);

    float* Zu1 = Zb;
    float* Zi1 = Zu1 + (size_t)N_U * DD;
    float* Euf = Efb;
    float* Eif = Euf + (size_t)N_U * DD;
    __nv_bfloat16* Eub = Eb;
    __nv_bfloat16* Eib = Eub + (size_t)N_U * DD;
    float* Mu = Sm + OFF_MU;
    float* Mi = Sm + OFF_MI;
    float* su = Sm + OFF_SU;
    float* si = Sm + OFF_SI;
    float* sc = Sm + OFF_SC;
    float* Gu = G;
    float* Gi = G + (size_t)BB * DD;
    __nv_bfloat16* Gub = Gb;
    __nv_bfloat16* Gib = Gub + (size_t)BB * DD;

    cudaFuncSetAttribute(logits_mma,
                         cudaFuncAttributeMaxDynamicSharedMemorySize, SMEM_MMA);

    cudaMemsetAsync(cnt, 0, NR * 4);
    cudaMemsetAsync(Sm, 0, 2304 * 4);

    cudaMemcpyAsync(out_mashup, mashup, EMB * 4, cudaMemcpyDeviceToDevice);
    cudaMemcpyAsync(out_posapi, pos_api, EMB * 4, cudaMemcpyDeviceToDevice);
    cudaMemcpyAsync(out_negapi, neg_api, EMB * 4, cudaMemcpyDeviceToDevice);

    // ---- CSR build (u rows then i rows, concatenated edge array) ----
    const int e2_blocks = (2 * NNZ_E + 255) / 256;
    hist_k<<<e2_blocks, 256>>>(adj_rows, adj_cols, cnt);
    scan1_k<<<SCAN_NB, SCAN_BS>>>(cnt, bsum);
    scan2_k<<<1, 1024>>>(bsum);
    scan3_k<<<SCAN_NB, SCAN_BS>>>(cnt, bsum, rp, off);
    scatter_k<<<e2_blocks, 256>>>(adj_rows, adj_cols, adj_vals, off, ecol, evalp);

    // ---- layer 1: Z1 = A @ E0 ----
    const int csr_blocks = (NR * 32 + 255) / 256;
    spmm_csr_k<<<csr_blocks, 256>>>(rp, ecol, evalp, E_u_0, E_i_0, Zb);
    // Ef = E0 + Z1 ; M reductions ; embedding L2 reg
    prep_both<<<3072, 256>>>(E_u_0, E_i_0, Zu1, Zi1, ut, vt,
                             Euf, Eif, Mi, Mu, sc);
    // ---- layer 2 (fused with E output + bf16 conversion) ----
    spmm_csr_out_k<<<csr_blocks, 256>>>(rp, ecol, evalp, Zu1, Zi1,
                                        Efb, Eu_out, Eb);

    reg_w_kernel<<<192, 256>>>(W_api, b_api, W_mashup, b_mashup, sc);
    gsel_kernel<<<1536, 64>>>(uids, pos, neg, E_u_0, E_i_0,
                              u_mul_s, v_mul_s, Mu, Mi, G, Gb);

    // ---- tensor-core logits (both sides in one launch) ----
    const int ntu = (N_U + 127) / 128;   // 782
    const int nti = (N_I + 127) / 128;   // 391
    const int ublocks = 4 * ntu;
    logits_mma<<<ublocks + 8 * nti, 256, SMEM_MMA>>>(Gub, Gib, Eub, Eib,
                                                     su, si, ublocks);

    small_loss_kernel<<<2304, 256>>>(uids, pos, neg, Euf, Eif, Gu, Gi,
                                     unpop, popi, sc);

    finalize_kernel<<<1, 512>>>(su, si, sc, out);
}

// round 14
// speedup vs baseline: 1.9841x; 1.0064x over previous
#include <cuda_runtime.h>
#include <cuda_bf16.h>
#include <cstdint>
#include <cstddef>

#define N_U 100000
#define N_I 50000
#define NR  (N_U + N_I)
#define DD  64
#define QQ  5
#define NNZ_E 1000000
#define BB  512
#define SCAN_BS 256
#define SCAN_NB ((NR + SCAN_BS - 1) / SCAN_BS)   // 586

typedef unsigned long long ull;

// ------------------------- scratch (device globals) -------------------------
__device__ __align__(16) __nv_bfloat16 g_E0b[(size_t)NR * DD];   // bf16 E0 (u|i)
__device__ __align__(16) __nv_bfloat16 g_Zb[(size_t)NR * DD];    // bf16 Z1 (u|i)
__device__ __align__(16) float g_Ef[(size_t)NR * DD];            // final E fp32 (u|i)
__device__ __align__(16) __nv_bfloat16 g_Eb[(size_t)NR * DD];    // bf16 final E
__device__ __align__(16) float g_small[2304];  // Mu(320) Mi(320) su(512) si(1024) sc(8)
__device__ __align__(16) float g_G[3 * BB * DD];
__device__ __align__(16) __nv_bfloat16 g_Gb[3 * BB * DD];
// CSR scratch
__device__ int   g_cnt[NR];
__device__ int   g_rp[NR + 1];
__device__ int   g_off[NR];
__device__ int   g_bsum[1024];
__device__ __align__(16) int   g_ecol[2 * NNZ_E];
__device__ __align__(16) float g_eval[2 * NNZ_E];

#define OFF_MU 0
#define OFF_MI 320
#define OFF_SU 640
#define OFF_SI 1152
#define OFF_SC 2176

// ------------------------------ helpers -------------------------------------
__device__ __forceinline__ float warp_sum(float v) {
    #pragma unroll
    for (int o = 16; o; o >>= 1) v += __shfl_xor_sync(0xffffffffu, v, o);
    return v;
}
__device__ __forceinline__ int warp_sum_i(int v) {
    #pragma unroll
    for (int o = 16; o; o >>= 1) v += __shfl_xor_sync(0xffffffffu, v, o);
    return v;
}
__device__ __forceinline__ uint32_t smem_u32(const void* p) {
    uint32_t a;
    asm("{ .reg .u64 t; cvta.to.shared.u64 t, %1; cvt.u32.u64 %0, t; }" : "=r"(a) : "l"(p));
    return a;
}
__device__ __forceinline__ void ldmx4(unsigned& r0, unsigned& r1,
                                      unsigned& r2, unsigned& r3, uint32_t addr) {
    asm volatile("ldmatrix.sync.aligned.m8n8.x4.shared.b16 {%0,%1,%2,%3}, [%4];"
                 : "=r"(r0), "=r"(r1), "=r"(r2), "=r"(r3) : "r"(addr));
}
__device__ __forceinline__ void mma16816(float* d, const unsigned* a, const unsigned* b) {
    asm volatile("mma.sync.aligned.m16n8k16.row.col.f32.bf16.bf16.f32 "
                 "{%0,%1,%2,%3}, {%4,%5,%6,%7}, {%8,%9}, {%0,%1,%2,%3};"
                 : "+f"(d[0]), "+f"(d[1]), "+f"(d[2]), "+f"(d[3])
                 : "r"(a[0]), "r"(a[1]), "r"(a[2]), "r"(a[3]), "r"(b[0]), "r"(b[1]));
}

// ------------------- E0 -> bf16 conversion (u then i) -------------------------
__global__ void conv0_k(const float* __restrict__ Eu0,
                        const float* __restrict__ Ei0,
                        __nv_bfloat16* __restrict__ E0b) {
    size_t i = (size_t)blockIdx.x * blockDim.x + threadIdx.x;   // float4 units
    const size_t nu4 = (size_t)N_U * DD / 4;
    const size_t n4 = (size_t)NR * DD / 4;
    if (i >= n4) return;
    float4 v = (i < nu4) ? ((const float4*)Eu0)[i]
                         : ((const float4*)Ei0)[i - nu4];
    *(__nv_bfloat162*)(E0b + i * 4)     = __floats2bfloat162_rn(v.x, v.y);
    *(__nv_bfloat162*)(E0b + i * 4 + 2) = __floats2bfloat162_rn(v.z, v.w);
}

// ------------------------------ CSR build ------------------------------------
__global__ void hist_k(const int* __restrict__ rows, const int* __restrict__ cols,
                       int* __restrict__ cnt) {
    int t = blockIdx.x * blockDim.x + threadIdx.x;
    if (t < NNZ_E) atomicAdd(&cnt[__ldg(rows + t)], 1);
    else if (t < 2 * NNZ_E) atomicAdd(&cnt[N_U + __ldg(cols + (t - NNZ_E))], 1);
}

__global__ void scan1_k(const int* __restrict__ cnt, int* __restrict__ bsum) {
    __shared__ int sh[8];
    int i = blockIdx.x * SCAN_BS + threadIdx.x;
    int v = (i < NR) ? cnt[i] : 0;
    v = warp_sum_i(v);
    if ((threadIdx.x & 31) == 0) sh[threadIdx.x >> 5] = v;
    __syncthreads();
    if (threadIdx.x == 0) {
        int t = 0;
        #pragma unroll
        for (int w = 0; w < 8; w++) t += sh[w];
        bsum[blockIdx.x] = t;
    }
}

__global__ void scan2_k(int* __restrict__ bsum) {    // 1 block, 1024 threads
    __shared__ int sh[1024];
    int tid = threadIdx.x;
    int v = (tid < SCAN_NB) ? bsum[tid] : 0;
    sh[tid] = v;
    __syncthreads();
    for (int o = 1; o < 1024; o <<= 1) {
        int t = (tid >= o) ? sh[tid - o] : 0;
        __syncthreads();
        sh[tid] += t;
        __syncthreads();
    }
    if (tid < SCAN_NB) bsum[tid] = sh[tid] - v;      // exclusive
}

__global__ void scan3_k(const int* __restrict__ cnt, const int* __restrict__ bsum,
                        int* __restrict__ rp, int* __restrict__ off) {
    __shared__ int sh[SCAN_BS];
    int tid = threadIdx.x;
    int i = blockIdx.x * SCAN_BS + tid;
    int v = (i < NR) ? cnt[i] : 0;
    sh[tid] = v;
    __syncthreads();
    for (int o = 1; o < SCAN_BS; o <<= 1) {
        int t = (tid >= o) ? sh[tid - o] : 0;
        __syncthreads();
        sh[tid] += t;
        __syncthreads();
    }
    int excl = sh[tid] - v + bsum[blockIdx.x];
    if (i < NR) { rp[i] = excl; off[i] = excl; }
    if (i == NR - 1) rp[NR] = excl + v;
}

__global__ void scatter_k(const int* __restrict__ rows, const int* __restrict__ cols,
                          const float* __restrict__ vals,
                          int* __restrict__ off, int* __restrict__ ecol,
                          float* __restrict__ eval) {
    int t = blockIdx.x * blockDim.x + threadIdx.x;
    int r, c; float v;
    if (t < NNZ_E) {
        r = __ldg(rows + t); c = __ldg(cols + t); v = __ldg(vals + t);
    } else if (t < 2 * NNZ_E) {
        int e = t - NNZ_E;
        r = N_U + __ldg(cols + e); c = __ldg(rows + e); v = __ldg(vals + e);
    } else return;
    int slot = atomicAdd(&off[r], 1);
    ecol[slot] = c; eval[slot] = v;
}

// ---------------- CSR SpMM layer1: warp per row, bf16 gather ------------------
// gathers from E0b (other side), accumulates fp32, writes bf16 Zb.
__global__ void spmm_csr_k(const int* __restrict__ rp,
                           const int* __restrict__ ecol,
                           const float* __restrict__ eval,
                           const __nv_bfloat16* __restrict__ E0b,
                           __nv_bfloat16* __restrict__ Zb) {
    int w = (blockIdx.x * blockDim.x + threadIdx.x) >> 5;
    int lane = threadIdx.x & 31;
    if (w >= NR) return;
    // dest u-row gathers item rows (offset N_U in E0b); dest i-row gathers user rows
    const __nv_bfloat16* X = (w < N_U) ? (E0b + (size_t)N_U * DD) : E0b;
    int e = __ldg(rp + w), e1 = __ldg(rp + w + 1);
    float2 acc = make_float2(0.f, 0.f);
    for (; e + 3 < e1; e += 4) {
        int c0 = __ldg(ecol + e),     c1 = __ldg(ecol + e + 1);
        int c2 = __ldg(ecol + e + 2), c3 = __ldg(ecol + e + 3);
        float v0 = __ldg(eval + e),     v1 = __ldg(eval + e + 1);
        float v2 = __ldg(eval + e + 2), v3 = __ldg(eval + e + 3);
        float2 x0 = __bfloat1622float2(*(const __nv_bfloat162*)(X + (size_t)c0 * DD + lane * 2));
        float2 x1 = __bfloat1622float2(*(const __nv_bfloat162*)(X + (size_t)c1 * DD + lane * 2));
        float2 x2 = __bfloat1622float2(*(const __nv_bfloat162*)(X + (size_t)c2 * DD + lane * 2));
        float2 x3 = __bfloat1622float2(*(const __nv_bfloat162*)(X + (size_t)c3 * DD + lane * 2));
        acc.x = fmaf(v0, x0.x, acc.x); acc.y = fmaf(v0, x0.y, acc.y);
        acc.x = fmaf(v1, x1.x, acc.x); acc.y = fmaf(v1, x1.y, acc.y);
        acc.x = fmaf(v2, x2.x, acc.x); acc.y = fmaf(v2, x2.y, acc.y);
        acc.x = fmaf(v3, x3.x, acc.x); acc.y = fmaf(v3, x3.y, acc.y);
    }
    for (; e < e1; e++) {
        int c0 = __ldg(ecol + e); float v0 = __ldg(eval + e);
        float2 x0 = __bfloat1622float2(*(const __nv_bfloat162*)(X + (size_t)c0 * DD + lane * 2));
        acc.x = fmaf(v0, x0.x, acc.x); acc.y = fmaf(v0, x0.y, acc.y);
    }
    *(__nv_bfloat162*)(Zb + (size_t)w * DD + lane * 2) = __floats2bfloat162_rn(acc.x, acc.y);
}

// ---- CSR SpMM layer2 (bf16 gather) fused out: Ef += A@Z1; Eout; bf16 Eb -----
__global__ void spmm_csr_out_k(const int* __restrict__ rp,
                               const int* __restrict__ ecol,
                               const float* __restrict__ eval,
                               const __nv_bfloat16* __restrict__ Zb,
                               float* __restrict__ Ef,      // pre-holds E0+Z1
                               float* __restrict__ Eout,    // misaligned d_out
                               __nv_bfloat16* __restrict__ Eb) {
    int w = (blockIdx.x * blockDim.x + threadIdx.x) >> 5;
    int lane = threadIdx.x & 31;
    if (w >= NR) return;
    const __nv_bfloat16* X = (w < N_U) ? (Zb + (size_t)N_U * DD) : Zb;
    int e = __ldg(rp + w), e1 = __ldg(rp + w + 1);
    float2 acc = make_float2(0.f, 0.f);
    for (; e + 3 < e1; e += 4) {
        int c0 = __ldg(ecol + e),     c1 = __ldg(ecol + e + 1);
        int c2 = __ldg(ecol + e + 2), c3 = __ldg(ecol + e + 3);
        float v0 = __ldg(eval + e),     v1 = __ldg(eval + e + 1);
        float v2 = __ldg(eval + e + 2), v3 = __ldg(eval + e + 3);
        float2 x0 = __bfloat1622float2(*(const __nv_bfloat162*)(X + (size_t)c0 * DD + lane * 2));
        float2 x1 = __bfloat1622float2(*(const __nv_bfloat162*)(X + (size_t)c1 * DD + lane * 2));
        float2 x2 = __bfloat1622float2(*(const __nv_bfloat162*)(X + (size_t)c2 * DD + lane * 2));
        float2 x3 = __bfloat1622float2(*(const __nv_bfloat162*)(X + (size_t)c3 * DD + lane * 2));
        acc.x = fmaf(v0, x0.x, acc.x); acc.y = fmaf(v0, x0.y, acc.y);
        acc.x = fmaf(v1, x1.x, acc.x); acc.y = fmaf(v1, x1.y, acc.y);
        acc.x = fmaf(v2, x2.x, acc.x); acc.y = fmaf(v2, x2.y, acc.y);
        acc.x = fmaf(v3, x3.x, acc.x); acc.y = fmaf(v3, x3.y, acc.y);
    }
    for (; e < e1; e++) {
        int c0 = __ldg(ecol + e); float v0 = __ldg(eval + e);
        float2 x0 = __bfloat1622float2(*(const __nv_bfloat162*)(X + (size_t)c0 * DD + lane * 2));
        acc.x = fmaf(v0, x0.x, acc.x); acc.y = fmaf(v0, x0.y, acc.y);
    }
    size_t base = (size_t)w * DD + lane * 2;
    float2 old = *(const float2*)(Ef + base);
    acc.x += old.x; acc.y += old.y;
    *(float2*)(Ef + base) = acc;                 // final fp32 E (aligned scratch)
    Eout[base] = acc.x;                          // misaligned d_out copy
    Eout[base + 1] = acc.y;
    *(__nv_bfloat162*)(Eb + base) = __floats2bfloat162_rn(acc.x, acc.y);
}

// ------------- prep (both): Ef = E0 + Zb(bf16) ; M, reg -----------------------
__global__ void prep_both(const float* __restrict__ Eu0,
                          const float* __restrict__ Ei0,
                          const __nv_bfloat16* __restrict__ Zb,
                          const float* __restrict__ Put,
                          const float* __restrict__ Pvt,
                          float* __restrict__ Euf,
                          float* __restrict__ Eif,
                          float* __restrict__ Mi,
                          float* __restrict__ Mu,
                          float* __restrict__ regAcc) {
    const bool isU = blockIdx.x < 2048;
    const int vbid = isU ? blockIdx.x : blockIdx.x - 2048;
    const int vgrid = isU ? 2048 : 1024;
    const int n_rows = isU ? N_U : N_I;
    const float* E0 = isU ? Eu0 : Ei0;
    const __nv_bfloat16* Z1 = isU ? Zb : (Zb + (size_t)N_U * DD);
    const float* P  = isU ? Put : Pvt;
    float* Ef = isU ? Euf : Eif;
    float* Macc = isU ? Mi : Mu;

    int d = threadIdx.x & 63;
    int grp = threadIdx.x >> 6;                 // 0..3
    float m0 = 0, m1 = 0, m2 = 0, m3 = 0, m4 = 0, racc = 0;
    for (int r = vbid * 4 + grp; r < n_rows; r += vgrid * 4) {
        size_t off = (size_t)r * DD + d;
        float e0 = E0[off];
        float t  = e0 + __bfloat162float(Z1[off]);
        Ef[off] = t;
        racc = fmaf(e0, e0, racc);
        m0 = fmaf(__ldg(P + r), t, m0);
        m1 = fmaf(__ldg(P + (size_t)n_rows + r), t, m1);
        m2 = fmaf(__ldg(P + 2 * (size_t)n_rows + r), t, m2);
        m3 = fmaf(__ldg(P + 3 * (size_t)n_rows + r), t, m3);
        m4 = fmaf(__ldg(P + 4 * (size_t)n_rows + r), t, m4);
    }
    __shared__ float sm[4][QQ][DD];
    sm[grp][0][d] = m0; sm[grp][1][d] = m1; sm[grp][2][d] = m2;
    sm[grp][3][d] = m3; sm[grp][4][d] = m4;
    __syncthreads();
    if (grp == 0) {
        #pragma unroll
        for (int q = 0; q < QQ; q++)
            atomicAdd(&Macc[q * DD + d],
                      sm[0][q][d] + sm[1][q][d] + sm[2][q][d] + sm[3][q][d]);
    }
    racc = warp_sum(racc);
    if ((threadIdx.x & 31) == 0) atomicAdd(regAcc, racc);
}

// ------------------------------ G selection ----------------------------------
__global__ void gsel_kernel(const int* __restrict__ uids,
                            const int* __restrict__ pos,
                            const int* __restrict__ neg,
                            const float* __restrict__ Eu0,
                            const float* __restrict__ Ei0,
                            const float* __restrict__ mu_s,
                            const float* __restrict__ mi_s,
                            const float* __restrict__ Mu,
                            const float* __restrict__ Mi,
                            float* __restrict__ G,
                            __nv_bfloat16* __restrict__ Gb) {
    int b = blockIdx.x, d = threadIdx.x;
    const float* E0; const float* ms; const float* M; int id;
    if (b < 512)       { E0 = Eu0; ms = mu_s; M = Mu; id = uids[b]; }
    else if (b < 1024) { E0 = Ei0; ms = mi_s; M = Mi; id = pos[b - 512]; }
    else               { E0 = Ei0; ms = mi_s; M = Mi; id = neg[b - 1024]; }
    float v = E0[(size_t)id * DD + d];
    #pragma unroll
    for (int q = 0; q < QQ; q++)
        v = fmaf(ms[(size_t)id * QQ + q], M[q * DD + d], v);
    float v5 = 5.0f * v;
    G[b * DD + d] = v5;
    Gb[b * DD + d] = __float2bfloat16(v5);
}

// --------- tensor-core logits: bf16 mma.16816 GEMM + exp + row-sum -----------
// one launch for both sides; blockIdx < ublocks -> user side
#define SMEM_MMA (2 * 128 * 144)
__global__ __launch_bounds__(256, 2)
void logits_mma(const __nv_bfloat16* __restrict__ Gbu,
                const __nv_bfloat16* __restrict__ Gbi,
                const __nv_bfloat16* __restrict__ Ebu,
                const __nv_bfloat16* __restrict__ Ebi,
                float* __restrict__ Su, float* __restrict__ Si,
                int ublocks) {
    extern __shared__ char smc[];
    const uint32_t sA = smem_u32(smc);
    const uint32_t sB = sA + 128 * 144;
    const int tid = threadIdx.x;

    const bool isU = ((int)blockIdx.x < ublocks);
    const int bid = isU ? blockIdx.x : blockIdx.x - ublocks;
    const int Mtiles = isU ? 4 : 8;
    const int N = isU ? N_U : N_I;
    const __nv_bfloat16* Gb = isU ? Gbu : Gbi;
    const __nv_bfloat16* Eb = isU ? Ebu : Ebi;
    float* S = isU ? Su : Si;
    const int mt = bid % Mtiles;
    const long n0 = (long)(bid / Mtiles) * 128;

    #pragma unroll
    for (int it = 0; it < 4; it++) {
        int idx = it * 256 + tid;          // 0..1023
        int row = idx >> 3, c = idx & 7;
        uint4 v = *(const uint4*)(Gb + ((size_t)(mt * 128 + row)) * DD + c * 8);
        *(uint4*)(smc + row * 144 + c * 16) = v;
    }
    #pragma unroll
    for (int it = 0; it < 4; it++) {
        int idx = it * 256 + tid;
        int row = idx >> 3, c = idx & 7;
        long n = n0 + row;
        uint4 v = make_uint4(0, 0, 0, 0);
        if (n < N) v = *(const uint4*)(Eb + n * DD + c * 8);
        *(uint4*)(smc + 128 * 144 + row * 144 + c * 16) = v;
    }
    __syncthreads();

    const int wid = tid >> 5, lane = tid & 31;
    const int wm = (wid & 3) * 32;
    const int wn = (wid >> 2) * 64;

    float d[2][8][4];
    #pragma unroll
    for (int mi = 0; mi < 2; mi++)
        #pragma unroll
        for (int ni = 0; ni < 8; ni++)
            #pragma unroll
            for (int j = 0; j < 4; j++) d[mi][ni][j] = 0.f;

    const int lrowA = (lane & 7) + ((lane & 8) ? 8 : 0);
    const int lcolA = (lane & 16) ? 8 : 0;
    const int lrowB = (lane & 7) + ((lane & 16) ? 8 : 0);
    const int lcolB = (lane & 8) ? 8 : 0;

    #pragma unroll
    for (int ks = 0; ks < 4; ks++) {
        const int k0 = ks * 16;
        unsigned a[2][4];
        #pragma unroll
        for (int mi = 0; mi < 2; mi++) {
            uint32_t addr = sA + (wm + mi * 16 + lrowA) * 144 + (k0 + lcolA) * 2;
            ldmx4(a[mi][0], a[mi][1], a[mi][2], a[mi][3], addr);
        }
        #pragma unroll
        for (int np = 0; np < 4; np++) {
            unsigned b[4];
            uint32_t addr = sB + (wn + np * 16 + lrowB) * 144 + (k0 + lcolB) * 2;
            ldmx4(b[0], b[1], b[2], b[3], addr);
            #pragma unroll
            for (int mi = 0; mi < 2; mi++) {
                mma16816(d[mi][np * 2 + 0], a[mi], b + 0);
                mma16816(d[mi][np * 2 + 1], a[mi], b + 2);
            }
        }
    }

    const bool full = (n0 + 128 <= N);
    const int r4 = lane >> 2;
    #pragma unroll
    for (int mi = 0; mi < 2; mi++) {
        float slo = 0.f, shi = 0.f;
        #pragma unroll
        for (int ni = 0; ni < 8; ni++) {
            if (full) {
                slo += __expf(d[mi][ni][0]) + __expf(d[mi][ni][1]);
                shi += __expf(d[mi][ni][2]) + __expf(d[mi][ni][3]);
            } else {
                long c = n0 + wn + ni * 8 + (lane & 3) * 2;
                if (c < N)     { slo += __expf(d[mi][ni][0]); shi += __expf(d[mi][ni][2]); }
                if (c + 1 < N) { slo += __expf(d[mi][ni][1]); shi += __expf(d[mi][ni][3]); }
            }
        }
        slo += __shfl_xor_sync(0xffffffffu, slo, 1);
        slo += __shfl_xor_sync(0xffffffffu, slo, 2);
        shi += __shfl_xor_sync(0xffffffffu, shi, 1);
        shi += __shfl_xor_sync(0xffffffffu, shi, 2);
        if ((lane & 3) == 0) {
            atomicAdd(&S[mt * 128 + wm + mi * 16 + r4], slo);
            atomicAdd(&S[mt * 128 + wm + mi * 16 + 8 + r4], shi);
        }
    }
}

// -------------------- pos / BPR / extra-loss (warp-per-task) -----------------
__global__ void small_loss_kernel(const int* __restrict__ uids,
                                  const int* __restrict__ pos,
                                  const int* __restrict__ neg,
                                  const float* __restrict__ Eu,
                                  const float* __restrict__ Ei,
                                  const float* __restrict__ Gu,
                                  const float* __restrict__ Gi,
                                  const int* __restrict__ unpop,
                                  const int* __restrict__ popi,
                                  float* __restrict__ sc) {
    int gtid = blockIdx.x * blockDim.x + threadIdx.x;
    int wid = gtid >> 5, lane = gtid & 31;
    if (wid < 512) {                       // pos_u
        int b = wid, u = uids[b];
        float s = Gu[b * DD + lane] * Eu[(size_t)u * DD + lane]
                + Gu[b * DD + 32 + lane] * Eu[(size_t)u * DD + 32 + lane];
        s = warp_sum(s);
        if (lane == 0) atomicAdd(&sc[1], fminf(fmaxf(s, -5.0f), 5.0f));
    } else if (wid < 1536) {               // pos_i
        int b = wid - 512;
        int id = (b < 512) ? pos[b] : neg[b - 512];
        float s = Gi[b * DD + lane] * Ei[(size_t)id * DD + lane]
                + Gi[b * DD + 32 + lane] * Ei[(size_t)id * DD + 32 + lane];
        s = warp_sum(s);
        if (lane == 0) atomicAdd(&sc[2], fminf(fmaxf(s, -5.0f), 5.0f));
    } else if (wid < 2048) {               // BPR
        int b = wid - 1536, u = uids[b], p = pos[b], nn = neg[b];
        float eu0 = Eu[(size_t)u * DD + lane], eu1 = Eu[(size_t)u * DD + 32 + lane];
        float sp = eu0 * Ei[(size_t)p * DD + lane]  + eu1 * Ei[(size_t)p * DD + 32 + lane];
        float sn = eu0 * Ei[(size_t)nn * DD + lane] + eu1 * Ei[(size_t)nn * DD + 32 + lane];
        sp = warp_sum(sp);
        sn = warp_sum(sn);
        if (lane == 0) {
            float x = sp - sn;
            float t = (x > 0.f) ? log1pf(expf(-x)) : (-x + log1pf(expf(x)));
            atomicAdd(&sc[3], t);
        }
    } else {                               // extra-loss pairs
        int p = wid - 2048;
        if (p >= 64 * 8 * 32) return;
        int ig = p >> 8, rem = p & 255, ui = rem >> 5, pi = rem & 31;
        int a = unpop[ig * 8 + ui];
        int c = popi[ig * 32 + pi];
        float d0 = Ei[(size_t)a * DD + lane] - Ei[(size_t)c * DD + lane];
        float d1 = Ei[(size_t)a * DD + 32 + lane] - Ei[(size_t)c * DD + 32 + lane];
        float s = warp_sum(d0 * d0 + d1 * d1);
        if (lane == 0) atomicAdd(&sc[4], sqrtf(s));
    }
}

// ------------------------------ weight L2 reg --------------------------------
__global__ void reg_w_kernel(const float* __restrict__ W1,
                             const float* __restrict__ b1,
                             const float* __restrict__ W2,
                             const float* __restrict__ b2,
                             float* __restrict__ acc) {
    int t = blockIdx.x * blockDim.x + threadIdx.x;
    int total = gridDim.x * blockDim.x;
    float s = 0.f;
    for (int i = t; i < 768 * 64; i += total) {
        float a = W1[i]; s = fmaf(a, a, s);
        float c = W2[i]; s = fmaf(c, c, s);
    }
    if (t < 64) {
        float a = b1[t]; s = fmaf(a, a, s);
        float c = b2[t]; s = fmaf(c, c, s);
    }
    s = warp_sum(s);
    if ((threadIdx.x & 31) == 0) atomicAdd(acc, s);
}

// -------------------------------- finalize -----------------------------------
__global__ void finalize_kernel(const float* __restrict__ su,
                                const float* __restrict__ si,
                                const float* __restrict__ sc,
                                float* __restrict__ out) {
    __shared__ float s_lu[16], s_li[16];
    int tid = threadIdx.x;   // 512 threads
    float lu = logf(su[tid] + 1e-8f);
    float li = logf(si[tid] + 1e-8f) + logf(si[tid + 512] + 1e-8f);
    lu = warp_sum(lu);
    li = warp_sum(li);
    if ((tid & 31) == 0) { s_lu[tid >> 5] = lu; s_li[tid >> 5] = li; }
    __syncthreads();
    if (tid == 0) {
        float LU = 0.f, LI = 0.f;
        #pragma unroll
        for (int w = 0; w < 16; w++) { LU += s_lu[w]; LI += s_li[w]; }
        float neg_score = LU / 512.f + LI / 1024.f;
        float pos_score = sc[1] / 512.f + sc[2] / 1024.f;
        float loss_s = -pos_score + neg_score;
        float loss_r = sc[3] / 512.f;
        float loss_reg = 1e-7f * sc[0];
        float extra = sc[4] * (1.f / 32.f);
        float loss = loss_r + 0.2f * loss_s + loss_reg + 0.01f * extra;
        out[0] = loss;
        out[1] = loss_r;
        out[2] = 0.2f * loss_s;
    }
}

// ------------------------------- launcher ------------------------------------
extern "C" void kernel_launch(void* const* d_in, const int* in_sizes, int n_in,
                              void* d_out, int out_size) {
    const int*   uids     = (const int*)d_in[0];
    const int*   pos      = (const int*)d_in[1];
    const int*   neg      = (const int*)d_in[2];
    const int*   adj_rows = (const int*)d_in[3];
    const int*   adj_cols = (const int*)d_in[4];
    const float* adj_vals = (const float*)d_in[5];
    const float* E_u_0    = (const float*)d_in[6];
    const float* E_i_0    = (const float*)d_in[7];
    const float* u_mul_s  = (const float*)d_in[8];
    const float* vt       = (const float*)d_in[9];
    const float* v_mul_s  = (const float*)d_in[10];
    const float* ut       = (const float*)d_in[11];
    const float* W_api    = (const float*)d_in[12];
    const float* b_api    = (const float*)d_in[13];
    const float* W_mashup = (const float*)d_in[14];
    const float* b_mashup = (const float*)d_in[15];
    const float* pos_api  = (const float*)d_in[16];
    const float* neg_api  = (const float*)d_in[17];
    const float* mashup   = (const float*)d_in[18];
    const int*   unpop    = (const int*)d_in[19];
    const int*   popi     = (const int*)d_in[20];

    float* out = (float*)d_out;
    const size_t EMB = (size_t)512 * 768;
    float* out_mashup = out + 3;
    float* out_posapi = out + 3 + EMB;
    float* out_negapi = out + 3 + 2 * EMB;
    float* Eu_out = out + 3 + 3 * EMB;

    float *Efb, *Sm, *G, *evalp;
    __nv_bfloat16 *E0b, *Zbb, *Eb, *Gb;
    int *cnt, *rp, *off, *bsum, *ecol;
    cudaGetSymbolAddress((void**)&E0b,  g_E0b);
    cudaGetSymbolAddress((void**)&Zbb,  g_Zb);
    cudaGetSymbolAddress((void**)&Efb,  g_Ef);
    cudaGetSymbolAddress((void**)&Eb,   g_Eb);
    cudaGetSymbolAddress((void**)&Sm,   g_small);
    cudaGetSymbolAddress((void**)&G,    g_G);
    cudaGetSymbolAddress((void**)&Gb,   g_Gb);
    cudaGetSymbolAddress((void**)&cnt,  g_cnt);
    cudaGetSymbolAddress((void**)&rp,   g_rp);
    cudaGetSymbolAddress((void**)&off,  g_off);
    cudaGetSymbolAddress((void**)&bsum, g_bsum);
    cudaGetSymbolAddress((void**)&ecol, g_ecol);
    cudaGetSymbolAddress((void**)&evalp, g_eval);

    float* Euf = Efb;
    float* Eif = Euf + (size_t)N_U * DD;
    __nv_bfloat16* Eub = Eb;
    __nv_bfloat16* Eib = Eub + (size_t)N_U * DD;
    float* Mu = Sm + OFF_MU;
    float* Mi = Sm + OFF_MI;
    float* su = Sm + OFF_SU;
    float* si = Sm + OFF_SI;
    float* sc = Sm + OFF_SC;
    float* Gu = G;
    float* Gi = G + (size_t)BB * DD;
    __nv_bfloat16* Gub = Gb;
    __nv_bfloat16* Gib = Gub + (size_t)BB * DD;

    cudaFuncSetAttribute(logits_mma,
                         cudaFuncAttributeMaxDynamicSharedMemorySize, SMEM_MMA);

    cudaMemsetAsync(cnt, 0, NR * 4);
    cudaMemsetAsync(Sm, 0, 2304 * 4);

    cudaMemcpyAsync(out_mashup, mashup, EMB * 4, cudaMemcpyDeviceToDevice);
    cudaMemcpyAsync(out_posapi, pos_api, EMB * 4, cudaMemcpyDeviceToDevice);
    cudaMemcpyAsync(out_negapi, neg_api, EMB * 4, cudaMemcpyDeviceToDevice);

    // ---- E0 -> bf16 ----
    const size_t n4 = (size_t)NR * DD / 4;
    conv0_k<<<(int)((n4 + 255) / 256), 256>>>(E_u_0, E_i_0, E0b);

    // ---- CSR build (u rows then i rows, concatenated edge array) ----
    const int e2_blocks = (2 * NNZ_E + 255) / 256;
    hist_k<<<e2_blocks, 256>>>(adj_rows, adj_cols, cnt);
    scan1_k<<<SCAN_NB, SCAN_BS>>>(cnt, bsum);
    scan2_k<<<1, 1024>>>(bsum);
    scan3_k<<<SCAN_NB, SCAN_BS>>>(cnt, bsum, rp, off);
    scatter_k<<<e2_blocks, 256>>>(adj_rows, adj_cols, adj_vals, off, ecol, evalp);

    // ---- layer 1: Zb = bf16(A @ bf16(E0)) ----
    const int csr_blocks = (NR * 32 + 255) / 256;
    spmm_csr_k<<<csr_blocks, 256>>>(rp, ecol, evalp, E0b, Zbb);
    // Ef = E0 + Z1 ; M reductions ; embedding L2 reg
    prep_both<<<3072, 256>>>(E_u_0, E_i_0, Zbb, ut, vt,
                             Euf, Eif, Mi, Mu, sc);
    // ---- layer 2 (bf16 gather, fused E output + bf16 conversion) ----
    spmm_csr_out_k<<<csr_blocks, 256>>>(rp, ecol, evalp, Zbb,
                                        Efb, Eu_out, Eb);

    reg_w_kernel<<<192, 256>>>(W_api, b_api, W_mashup, b_mashup, sc);
    gsel_kernel<<<1536, 64>>>(uids, pos, neg, E_u_0, E_i_0,
                              u_mul_s, v_mul_s, Mu, Mi, G, Gb);

    // ---- tensor-core logits (both sides in one launch) ----
    const int ntu = (N_U + 127) / 128;   // 782
    const int nti = (N_I + 127) / 128;   // 391
    const int ublocks = 4 * ntu;
    logits_mma<<<ublocks + 8 * nti, 256, SMEM_MMA>>>(Gub, Gib, Eub, Eib,
                                                     su, si, ublocks);

    small_loss_kernel<<<2304, 256>>>(uids, pos, neg, Euf, Eif, Gu, Gi,
                                     unpop, popi, sc);

    finalize_kernel<<<1, 512>>>(su, si, sc, out);
}

// round 15
// speedup vs baseline: 2.1360x; 1.0765x over previous
#include <cuda_runtime.h>
#include <cuda_bf16.h>
#include <cstdint>
#include <cstddef>

#define N_U 100000
#define N_I 50000
#define NR  (N_U + N_I)
#define DD  64
#define QQ  5
#define NNZ_E 1000000
#define BB  512
#define SCAN_BS 256
#define SCAN_NB ((NR + SCAN_BS - 1) / SCAN_BS)   // 586
#define EMBF 393216                              // 512*768 floats
#define EMB4 (EMBF / 4)                          // float4 count per api tensor

typedef unsigned long long ull;

// ------------------------- scratch (device globals) -------------------------
__device__ __align__(16) __nv_bfloat16 g_E0b[(size_t)NR * DD];   // bf16 E0 (u|i)
__device__ __align__(16) __nv_bfloat16 g_Zb[(size_t)NR * DD];    // bf16 Z1 (u|i)
__device__ __align__(16) float g_Ef[(size_t)NR * DD];            // final E fp32 (u|i)
__device__ __align__(16) __nv_bfloat16 g_Eb[(size_t)NR * DD];    // bf16 final E
__device__ __align__(16) float g_small[2304];  // Mu(320) Mi(320) su(512) si(1024) sc(8)
__device__ __align__(16) float g_G[3 * BB * DD];
__device__ __align__(16) __nv_bfloat16 g_Gb[3 * BB * DD];
// CSR scratch
__device__ int   g_cnt[NR];
__device__ int   g_rp[NR + 1];
__device__ int   g_off[NR];
__device__ int   g_bsum[1024];
__device__ __align__(16) int   g_ecol[2 * NNZ_E];
__device__ __align__(16) float g_eval[2 * NNZ_E];

#define OFF_MU 0
#define OFF_MI 320
#define OFF_SU 640
#define OFF_SI 1152
#define OFF_SC 2176

// ------------------------------ helpers -------------------------------------
__device__ __forceinline__ float warp_sum(float v) {
    #pragma unroll
    for (int o = 16; o; o >>= 1) v += __shfl_xor_sync(0xffffffffu, v, o);
    return v;
}
__device__ __forceinline__ int warp_sum_i(int v) {
    #pragma unroll
    for (int o = 16; o; o >>= 1) v += __shfl_xor_sync(0xffffffffu, v, o);
    return v;
}
__device__ __forceinline__ uint32_t smem_u32(const void* p) {
    uint32_t a;
    asm("{ .reg .u64 t; cvta.to.shared.u64 t, %1; cvt.u32.u64 %0, t; }" : "=r"(a) : "l"(p));
    return a;
}
__device__ __forceinline__ void ldmx4(unsigned& r0, unsigned& r1,
                                      unsigned& r2, unsigned& r3, uint32_t addr) {
    asm volatile("ldmatrix.sync.aligned.m8n8.x4.shared.b16 {%0,%1,%2,%3}, [%4];"
                 : "=r"(r0), "=r"(r1), "=r"(r2), "=r"(r3) : "r"(addr));
}
__device__ __forceinline__ void mma16816(float* d, const unsigned* a, const unsigned* b) {
    asm volatile("mma.sync.aligned.m16n8k16.row.col.f32.bf16.bf16.f32 "
                 "{%0,%1,%2,%3}, {%4,%5,%6,%7}, {%8,%9}, {%0,%1,%2,%3};"
                 : "+f"(d[0]), "+f"(d[1]), "+f"(d[2]), "+f"(d[3])
                 : "r"(a[0]), "r"(a[1]), "r"(a[2]), "r"(a[3]), "r"(b[0]), "r"(b[1]));
}

// -------- fused: E0->bf16 conversion + degree histogram + api copies ---------
__global__ void conv_hist_copy_k(const float* __restrict__ Eu0,
                                 const float* __restrict__ Ei0,
                                 __nv_bfloat16* __restrict__ E0b,
                                 const int* __restrict__ rows,
                                 const int* __restrict__ cols,
                                 int* __restrict__ cnt,
                                 const float* __restrict__ mashup,
                                 const float* __restrict__ pos_api,
                                 const float* __restrict__ neg_api,
                                 float* __restrict__ o_mash,
                                 float* __restrict__ o_pos,
                                 float* __restrict__ o_neg) {
    size_t i = (size_t)blockIdx.x * blockDim.x + threadIdx.x;
    const size_t nu4 = (size_t)N_U * DD / 4;
    const size_t n4 = (size_t)NR * DD / 4;
    if (i < n4) {
        float4 v = (i < nu4) ? ((const float4*)Eu0)[i]
                             : ((const float4*)Ei0)[i - nu4];
        *(__nv_bfloat162*)(E0b + i * 4)     = __floats2bfloat162_rn(v.x, v.y);
        *(__nv_bfloat162*)(E0b + i * 4 + 2) = __floats2bfloat162_rn(v.z, v.w);
    }
    if (i < NNZ_E) atomicAdd(&cnt[__ldg(rows + i)], 1);
    else if (i < 2 * NNZ_E) atomicAdd(&cnt[N_U + __ldg(cols + (i - NNZ_E))], 1);
    if (i < 3 * EMB4) {
        const float* src; float* dst; size_t j;
        if (i < EMB4)            { src = mashup;  dst = o_mash; j = i; }
        else if (i < 2 * EMB4)   { src = pos_api; dst = o_pos;  j = i - EMB4; }
        else                     { src = neg_api; dst = o_neg;  j = i - 2 * EMB4; }
        float4 v = ((const float4*)src)[j];
        float* o = dst + j * 4;          // dst is 4B-aligned only -> scalar stores
        o[0] = v.x; o[1] = v.y; o[2] = v.z; o[3] = v.w;
    }
}

// ------------------------------ CSR build ------------------------------------
__global__ void scan1_k(const int* __restrict__ cnt, int* __restrict__ bsum,
                        float* __restrict__ Sm) {
    __shared__ int sh[8];
    int i = blockIdx.x * SCAN_BS + threadIdx.x;
    int v = (i < NR) ? cnt[i] : 0;
    v = warp_sum_i(v);
    if ((threadIdx.x & 31) == 0) sh[threadIdx.x >> 5] = v;
    __syncthreads();
    if (threadIdx.x == 0) {
        int t = 0;
        #pragma unroll
        for (int w = 0; w < 8; w++) t += sh[w];
        bsum[blockIdx.x] = t;
    }
    if (blockIdx.x == 0)
        for (int j = threadIdx.x; j < 2304; j += SCAN_BS) Sm[j] = 0.f;
}

// scan3: each block computes its own prefix over bsum then local scan
__global__ void scan3_k(const int* __restrict__ cnt, const int* __restrict__ bsum,
                        int* __restrict__ rp, int* __restrict__ off) {
    __shared__ int sh[SCAN_BS];
    __shared__ int shp[8];
    int tid = threadIdx.x;
    // prefix = sum(bsum[0..blockIdx.x))
    int partial = 0;
    for (int j = tid; j < (int)blockIdx.x; j += SCAN_BS) partial += bsum[j];
    partial = warp_sum_i(partial);
    if ((tid & 31) == 0) shp[tid >> 5] = partial;
    __syncthreads();
    int pre = 0;
    #pragma unroll
    for (int w = 0; w < 8; w++) pre += shp[w];

    int i = blockIdx.x * SCAN_BS + tid;
    int v = (i < NR) ? cnt[i] : 0;
    sh[tid] = v;
    __syncthreads();
    for (int o = 1; o < SCAN_BS; o <<= 1) {
        int t = (tid >= o) ? sh[tid - o] : 0;
        __syncthreads();
        sh[tid] += t;
        __syncthreads();
    }
    int excl = sh[tid] - v + pre;
    if (i < NR) { rp[i] = excl; off[i] = excl; }
    if (i == NR - 1) rp[NR] = excl + v;
}

__global__ void scatter_k(const int* __restrict__ rows, const int* __restrict__ cols,
                          const float* __restrict__ vals,
                          int* __restrict__ off, int* __restrict__ ecol,
                          float* __restrict__ eval) {
    int t = blockIdx.x * blockDim.x + threadIdx.x;
    int r, c; float v;
    if (t < NNZ_E) {
        r = __ldg(rows + t); c = __ldg(cols + t); v = __ldg(vals + t);
    } else if (t < 2 * NNZ_E) {
        int e = t - NNZ_E;
        r = N_U + __ldg(cols + e); c = __ldg(rows + e); v = __ldg(vals + e);
    } else return;
    int slot = atomicAdd(&off[r], 1);
    ecol[slot] = c; eval[slot] = v;
}

// ---------------- CSR SpMM layer1: warp per row, bf16 gather ------------------
__global__ void spmm_csr_k(const int* __restrict__ rp,
                           const int* __restrict__ ecol,
                           const float* __restrict__ eval,
                           const __nv_bfloat16* __restrict__ E0b,
                           __nv_bfloat16* __restrict__ Zb) {
    int w = (blockIdx.x * blockDim.x + threadIdx.x) >> 5;
    int lane = threadIdx.x & 31;
    if (w >= NR) return;
    const __nv_bfloat16* X = (w < N_U) ? (E0b + (size_t)N_U * DD) : E0b;
    int e = __ldg(rp + w), e1 = __ldg(rp + w + 1);
    float2 acc = make_float2(0.f, 0.f);
    for (; e + 3 < e1; e += 4) {
        int c0 = __ldg(ecol + e),     c1 = __ldg(ecol + e + 1);
        int c2 = __ldg(ecol + e + 2), c3 = __ldg(ecol + e + 3);
        float v0 = __ldg(eval + e),     v1 = __ldg(eval + e + 1);
        float v2 = __ldg(eval + e + 2), v3 = __ldg(eval + e + 3);
        float2 x0 = __bfloat1622float2(*(const __nv_bfloat162*)(X + (size_t)c0 * DD + lane * 2));
        float2 x1 = __bfloat1622float2(*(const __nv_bfloat162*)(X + (size_t)c1 * DD + lane * 2));
        float2 x2 = __bfloat1622float2(*(const __nv_bfloat162*)(X + (size_t)c2 * DD + lane * 2));
        float2 x3 = __bfloat1622float2(*(const __nv_bfloat162*)(X + (size_t)c3 * DD + lane * 2));
        acc.x = fmaf(v0, x0.x, acc.x); acc.y = fmaf(v0, x0.y, acc.y);
        acc.x = fmaf(v1, x1.x, acc.x); acc.y = fmaf(v1, x1.y, acc.y);
        acc.x = fmaf(v2, x2.x, acc.x); acc.y = fmaf(v2, x2.y, acc.y);
        acc.x = fmaf(v3, x3.x, acc.x); acc.y = fmaf(v3, x3.y, acc.y);
    }
    for (; e < e1; e++) {
        int c0 = __ldg(ecol + e); float v0 = __ldg(eval + e);
        float2 x0 = __bfloat1622float2(*(const __nv_bfloat162*)(X + (size_t)c0 * DD + lane * 2));
        acc.x = fmaf(v0, x0.x, acc.x); acc.y = fmaf(v0, x0.y, acc.y);
    }
    *(__nv_bfloat162*)(Zb + (size_t)w * DD + lane * 2) = __floats2bfloat162_rn(acc.x, acc.y);
}

// ---- CSR SpMM layer2 fused: Ef = E0 + Z1 + A@Z1 ; write Eout + bf16 Eb ------
__global__ void spmm_csr_out_k(const int* __restrict__ rp,
                               const int* __restrict__ ecol,
                               const float* __restrict__ eval,
                               const __nv_bfloat16* __restrict__ Zb,
                               const float* __restrict__ Eu0,
                               const float* __restrict__ Ei0,
                               float* __restrict__ Ef,
                               float* __restrict__ Eout,    // misaligned d_out
                               __nv_bfloat16* __restrict__ Eb) {
    int w = (blockIdx.x * blockDim.x + threadIdx.x) >> 5;
    int lane = threadIdx.x & 31;
    if (w >= NR) return;
    const __nv_bfloat16* X = (w < N_U) ? (Zb + (size_t)N_U * DD) : Zb;
    const float* E0row = (w < N_U) ? (Eu0 + (size_t)w * DD)
                                   : (Ei0 + (size_t)(w - N_U) * DD);
    int e = __ldg(rp + w), e1 = __ldg(rp + w + 1);
    float2 acc = make_float2(0.f, 0.f);
    for (; e + 3 < e1; e += 4) {
        int c0 = __ldg(ecol + e),     c1 = __ldg(ecol + e + 1);
        int c2 = __ldg(ecol + e + 2), c3 = __ldg(ecol + e + 3);
        float v0 = __ldg(eval + e),     v1 = __ldg(eval + e + 1);
        float v2 = __ldg(eval + e + 2), v3 = __ldg(eval + e + 3);
        float2 x0 = __bfloat1622float2(*(const __nv_bfloat162*)(X + (size_t)c0 * DD + lane * 2));
        float2 x1 = __bfloat1622float2(*(const __nv_bfloat162*)(X + (size_t)c1 * DD + lane * 2));
        float2 x2 = __bfloat1622float2(*(const __nv_bfloat162*)(X + (size_t)c2 * DD + lane * 2));
        float2 x3 = __bfloat1622float2(*(const __nv_bfloat162*)(X + (size_t)c3 * DD + lane * 2));
        acc.x = fmaf(v0, x0.x, acc.x); acc.y = fmaf(v0, x0.y, acc.y);
        acc.x = fmaf(v1, x1.x, acc.x); acc.y = fmaf(v1, x1.y, acc.y);
        acc.x = fmaf(v2, x2.x, acc.x); acc.y = fmaf(v2, x2.y, acc.y);
        acc.x = fmaf(v3, x3.x, acc.x); acc.y = fmaf(v3, x3.y, acc.y);
    }
    for (; e < e1; e++) {
        int c0 = __ldg(ecol + e); float v0 = __ldg(eval + e);
        float2 x0 = __bfloat1622float2(*(const __nv_bfloat162*)(X + (size_t)c0 * DD + lane * 2));
        acc.x = fmaf(v0, x0.x, acc.x); acc.y = fmaf(v0, x0.y, acc.y);
    }
    size_t base = (size_t)w * DD + lane * 2;
    float2 e0 = *(const float2*)(E0row + lane * 2);
    float2 z1 = __bfloat1622float2(*(const __nv_bfloat162*)(Zb + base));
    acc.x += e0.x + z1.x; acc.y += e0.y + z1.y;
    *(float2*)(Ef + base) = acc;
    Eout[base] = acc.x;
    Eout[base + 1] = acc.y;
    *(__nv_bfloat162*)(Eb + base) = __floats2bfloat162_rn(acc.x, acc.y);
}

// ------------- prep (slim): M = P @ (E0+Z1) ; reg = sum(E0^2) -----------------
__global__ void prep_slim(const float* __restrict__ Eu0,
                          const float* __restrict__ Ei0,
                          const __nv_bfloat16* __restrict__ Zb,
                          const float* __restrict__ Put,
                          const float* __restrict__ Pvt,
                          float* __restrict__ Mi,
                          float* __restrict__ Mu,
                          float* __restrict__ regAcc) {
    const bool isU = blockIdx.x < 2048;
    const int vbid = isU ? blockIdx.x : blockIdx.x - 2048;
    const int vgrid = isU ? 2048 : 1024;
    const int n_rows = isU ? N_U : N_I;
    const float* E0 = isU ? Eu0 : Ei0;
    const __nv_bfloat16* Z1 = isU ? Zb : (Zb + (size_t)N_U * DD);
    const float* P  = isU ? Put : Pvt;
    float* Macc = isU ? Mi : Mu;

    int d = threadIdx.x & 63;
    int grp = threadIdx.x >> 6;                 // 0..3
    float m0 = 0, m1 = 0, m2 = 0, m3 = 0, m4 = 0, racc = 0;
    for (int r = vbid * 4 + grp; r < n_rows; r += vgrid * 4) {
        size_t off = (size_t)r * DD + d;
        float e0 = E0[off];
        float t  = e0 + __bfloat162float(Z1[off]);
        racc = fmaf(e0, e0, racc);
        m0 = fmaf(__ldg(P + r), t, m0);
        m1 = fmaf(__ldg(P + (size_t)n_rows + r), t, m1);
        m2 = fmaf(__ldg(P + 2 * (size_t)n_rows + r), t, m2);
        m3 = fmaf(__ldg(P + 3 * (size_t)n_rows + r), t, m3);
        m4 = fmaf(__ldg(P + 4 * (size_t)n_rows + r), t, m4);
    }
    __shared__ float sm[4][QQ][DD];
    sm[grp][0][d] = m0; sm[grp][1][d] = m1; sm[grp][2][d] = m2;
    sm[grp][3][d] = m3; sm[grp][4][d] = m4;
    __syncthreads();
    if (grp == 0) {
        #pragma unroll
        for (int q = 0; q < QQ; q++)
            atomicAdd(&Macc[q * DD + d],
                      sm[0][q][d] + sm[1][q][d] + sm[2][q][d] + sm[3][q][d]);
    }
    racc = warp_sum(racc);
    if ((threadIdx.x & 31) == 0) atomicAdd(regAcc, racc);
}

// ---------------- G selection (+ merged weight L2 reg, blocks >= 1536) --------
__global__ void gsel_kernel(const int* __restrict__ uids,
                            const int* __restrict__ pos,
                            const int* __restrict__ neg,
                            const float* __restrict__ Eu0,
                            const float* __restrict__ Ei0,
                            const float* __restrict__ mu_s,
                            const float* __restrict__ mi_s,
                            const float* __restrict__ Mu,
                            const float* __restrict__ Mi,
                            float* __restrict__ G,
                            __nv_bfloat16* __restrict__ Gb,
                            const float* __restrict__ W1,
                            const float* __restrict__ b1,
                            const float* __restrict__ W2,
                            const float* __restrict__ b2,
                            float* __restrict__ wacc) {
    int b = blockIdx.x, d = threadIdx.x;
    if (b >= 1536) {                       // weight L2 reg
        int t = (b - 1536) * 64 + d;       // 0..12287
        float s = 0.f;
        for (int i = t; i < 768 * 64; i += 192 * 64) {
            float a = W1[i]; s = fmaf(a, a, s);
            float c = W2[i]; s = fmaf(c, c, s);
        }
        if (t < 64) {
            float a = b1[t]; s = fmaf(a, a, s);
            float c = b2[t]; s = fmaf(c, c, s);
        }
        s = warp_sum(s);
        if ((d & 31) == 0) atomicAdd(wacc, s);
        return;
    }
    const float* E0; const float* ms; const float* M; int id;
    if (b < 512)       { E0 = Eu0; ms = mu_s; M = Mu; id = uids[b]; }
    else if (b < 1024) { E0 = Ei0; ms = mi_s; M = Mi; id = pos[b - 512]; }
    else               { E0 = Ei0; ms = mi_s; M = Mi; id = neg[b - 1024]; }
    float v = E0[(size_t)id * DD + d];
    #pragma unroll
    for (int q = 0; q < QQ; q++)
        v = fmaf(ms[(size_t)id * QQ + q], M[q * DD + d], v);
    float v5 = 5.0f * v;
    G[b * DD + d] = v5;
    Gb[b * DD + d] = __float2bfloat16(v5);
}

// ----- tensor-core logits (+ merged small-loss blocks at the grid tail) -------
#define SMEM_MMA (2 * 128 * 144)
__global__ __launch_bounds__(256, 2)
void logits_mma(const __nv_bfloat16* __restrict__ Gbu,
                const __nv_bfloat16* __restrict__ Gbi,
                const __nv_bfloat16* __restrict__ Ebu,
                const __nv_bfloat16* __restrict__ Ebi,
                float* __restrict__ Su, float* __restrict__ Si,
                int ublocks, int gemm_blocks,
                const int* __restrict__ uids,
                const int* __restrict__ pos,
                const int* __restrict__ neg,
                const float* __restrict__ Eu,
                const float* __restrict__ Ei,
                const float* __restrict__ Gu,
                const float* __restrict__ Gi,
                const int* __restrict__ unpop,
                const int* __restrict__ popi,
                float* __restrict__ sc) {
    extern __shared__ char smc[];
    const int tid = threadIdx.x;

    if ((int)blockIdx.x >= gemm_blocks) {
        // ---------------- small-loss blocks ----------------
        int gtid = ((int)blockIdx.x - gemm_blocks) * 256 + tid;
        int wid = gtid >> 5, lane = gtid & 31;
        if (wid < 512) {                       // pos_u
            int b = wid, u = uids[b];
            float s = Gu[b * DD + lane] * Eu[(size_t)u * DD + lane]
                    + Gu[b * DD + 32 + lane] * Eu[(size_t)u * DD + 32 + lane];
            s = warp_sum(s);
            if (lane == 0) atomicAdd(&sc[1], fminf(fmaxf(s, -5.0f), 5.0f));
        } else if (wid < 1536) {               // pos_i
            int b = wid - 512;
            int id = (b < 512) ? pos[b] : neg[b - 512];
            float s = Gi[b * DD + lane] * Ei[(size_t)id * DD + lane]
                    + Gi[b * DD + 32 + lane] * Ei[(size_t)id * DD + 32 + lane];
            s = warp_sum(s);
            if (lane == 0) atomicAdd(&sc[2], fminf(fmaxf(s, -5.0f), 5.0f));
        } else if (wid < 2048) {               // BPR
            int b = wid - 1536, u = uids[b], p = pos[b], nn = neg[b];
            float eu0 = Eu[(size_t)u * DD + lane], eu1 = Eu[(size_t)u * DD + 32 + lane];
            float sp = eu0 * Ei[(size_t)p * DD + lane]  + eu1 * Ei[(size_t)p * DD + 32 + lane];
            float sn = eu0 * Ei[(size_t)nn * DD + lane] + eu1 * Ei[(size_t)nn * DD + 32 + lane];
            sp = warp_sum(sp);
            sn = warp_sum(sn);
            if (lane == 0) {
                float x = sp - sn;
                float t = (x > 0.f) ? log1pf(expf(-x)) : (-x + log1pf(expf(x)));
                atomicAdd(&sc[3], t);
            }
        } else {                               // extra-loss pairs
            int p = wid - 2048;
            if (p >= 64 * 8 * 32) return;
            int ig = p >> 8, rem = p & 255, ui = rem >> 5, pi = rem & 31;
            int a = unpop[ig * 8 + ui];
            int c = popi[ig * 32 + pi];
            float d0 = Ei[(size_t)a * DD + lane] - Ei[(size_t)c * DD + lane];
            float d1 = Ei[(size_t)a * DD + 32 + lane] - Ei[(size_t)c * DD + 32 + lane];
            float s = warp_sum(d0 * d0 + d1 * d1);
            if (lane == 0) atomicAdd(&sc[4], sqrtf(s));
        }
        return;
    }

    // ---------------- GEMM blocks ----------------
    const uint32_t sA = smem_u32(smc);
    const uint32_t sB = sA + 128 * 144;
    const bool isU = ((int)blockIdx.x < ublocks);
    const int bid = isU ? blockIdx.x : blockIdx.x - ublocks;
    const int Mtiles = isU ? 4 : 8;
    const int N = isU ? N_U : N_I;
    const __nv_bfloat16* Gb = isU ? Gbu : Gbi;
    const __nv_bfloat16* Eb = isU ? Ebu : Ebi;
    float* S = isU ? Su : Si;
    const int mt = bid % Mtiles;
    const long n0 = (long)(bid / Mtiles) * 128;

    #pragma unroll
    for (int it = 0; it < 4; it++) {
        int idx = it * 256 + tid;          // 0..1023
        int row = idx >> 3, c = idx & 7;
        uint4 v = *(const uint4*)(Gb + ((size_t)(mt * 128 + row)) * DD + c * 8);
        *(uint4*)(smc + row * 144 + c * 16) = v;
    }
    #pragma unroll
    for (int it = 0; it < 4; it++) {
        int idx = it * 256 + tid;
        int row = idx >> 3, c = idx & 7;
        long n = n0 + row;
        uint4 v = make_uint4(0, 0, 0, 0);
        if (n < N) v = *(const uint4*)(Eb + n * DD + c * 8);
        *(uint4*)(smc + 128 * 144 + row * 144 + c * 16) = v;
    }
    __syncthreads();

    const int wid = tid >> 5, lane = tid & 31;
    const int wm = (wid & 3) * 32;
    const int wn = (wid >> 2) * 64;

    float d[2][8][4];
    #pragma unroll
    for (int mi = 0; mi < 2; mi++)
        #pragma unroll
        for (int ni = 0; ni < 8; ni++)
            #pragma unroll
            for (int j = 0; j < 4; j++) d[mi][ni][j] = 0.f;

    const int lrowA = (lane & 7) + ((lane & 8) ? 8 : 0);
    const int lcolA = (lane & 16) ? 8 : 0;
    const int lrowB = (lane & 7) + ((lane & 16) ? 8 : 0);
    const int lcolB = (lane & 8) ? 8 : 0;

    #pragma unroll
    for (int ks = 0; ks < 4; ks++) {
        const int k0 = ks * 16;
        unsigned a[2][4];
        #pragma unroll
        for (int mi = 0; mi < 2; mi++) {
            uint32_t addr = sA + (wm + mi * 16 + lrowA) * 144 + (k0 + lcolA) * 2;
            ldmx4(a[mi][0], a[mi][1], a[mi][2], a[mi][3], addr);
        }
        #pragma unroll
        for (int np = 0; np < 4; np++) {
            unsigned b[4];
            uint32_t addr = sB + (wn + np * 16 + lrowB) * 144 + (k0 + lcolB) * 2;
            ldmx4(b[0], b[1], b[2], b[3], addr);
            #pragma unroll
            for (int mi = 0; mi < 2; mi++) {
                mma16816(d[mi][np * 2 + 0], a[mi], b + 0);
                mma16816(d[mi][np * 2 + 1], a[mi], b + 2);
            }
        }
    }

    const bool full = (n0 + 128 <= N);
    const int r4 = lane >> 2;
    #pragma unroll
    for (int mi = 0; mi < 2; mi++) {
        float slo = 0.f, shi = 0.f;
        #pragma unroll
        for (int ni = 0; ni < 8; ni++) {
            if (full) {
                slo += __expf(d[mi][ni][0]) + __expf(d[mi][ni][1]);
                shi += __expf(d[mi][ni][2]) + __expf(d[mi][ni][3]);
            } else {
                long c = n0 + wn + ni * 8 + (lane & 3) * 2;
                if (c < N)     { slo += __expf(d[mi][ni][0]); shi += __expf(d[mi][ni][2]); }
                if (c + 1 < N) { slo += __expf(d[mi][ni][1]); shi += __expf(d[mi][ni][3]); }
            }
        }
        slo += __shfl_xor_sync(0xffffffffu, slo, 1);
        slo += __shfl_xor_sync(0xffffffffu, slo, 2);
        shi += __shfl_xor_sync(0xffffffffu, shi, 1);
        shi += __shfl_xor_sync(0xffffffffu, shi, 2);
        if ((lane & 3) == 0) {
            atomicAdd(&S[mt * 128 + wm + mi * 16 + r4], slo);
            atomicAdd(&S[mt * 128 + wm + mi * 16 + 8 + r4], shi);
        }
    }
}

// -------------------------------- finalize -----------------------------------
__global__ void finalize_kernel(const float* __restrict__ su,
                                const float* __restrict__ si,
                                const float* __restrict__ sc,
                                float* __restrict__ out) {
    __shared__ float s_lu[16], s_li[16];
    int tid = threadIdx.x;   // 512 threads
    float lu = logf(su[tid] + 1e-8f);
    float li = logf(si[tid] + 1e-8f) + logf(si[tid + 512] + 1e-8f);
    lu = warp_sum(lu);
    li = warp_sum(li);
    if ((tid & 31) == 0) { s_lu[tid >> 5] = lu; s_li[tid >> 5] = li; }
    __syncthreads();
    if (tid == 0) {
        float LU = 0.f, LI = 0.f;
        #pragma unroll
        for (int w = 0; w < 16; w++) { LU += s_lu[w]; LI += s_li[w]; }
        float neg_score = LU / 512.f + LI / 1024.f;
        float pos_score = sc[1] / 512.f + sc[2] / 1024.f;
        float loss_s = -pos_score + neg_score;
        float loss_r = sc[3] / 512.f;
        float loss_reg = 1e-7f * sc[0];
        float extra = sc[4] * (1.f / 32.f);
        float loss = loss_r + 0.2f * loss_s + loss_reg + 0.01f * extra;
        out[0] = loss;
        out[1] = loss_r;
        out[2] = 0.2f * loss_s;
    }
}

// ------------------------------- launcher ------------------------------------
extern "C" void kernel_launch(void* const* d_in, const int* in_sizes, int n_in,
                              void* d_out, int out_size) {
    const int*   uids     = (const int*)d_in[0];
    const int*   pos      = (const int*)d_in[1];
    const int*   neg      = (const int*)d_in[2];
    const int*   adj_rows = (const int*)d_in[3];
    const int*   adj_cols = (const int*)d_in[4];
    const float* adj_vals = (const float*)d_in[5];
    const float* E_u_0    = (const float*)d_in[6];
    const float* E_i_0    = (const float*)d_in[7];
    const float* u_mul_s  = (const float*)d_in[8];
    const float* vt       = (const float*)d_in[9];
    const float* v_mul_s  = (const float*)d_in[10];
    const float* ut       = (const float*)d_in[11];
    const float* W_api    = (const float*)d_in[12];
    const float* b_api    = (const float*)d_in[13];
    const float* W_mashup = (const float*)d_in[14];
    const float* b_mashup = (const float*)d_in[15];
    const float* pos_api  = (const float*)d_in[16];
    const float* neg_api  = (const float*)d_in[17];
    const float* mashup   = (const float*)d_in[18];
    const int*   unpop    = (const int*)d_in[19];
    const int*   popi     = (const int*)d_in[20];

    float* out = (float*)d_out;
    const size_t EMB = (size_t)EMBF;
    float* out_mashup = out + 3;
    float* out_posapi = out + 3 + EMB;
    float* out_negapi = out + 3 + 2 * EMB;
    float* Eu_out = out + 3 + 3 * EMB;

    float *Efb, *Sm, *G, *evalp;
    __nv_bfloat16 *E0b, *Zbb, *Eb, *Gb;
    int *cnt, *rp, *off, *bsum, *ecol;
    cudaGetSymbolAddress((void**)&E0b,  g_E0b);
    cudaGetSymbolAddress((void**)&Zbb,  g_Zb);
    cudaGetSymbolAddress((void**)&Efb,  g_Ef);
    cudaGetSymbolAddress((void**)&Eb,   g_Eb);
    cudaGetSymbolAddress((void**)&Sm,   g_small);
    cudaGetSymbolAddress((void**)&G,    g_G);
    cudaGetSymbolAddress((void**)&Gb,   g_Gb);
    cudaGetSymbolAddress((void**)&cnt,  g_cnt);
    cudaGetSymbolAddress((void**)&rp,   g_rp);
    cudaGetSymbolAddress((void**)&off,  g_off);
    cudaGetSymbolAddress((void**)&bsum, g_bsum);
    cudaGetSymbolAddress((void**)&ecol, g_ecol);
    cudaGetSymbolAddress((void**)&evalp, g_eval);

    float* Euf = Efb;
    float* Eif = Euf + (size_t)N_U * DD;
    __nv_bfloat16* Eub = Eb;
    __nv_bfloat16* Eib = Eub + (size_t)N_U * DD;
    float* Mu = Sm + OFF_MU;
    float* Mi = Sm + OFF_MI;
    float* su = Sm + OFF_SU;
    float* si = Sm + OFF_SI;
    float* sc = Sm + OFF_SC;
    float* Gu = G;
    float* Gi = G + (size_t)BB * DD;
    __nv_bfloat16* Gub = Gb;
    __nv_bfloat16* Gib = Gub + (size_t)BB * DD;

    cudaFuncSetAttribute(logits_mma,
                         cudaFuncAttributeMaxDynamicSharedMemorySize, SMEM_MMA);

    cudaMemsetAsync(cnt, 0, NR * 4);

    // fused conv + hist + api copies (covers max(2.4M, 2M, 0.9M) threads)
    const size_t n4 = (size_t)NR * DD / 4;
    conv_hist_copy_k<<<(int)((n4 + 255) / 256), 256>>>(
        E_u_0, E_i_0, E0b, adj_rows, adj_cols, cnt,
        mashup, pos_api, neg_api, out_mashup, out_posapi, out_negapi);

    scan1_k<<<SCAN_NB, SCAN_BS>>>(cnt, bsum, Sm);
    scan3_k<<<SCAN_NB, SCAN_BS>>>(cnt, bsum, rp, off);
    const int e2_blocks = (2 * NNZ_E + 255) / 256;
    scatter_k<<<e2_blocks, 256>>>(adj_rows, adj_cols, adj_vals, off, ecol, evalp);

    // layer 1: Zb = bf16(A @ bf16(E0))
    const int csr_blocks = (NR * 32 + 255) / 256;
    spmm_csr_k<<<csr_blocks, 256>>>(rp, ecol, evalp, E0b, Zbb);
    // M reductions + embedding L2 reg (no Ef write)
    prep_slim<<<3072, 256>>>(E_u_0, E_i_0, Zbb, ut, vt, Mi, Mu, sc);
    // layer 2: Ef = E0 + Z1 + A@Z1 ; write d_out copy + bf16 E
    spmm_csr_out_k<<<csr_blocks, 256>>>(rp, ecol, evalp, Zbb, E_u_0, E_i_0,
                                        Efb, Eu_out, Eb);

    // gsel (+ merged weight reg)
    gsel_kernel<<<1536 + 192, 64>>>(uids, pos, neg, E_u_0, E_i_0,
                                    u_mul_s, v_mul_s, Mu, Mi, G, Gb,
                                    W_api, b_api, W_mashup, b_mashup, sc);

    // logits (+ merged small-loss tail blocks)
    const int ntu = (N_U + 127) / 128;   // 782
    const int nti = (N_I + 127) / 128;   // 391
    const int ublocks = 4 * ntu;
    const int gemm_blocks = ublocks + 8 * nti;
    logits_mma<<<gemm_blocks + 2304, 256, SMEM_MMA>>>(
        Gub, Gib, Eub, Eib, su, si, ublocks, gemm_blocks,
        uids, pos, neg, Euf, Eif, Gu, Gi, unpop, popi, sc);

    finalize_kernel<<<1, 512>>>(su, si, sc, out);
}

// round 16
// speedup vs baseline: 2.1907x; 1.0256x over previous
#include <cuda_runtime.h>
#include <cuda_bf16.h>
#include <cstdint>
#include <cstddef>

#define N_U 100000
#define N_I 50000
#define NR  (N_U + N_I)
#define DD  64
#define QQ  5
#define NNZ_E 1000000
#define BB  512
#define SCAN_BS 256
#define SCAN_NB ((NR + SCAN_BS - 1) / SCAN_BS)   // 586
#define EMBF 393216                              // 512*768 floats
#define EMB4 (EMBF / 4)

typedef unsigned long long ull;

// ------------------------- scratch (device globals) -------------------------
__device__ __align__(16) __nv_bfloat16 g_E0b[(size_t)NR * DD];   // bf16 E0 (u|i)
__device__ __align__(16) __nv_bfloat16 g_Zb[(size_t)NR * DD];    // bf16 Z1 (u|i)
__device__ __align__(16) float g_Ef[(size_t)NR * DD];            // final E fp32 (u|i)
__device__ __align__(16) __nv_bfloat16 g_Eb[(size_t)NR * DD];    // bf16 final E
__device__ __align__(16) float g_small[2304];  // Mu(320) Mi(320) su(512) si(1024) sc(8)
__device__ __align__(16) float g_G[3 * BB * DD];
__device__ __align__(16) __nv_bfloat16 g_Gb[3 * BB * DD];
// CSR scratch
__device__ int   g_cnt[NR];
__device__ int   g_rp[NR + 1];
__device__ int   g_off[NR];
__device__ int   g_bsum[1024];
__device__ __align__(16) ull g_epack[2 * NNZ_E];   // hi32 = val bits, lo32 = col

#define OFF_MU 0
#define OFF_MI 320
#define OFF_SU 640
#define OFF_SI 1152
#define OFF_SC 2176

// ------------------------------ helpers -------------------------------------
__device__ __forceinline__ float warp_sum(float v) {
    #pragma unroll
    for (int o = 16; o; o >>= 1) v += __shfl_xor_sync(0xffffffffu, v, o);
    return v;
}
__device__ __forceinline__ int warp_sum_i(int v) {
    #pragma unroll
    for (int o = 16; o; o >>= 1) v += __shfl_xor_sync(0xffffffffu, v, o);
    return v;
}
__device__ __forceinline__ uint32_t smem_u32(const void* p) {
    uint32_t a;
    asm("{ .reg .u64 t; cvta.to.shared.u64 t, %1; cvt.u32.u64 %0, t; }" : "=r"(a) : "l"(p));
    return a;
}
__device__ __forceinline__ void ldmx4(unsigned& r0, unsigned& r1,
                                      unsigned& r2, unsigned& r3, uint32_t addr) {
    asm volatile("ldmatrix.sync.aligned.m8n8.x4.shared.b16 {%0,%1,%2,%3}, [%4];"
                 : "=r"(r0), "=r"(r1), "=r"(r2), "=r"(r3) : "r"(addr));
}
__device__ __forceinline__ void mma16816(float* d, const unsigned* a, const unsigned* b) {
    asm volatile("mma.sync.aligned.m16n8k16.row.col.f32.bf16.bf16.f32 "
                 "{%0,%1,%2,%3}, {%4,%5,%6,%7}, {%8,%9}, {%0,%1,%2,%3};"
                 : "+f"(d[0]), "+f"(d[1]), "+f"(d[2]), "+f"(d[3])
                 : "r"(a[0]), "r"(a[1]), "r"(a[2]), "r"(a[3]), "r"(b[0]), "r"(b[1]));
}
__device__ __forceinline__ void unpack_edge(ull p, int& c, float& v) {
    c = (int)(unsigned)p;
    v = __uint_as_float((unsigned)(p >> 32));
}

// -------- fused: E0->bf16 conversion + degree histogram + api copies ---------
__global__ void conv_hist_copy_k(const float* __restrict__ Eu0,
                                 const float* __restrict__ Ei0,
                                 __nv_bfloat16* __restrict__ E0b,
                                 const int* __restrict__ rows,
                                 const int* __restrict__ cols,
                                 int* __restrict__ cnt,
                                 const float* __restrict__ mashup,
                                 const float* __restrict__ pos_api,
                                 const float* __restrict__ neg_api,
                                 float* __restrict__ o_mash,
                                 float* __restrict__ o_pos,
                                 float* __restrict__ o_neg) {
    size_t i = (size_t)blockIdx.x * blockDim.x + threadIdx.x;
    const size_t nu4 = (size_t)N_U * DD / 4;
    const size_t n4 = (size_t)NR * DD / 4;
    if (i < n4) {
        float4 v = (i < nu4) ? ((const float4*)Eu0)[i]
                             : ((const float4*)Ei0)[i - nu4];
        *(__nv_bfloat162*)(E0b + i * 4)     = __floats2bfloat162_rn(v.x, v.y);
        *(__nv_bfloat162*)(E0b + i * 4 + 2) = __floats2bfloat162_rn(v.z, v.w);
    }
    if (i < NNZ_E) atomicAdd(&cnt[__ldg(rows + i)], 1);
    else if (i < 2 * NNZ_E) atomicAdd(&cnt[N_U + __ldg(cols + (i - NNZ_E))], 1);
    if (i < 3 * EMB4) {
        const float* src; float* dst; size_t j;
        if (i < EMB4)            { src = mashup;  dst = o_mash; j = i; }
        else if (i < 2 * EMB4)   { src = pos_api; dst = o_pos;  j = i - EMB4; }
        else                     { src = neg_api; dst = o_neg;  j = i - 2 * EMB4; }
        float4 v = ((const float4*)src)[j];
        float* o = dst + j * 4;
        o[0] = v.x; o[1] = v.y; o[2] = v.z; o[3] = v.w;
    }
}

// ------------------------------ CSR build ------------------------------------
__global__ void scan1_k(const int* __restrict__ cnt, int* __restrict__ bsum,
                        float* __restrict__ Sm) {
    __shared__ int sh[8];
    int i = blockIdx.x * SCAN_BS + threadIdx.x;
    int v = (i < NR) ? cnt[i] : 0;
    v = warp_sum_i(v);
    if ((threadIdx.x & 31) == 0) sh[threadIdx.x >> 5] = v;
    __syncthreads();
    if (threadIdx.x == 0) {
        int t = 0;
        #pragma unroll
        for (int w = 0; w < 8; w++) t += sh[w];
        bsum[blockIdx.x] = t;
    }
    if (blockIdx.x == 0)
        for (int j = threadIdx.x; j < 2304; j += SCAN_BS) Sm[j] = 0.f;
}

__global__ void scan3_k(const int* __restrict__ cnt, const int* __restrict__ bsum,
                        int* __restrict__ rp, int* __restrict__ off) {
    __shared__ int sh[SCAN_BS];
    __shared__ int shp[8];
    int tid = threadIdx.x;
    int partial = 0;
    for (int j = tid; j < (int)blockIdx.x; j += SCAN_BS) partial += bsum[j];
    partial = warp_sum_i(partial);
    if ((tid & 31) == 0) shp[tid >> 5] = partial;
    __syncthreads();
    int pre = 0;
    #pragma unroll
    for (int w = 0; w < 8; w++) pre += shp[w];

    int i = blockIdx.x * SCAN_BS + tid;
    int v = (i < NR) ? cnt[i] : 0;
    sh[tid] = v;
    __syncthreads();
    for (int o = 1; o < SCAN_BS; o <<= 1) {
        int t = (tid >= o) ? sh[tid - o] : 0;
        __syncthreads();
        sh[tid] += t;
        __syncthreads();
    }
    int excl = sh[tid] - v + pre;
    if (i < NR) { rp[i] = excl; off[i] = excl; }
    if (i == NR - 1) rp[NR] = excl + v;
}

// scatter: 4 edges/thread, packed 8B stores
__global__ void scatter_k(const int* __restrict__ rows, const int* __restrict__ cols,
                          const float* __restrict__ vals,
                          int* __restrict__ off, ull* __restrict__ epack) {
    const int E4 = (2 * NNZ_E) / 4;                // 500000
    int t = blockIdx.x * blockDim.x + threadIdx.x;
    if (t >= E4) return;
    int r[4], c[4]; unsigned vb[4];
    #pragma unroll
    for (int j = 0; j < 4; j++) {
        int idx = t + j * E4;                      // 0 .. 2*NNZ-1
        if (idx < NNZ_E) {
            r[j] = __ldg(rows + idx);
            c[j] = __ldg(cols + idx);
            vb[j] = __float_as_uint(__ldg(vals + idx));
        } else {
            int e = idx - NNZ_E;
            r[j] = N_U + __ldg(cols + e);
            c[j] = __ldg(rows + e);
            vb[j] = __float_as_uint(__ldg(vals + e));
        }
    }
    int slot[4];
    #pragma unroll
    for (int j = 0; j < 4; j++) slot[j] = atomicAdd(&off[r[j]], 1);
    #pragma unroll
    for (int j = 0; j < 4; j++)
        epack[slot[j]] = ((ull)vb[j] << 32) | (unsigned)c[j];
}

// ---------------- CSR SpMM layer1: warp per row, bf16 gather ------------------
__global__ void spmm_csr_k(const int* __restrict__ rp,
                           const ull* __restrict__ epack,
                           const __nv_bfloat16* __restrict__ E0b,
                           __nv_bfloat16* __restrict__ Zb) {
    int w = (blockIdx.x * blockDim.x + threadIdx.x) >> 5;
    int lane = threadIdx.x & 31;
    if (w >= NR) return;
    const __nv_bfloat16* X = (w < N_U) ? (E0b + (size_t)N_U * DD) : E0b;
    int e = __ldg(rp + w), e1 = __ldg(rp + w + 1);
    float2 acc = make_float2(0.f, 0.f);
    for (; e + 3 < e1; e += 4) {
        ull p0 = __ldg(epack + e),     p1 = __ldg(epack + e + 1);
        ull p2 = __ldg(epack + e + 2), p3 = __ldg(epack + e + 3);
        int c0, c1, c2, c3; float v0, v1, v2, v3;
        unpack_edge(p0, c0, v0); unpack_edge(p1, c1, v1);
        unpack_edge(p2, c2, v2); unpack_edge(p3, c3, v3);
        float2 x0 = __bfloat1622float2(*(const __nv_bfloat162*)(X + (size_t)c0 * DD + lane * 2));
        float2 x1 = __bfloat1622float2(*(const __nv_bfloat162*)(X + (size_t)c1 * DD + lane * 2));
        float2 x2 = __bfloat1622float2(*(const __nv_bfloat162*)(X + (size_t)c2 * DD + lane * 2));
        float2 x3 = __bfloat1622float2(*(const __nv_bfloat162*)(X + (size_t)c3 * DD + lane * 2));
        acc.x = fmaf(v0, x0.x, acc.x); acc.y = fmaf(v0, x0.y, acc.y);
        acc.x = fmaf(v1, x1.x, acc.x); acc.y = fmaf(v1, x1.y, acc.y);
        acc.x = fmaf(v2, x2.x, acc.x); acc.y = fmaf(v2, x2.y, acc.y);
        acc.x = fmaf(v3, x3.x, acc.x); acc.y = fmaf(v3, x3.y, acc.y);
    }
    for (; e < e1; e++) {
        int c0; float v0; unpack_edge(__ldg(epack + e), c0, v0);
        float2 x0 = __bfloat1622float2(*(const __nv_bfloat162*)(X + (size_t)c0 * DD + lane * 2));
        acc.x = fmaf(v0, x0.x, acc.x); acc.y = fmaf(v0, x0.y, acc.y);
    }
    *(__nv_bfloat162*)(Zb + (size_t)w * DD + lane * 2) = __floats2bfloat162_rn(acc.x, acc.y);
}

// ---- CSR SpMM layer2 fused: Ef = E0 + Z1 + A@Z1 ; write Eout + bf16 Eb ------
__global__ void spmm_csr_out_k(const int* __restrict__ rp,
                               const ull* __restrict__ epack,
                               const __nv_bfloat16* __restrict__ Zb,
                               const float* __restrict__ Eu0,
                               const float* __restrict__ Ei0,
                               float* __restrict__ Ef,
                               float* __restrict__ Eout,    // misaligned d_out
                               __nv_bfloat16* __restrict__ Eb) {
    int w = (blockIdx.x * blockDim.x + threadIdx.x) >> 5;
    int lane = threadIdx.x & 31;
    if (w >= NR) return;
    const __nv_bfloat16* X = (w < N_U) ? (Zb + (size_t)N_U * DD) : Zb;
    const float* E0row = (w < N_U) ? (Eu0 + (size_t)w * DD)
                                   : (Ei0 + (size_t)(w - N_U) * DD);
    int e = __ldg(rp + w), e1 = __ldg(rp + w + 1);
    float2 acc = make_float2(0.f, 0.f);
    for (; e + 3 < e1; e += 4) {
        ull p0 = __ldg(epack + e),     p1 = __ldg(epack + e + 1);
        ull p2 = __ldg(epack + e + 2), p3 = __ldg(epack + e + 3);
        int c0, c1, c2, c3; float v0, v1, v2, v3;
        unpack_edge(p0, c0, v0); unpack_edge(p1, c1, v1);
        unpack_edge(p2, c2, v2); unpack_edge(p3, c3, v3);
        float2 x0 = __bfloat1622float2(*(const __nv_bfloat162*)(X + (size_t)c0 * DD + lane * 2));
        float2 x1 = __bfloat1622float2(*(const __nv_bfloat162*)(X + (size_t)c1 * DD + lane * 2));
        float2 x2 = __bfloat1622float2(*(const __nv_bfloat162*)(X + (size_t)c2 * DD + lane * 2));
        float2 x3 = __bfloat1622float2(*(const __nv_bfloat162*)(X + (size_t)c3 * DD + lane * 2));
        acc.x = fmaf(v0, x0.x, acc.x); acc.y = fmaf(v0, x0.y, acc.y);
        acc.x = fmaf(v1, x1.x, acc.x); acc.y = fmaf(v1, x1.y, acc.y);
        acc.x = fmaf(v2, x2.x, acc.x); acc.y = fmaf(v2, x2.y, acc.y);
        acc.x = fmaf(v3, x3.x, acc.x); acc.y = fmaf(v3, x3.y, acc.y);
    }
    for (; e < e1; e++) {
        int c0; float v0; unpack_edge(__ldg(epack + e), c0, v0);
        float2 x0 = __bfloat1622float2(*(const __nv_bfloat162*)(X + (size_t)c0 * DD + lane * 2));
        acc.x = fmaf(v0, x0.x, acc.x); acc.y = fmaf(v0, x0.y, acc.y);
    }
    size_t base = (size_t)w * DD + lane * 2;
    float2 e0 = *(const float2*)(E0row + lane * 2);
    float2 z1 = __bfloat1622float2(*(const __nv_bfloat162*)(Zb + base));
    acc.x += e0.x + z1.x; acc.y += e0.y + z1.y;
    *(float2*)(Ef + base) = acc;
    Eout[base] = acc.x;
    Eout[base + 1] = acc.y;
    *(__nv_bfloat162*)(Eb + base) = __floats2bfloat162_rn(acc.x, acc.y);
}

// ------------- prep (slim): M = P @ (E0+Z1) ; reg = sum(E0^2) -----------------
__global__ void prep_slim(const float* __restrict__ Eu0,
                          const float* __restrict__ Ei0,
                          const __nv_bfloat16* __restrict__ Zb,
                          const float* __restrict__ Put,
                          const float* __restrict__ Pvt,
                          float* __restrict__ Mi,
                          float* __restrict__ Mu,
                          float* __restrict__ regAcc) {
    const bool isU = blockIdx.x < 2048;
    const int vbid = isU ? blockIdx.x : blockIdx.x - 2048;
    const int vgrid = isU ? 2048 : 1024;
    const int n_rows = isU ? N_U : N_I;
    const float* E0 = isU ? Eu0 : Ei0;
    const __nv_bfloat16* Z1 = isU ? Zb : (Zb + (size_t)N_U * DD);
    const float* P  = isU ? Put : Pvt;
    float* Macc = isU ? Mi : Mu;

    int d = threadIdx.x & 63;
    int grp = threadIdx.x >> 6;                 // 0..3
    float m0 = 0, m1 = 0, m2 = 0, m3 = 0, m4 = 0, racc = 0;
    for (int r = vbid * 4 + grp; r < n_rows; r += vgrid * 4) {
        size_t off = (size_t)r * DD + d;
        float e0 = E0[off];
        float t  = e0 + __bfloat162float(Z1[off]);
        racc = fmaf(e0, e0, racc);
        m0 = fmaf(__ldg(P + r), t, m0);
        m1 = fmaf(__ldg(P + (size_t)n_rows + r), t, m1);
        m2 = fmaf(__ldg(P + 2 * (size_t)n_rows + r), t, m2);
        m3 = fmaf(__ldg(P + 3 * (size_t)n_rows + r), t, m3);
        m4 = fmaf(__ldg(P + 4 * (size_t)n_rows + r), t, m4);
    }
    __shared__ float sm[4][QQ][DD];
    sm[grp][0][d] = m0; sm[grp][1][d] = m1; sm[grp][2][d] = m2;
    sm[grp][3][d] = m3; sm[grp][4][d] = m4;
    __syncthreads();
    if (grp == 0) {
        #pragma unroll
        for (int q = 0; q < QQ; q++)
            atomicAdd(&Macc[q * DD + d],
                      sm[0][q][d] + sm[1][q][d] + sm[2][q][d] + sm[3][q][d]);
    }
    racc = warp_sum(racc);
    if ((threadIdx.x & 31) == 0) atomicAdd(regAcc, racc);
}

// ---------------- G selection (+ merged weight L2 reg, blocks >= 1536) --------
__global__ void gsel_kernel(const int* __restrict__ uids,
                            const int* __restrict__ pos,
                            const int* __restrict__ neg,
                            const float* __restrict__ Eu0,
                            const float* __restrict__ Ei0,
                            const float* __restrict__ mu_s,
                            const float* __restrict__ mi_s,
                            const float* __restrict__ Mu,
                            const float* __restrict__ Mi,
                            float* __restrict__ G,
                            __nv_bfloat16* __restrict__ Gb,
                            const float* __restrict__ W1,
                            const float* __restrict__ b1,
                            const float* __restrict__ W2,
                            const float* __restrict__ b2,
                            float* __restrict__ wacc) {
    int b = blockIdx.x, d = threadIdx.x;
    if (b >= 1536) {                       // weight L2 reg
        int t = (b - 1536) * 64 + d;       // 0..12287
        float s = 0.f;
        for (int i = t; i < 768 * 64; i += 192 * 64) {
            float a = W1[i]; s = fmaf(a, a, s);
            float c = W2[i]; s = fmaf(c, c, s);
        }
        if (t < 64) {
            float a = b1[t]; s = fmaf(a, a, s);
            float c = b2[t]; s = fmaf(c, c, s);
        }
        s = warp_sum(s);
        if ((d & 31) == 0) atomicAdd(wacc, s);
        return;
    }
    const float* E0; const float* ms; const float* M; int id;
    if (b < 512)       { E0 = Eu0; ms = mu_s; M = Mu; id = uids[b]; }
    else if (b < 1024) { E0 = Ei0; ms = mi_s; M = Mi; id = pos[b - 512]; }
    else               { E0 = Ei0; ms = mi_s; M = Mi; id = neg[b - 1024]; }
    float v = E0[(size_t)id * DD + d];
    #pragma unroll
    for (int q = 0; q < QQ; q++)
        v = fmaf(ms[(size_t)id * QQ + q], M[q * DD + d], v);
    float v5 = 5.0f * v;
    G[b * DD + d] = v5;
    Gb[b * DD + d] = __float2bfloat16(v5);
}

// ----- tensor-core logits (+ merged small-loss blocks at the grid tail) -------
#define SMEM_MMA (2 * 128 * 144)
__global__ __launch_bounds__(256, 2)
void logits_mma(const __nv_bfloat16* __restrict__ Gbu,
                const __nv_bfloat16* __restrict__ Gbi,
                const __nv_bfloat16* __restrict__ Ebu,
                const __nv_bfloat16* __restrict__ Ebi,
                float* __restrict__ Su, float* __restrict__ Si,
                int ublocks, int gemm_blocks,
                const int* __restrict__ uids,
                const int* __restrict__ pos,
                const int* __restrict__ neg,
                const float* __restrict__ Eu,
                const float* __restrict__ Ei,
                const float* __restrict__ Gu,
                const float* __restrict__ Gi,
                const int* __restrict__ unpop,
                const int* __restrict__ popi,
                float* __restrict__ sc) {
    extern __shared__ char smc[];
    const int tid = threadIdx.x;

    if ((int)blockIdx.x >= gemm_blocks) {
        int gtid = ((int)blockIdx.x - gemm_blocks) * 256 + tid;
        int wid = gtid >> 5, lane = gtid & 31;
        if (wid < 512) {                       // pos_u
            int b = wid, u = uids[b];
            float s = Gu[b * DD + lane] * Eu[(size_t)u * DD + lane]
                    + Gu[b * DD + 32 + lane] * Eu[(size_t)u * DD + 32 + lane];
            s = warp_sum(s);
            if (lane == 0) atomicAdd(&sc[1], fminf(fmaxf(s, -5.0f), 5.0f));
        } else if (wid < 1536) {               // pos_i
            int b = wid - 512;
            int id = (b < 512) ? pos[b] : neg[b - 512];
            float s = Gi[b * DD + lane] * Ei[(size_t)id * DD + lane]
                    + Gi[b * DD + 32 + lane] * Ei[(size_t)id * DD + 32 + lane];
            s = warp_sum(s);
            if (lane == 0) atomicAdd(&sc[2], fminf(fmaxf(s, -5.0f), 5.0f));
        } else if (wid < 2048) {               // BPR
            int b = wid - 1536, u = uids[b], p = pos[b], nn = neg[b];
            float eu0 = Eu[(size_t)u * DD + lane], eu1 = Eu[(size_t)u * DD + 32 + lane];
            float sp = eu0 * Ei[(size_t)p * DD + lane]  + eu1 * Ei[(size_t)p * DD + 32 + lane];
            float sn = eu0 * Ei[(size_t)nn * DD + lane] + eu1 * Ei[(size_t)nn * DD + 32 + lane];
            sp = warp_sum(sp);
            sn = warp_sum(sn);
            if (lane == 0) {
                float x = sp - sn;
                float t = (x > 0.f) ? log1pf(expf(-x)) : (-x + log1pf(expf(x)));
                atomicAdd(&sc[3], t);
            }
        } else {                               // extra-loss pairs
            int p = wid - 2048;
            if (p >= 64 * 8 * 32) return;
            int ig = p >> 8, rem = p & 255, ui = rem >> 5, pi = rem & 31;
            int a = unpop[ig * 8 + ui];
            int c = popi[ig * 32 + pi];
            float d0 = Ei[(size_t)a * DD + lane] - Ei[(size_t)c * DD + lane];
            float d1 = Ei[(size_t)a * DD + 32 + lane] - Ei[(size_t)c * DD + 32 + lane];
            float s = warp_sum(d0 * d0 + d1 * d1);
            if (lane == 0) atomicAdd(&sc[4], sqrtf(s));
        }
        return;
    }

    // ---------------- GEMM blocks ----------------
    const uint32_t sA = smem_u32(smc);
    const uint32_t sB = sA + 128 * 144;
    const bool isU = ((int)blockIdx.x < ublocks);
    const int bid = isU ? blockIdx.x : blockIdx.x - ublocks;
    const int Mtiles = isU ? 4 : 8;
    const int N = isU ? N_U : N_I;
    const __nv_bfloat16* Gb = isU ? Gbu : Gbi;
    const __nv_bfloat16* Eb = isU ? Ebu : Ebi;
    float* S = isU ? Su : Si;
    const int mt = bid % Mtiles;
    const long n0 = (long)(bid / Mtiles) * 128;

    #pragma unroll
    for (int it = 0; it < 4; it++) {
        int idx = it * 256 + tid;
        int row = idx >> 3, c = idx & 7;
        uint4 v = *(const uint4*)(Gb + ((size_t)(mt * 128 + row)) * DD + c * 8);
        *(uint4*)(smc + row * 144 + c * 16) = v;
    }
    #pragma unroll
    for (int it = 0; it < 4; it++) {
        int idx = it * 256 + tid;
        int row = idx >> 3, c = idx & 7;
        long n = n0 + row;
        uint4 v = make_uint4(0, 0, 0, 0);
        if (n < N) v = *(const uint4*)(Eb + n * DD + c * 8);
        *(uint4*)(smc + 128 * 144 + row * 144 + c * 16) = v;
    }
    __syncthreads();

    const int wid = tid >> 5, lane = tid & 31;
    const int wm = (wid & 3) * 32;
    const int wn = (wid >> 2) * 64;

    float d[2][8][4];
    #pragma unroll
    for (int mi = 0; mi < 2; mi++)
        #pragma unroll
        for (int ni = 0; ni < 8; ni++)
            #pragma unroll
            for (int j = 0; j < 4; j++) d[mi][ni][j] = 0.f;

    const int lrowA = (lane & 7) + ((lane & 8) ? 8 : 0);
    const int lcolA = (lane & 16) ? 8 : 0;
    const int lrowB = (lane & 7) + ((lane & 16) ? 8 : 0);
    const int lcolB = (lane & 8) ? 8 : 0;

    #pragma unroll
    for (int ks = 0; ks < 4; ks++) {
        const int k0 = ks * 16;
        unsigned a[2][4];
        #pragma unroll
        for (int mi = 0; mi < 2; mi++) {
            uint32_t addr = sA + (wm + mi * 16 + lrowA) * 144 + (k0 + lcolA) * 2;
            ldmx4(a[mi][0], a[mi][1], a[mi][2], a[mi][3], addr);
        }
        #pragma unroll
        for (int np = 0; np < 4; np++) {
            unsigned b[4];
            uint32_t addr = sB + (wn + np * 16 + lrowB) * 144 + (k0 + lcolB) * 2;
            ldmx4(b[0], b[1], b[2], b[3], addr);
            #pragma unroll
            for (int mi = 0; mi < 2; mi++) {
                mma16816(d[mi][np * 2 + 0], a[mi], b + 0);
                mma16816(d[mi][np * 2 + 1], a[mi], b + 2);
            }
        }
    }

    const bool full = (n0 + 128 <= N);
    const int r4 = lane >> 2;
    #pragma unroll
    for (int mi = 0; mi < 2; mi++) {
        float slo = 0.f, shi = 0.f;
        #pragma unroll
        for (int ni = 0; ni < 8; ni++) {
            if (full) {
                slo += __expf(d[mi][ni][0]) + __expf(d[mi][ni][1]);
                shi += __expf(d[mi][ni][2]) + __expf(d[mi][ni][3]);
            } else {
                long c = n0 + wn + ni * 8 + (lane & 3) * 2;
                if (c < N)     { slo += __expf(d[mi][ni][0]); shi += __expf(d[mi][ni][2]); }
                if (c + 1 < N) { slo += __expf(d[mi][ni][1]); shi += __expf(d[mi][ni][3]); }
            }
        }
        slo += __shfl_xor_sync(0xffffffffu, slo, 1);
        slo += __shfl_xor_sync(0xffffffffu, slo, 2);
        shi += __shfl_xor_sync(0xffffffffu, shi, 1);
        shi += __shfl_xor_sync(0xffffffffu, shi, 2);
        if ((lane & 3) == 0) {
            atomicAdd(&S[mt * 128 + wm + mi * 16 + r4], slo);
            atomicAdd(&S[mt * 128 + wm + mi * 16 + 8 + r4], shi);
        }
    }
}

// -------------------------------- finalize -----------------------------------
__global__ void finalize_kernel(const float* __restrict__ su,
                                const float* __restrict__ si,
                                const float* __restrict__ sc,
                                float* __restrict__ out) {
    __shared__ float s_lu[16], s_li[16];
    int tid = threadIdx.x;   // 512 threads
    float lu = logf(su[tid] + 1e-8f);
    float li = logf(si[tid] + 1e-8f) + logf(si[tid + 512] + 1e-8f);
    lu = warp_sum(lu);
    li = warp_sum(li);
    if ((tid & 31) == 0) { s_lu[tid >> 5] = lu; s_li[tid >> 5] = li; }
    __syncthreads();
    if (tid == 0) {
        float LU = 0.f, LI = 0.f;
        #pragma unroll
        for (int w = 0; w < 16; w++) { LU += s_lu[w]; LI += s_li[w]; }
        float neg_score = LU / 512.f + LI / 1024.f;
        float pos_score = sc[1] / 512.f + sc[2] / 1024.f;
        float loss_s = -pos_score + neg_score;
        float loss_r = sc[3] / 512.f;
        float loss_reg = 1e-7f * sc[0];
        float extra = sc[4] * (1.f / 32.f);
        float loss = loss_r + 0.2f * loss_s + loss_reg + 0.01f * extra;
        out[0] = loss;
        out[1] = loss_r;
        out[2] = 0.2f * loss_s;
    }
}

// ------------------------------- launcher ------------------------------------
extern "C" void kernel_launch(void* const* d_in, const int* in_sizes, int n_in,
                              void* d_out, int out_size) {
    const int*   uids     = (const int*)d_in[0];
    const int*   pos      = (const int*)d_in[1];
    const int*   neg      = (const int*)d_in[2];
    const int*   adj_rows = (const int*)d_in[3];
    const int*   adj_cols = (const int*)d_in[4];
    const float* adj_vals = (const float*)d_in[5];
    const float* E_u_0    = (const float*)d_in[6];
    const float* E_i_0    = (const float*)d_in[7];
    const float* u_mul_s  = (const float*)d_in[8];
    const float* vt       = (const float*)d_in[9];
    const float* v_mul_s  = (const float*)d_in[10];
    const float* ut       = (const float*)d_in[11];
    const float* W_api    = (const float*)d_in[12];
    const float* b_api    = (const float*)d_in[13];
    const float* W_mashup = (const float*)d_in[14];
    const float* b_mashup = (const float*)d_in[15];
    const float* pos_api  = (const float*)d_in[16];
    const float* neg_api  = (const float*)d_in[17];
    const float* mashup   = (const float*)d_in[18];
    const int*   unpop    = (const int*)d_in[19];
    const int*   popi     = (const int*)d_in[20];

    float* out = (float*)d_out;
    const size_t EMB = (size_t)EMBF;
    float* out_mashup = out + 3;
    float* out_posapi = out + 3 + EMB;
    float* out_negapi = out + 3 + 2 * EMB;
    float* Eu_out = out + 3 + 3 * EMB;

    float *Efb, *Sm, *G;
    __nv_bfloat16 *E0b, *Zbb, *Eb, *Gb;
    int *cnt, *rp, *off, *bsum;
    ull *epack;
    cudaGetSymbolAddress((void**)&E0b,  g_E0b);
    cudaGetSymbolAddress((void**)&Zbb,  g_Zb);
    cudaGetSymbolAddress((void**)&Efb,  g_Ef);
    cudaGetSymbolAddress((void**)&Eb,   g_Eb);
    cudaGetSymbolAddress((void**)&Sm,   g_small);
    cudaGetSymbolAddress((void**)&G,    g_G);
    cudaGetSymbolAddress((void**)&Gb,   g_Gb);
    cudaGetSymbolAddress((void**)&cnt,  g_cnt);
    cudaGetSymbolAddress((void**)&rp,   g_rp);
    cudaGetSymbolAddress((void**)&off,  g_off);
    cudaGetSymbolAddress((void**)&bsum, g_bsum);
    cudaGetSymbolAddress((void**)&epack, g_epack);

    float* Euf = Efb;
    float* Eif = Euf + (size_t)N_U * DD;
    __nv_bfloat16* Eub = Eb;
    __nv_bfloat16* Eib = Eub + (size_t)N_U * DD;
    float* Mu = Sm + OFF_MU;
    float* Mi = Sm + OFF_MI;
    float* su = Sm + OFF_SU;
    float* si = Sm + OFF_SI;
    float* sc = Sm + OFF_SC;
    float* Gu = G;
    float* Gi = G + (size_t)BB * DD;
    __nv_bfloat16* Gub = Gb;
    __nv_bfloat16* Gib = Gub + (size_t)BB * DD;

    cudaFuncSetAttribute(logits_mma,
                         cudaFuncAttributeMaxDynamicSharedMemorySize, SMEM_MMA);

    cudaMemsetAsync(cnt, 0, NR * 4);

    const size_t n4 = (size_t)NR * DD / 4;
    conv_hist_copy_k<<<(int)((n4 + 255) / 256), 256>>>(
        E_u_0, E_i_0, E0b, adj_rows, adj_cols, cnt,
        mashup, pos_api, neg_api, out_mashup, out_posapi, out_negapi);

    scan1_k<<<SCAN_NB, SCAN_BS>>>(cnt, bsum, Sm);
    scan3_k<<<SCAN_NB, SCAN_BS>>>(cnt, bsum, rp, off);
    scatter_k<<<((2 * NNZ_E / 4) + 255) / 256, 256>>>(adj_rows, adj_cols, adj_vals,
                                                      off, epack);

    const int csr_blocks = (NR * 32 + 255) / 256;
    spmm_csr_k<<<csr_blocks, 256>>>(rp, epack, E0b, Zbb);
    prep_slim<<<3072, 256>>>(E_u_0, E_i_0, Zbb, ut, vt, Mi, Mu, sc);
    spmm_csr_out_k<<<csr_blocks, 256>>>(rp, epack, Zbb, E_u_0, E_i_0,
                                        Efb, Eu_out, Eb);

    gsel_kernel<<<1536 + 192, 64>>>(uids, pos, neg, E_u_0, E_i_0,
                                    u_mul_s, v_mul_s, Mu, Mi, G, Gb,
                                    W_api, b_api, W_mashup, b_mashup, sc);

    const int ntu = (N_U + 127) / 128;   // 782
    const int nti = (N_I + 127) / 128;   // 391
    const int ublocks = 4 * ntu;
    const int gemm_blocks = ublocks + 8 * nti;
    logits_mma<<<gemm_blocks + 2304, 256, SMEM_MMA>>>(
        Gub, Gib, Eub, Eib, su, si, ublocks, gemm_blocks,
        uids, pos, neg, Euf, Eif, Gu, Gi, unpop, popi, sc);

    finalize_kernel<<<1, 512>>>(su, si, sc, out);
}

// round 17
// speedup vs baseline: 2.3678x; 1.0808x over previous
#include <cuda_runtime.h>
#include <cuda_bf16.h>
#include <cstdint>
#include <cstddef>

#define N_U 100000
#define N_I 50000
#define NR  (N_U + N_I)
#define DD  64
#define QQ  5
#define NNZ_E 1000000
#define BB  512
#define SCAN_BS 256
#define SCAN_NB ((NR + SCAN_BS - 1) / SCAN_BS)   // 586
#define EMBF 393216
#define EMB4 (EMBF / 4)

typedef unsigned long long ull;

// ------------------------- scratch (device globals) -------------------------
__device__ __align__(16) __nv_bfloat16 g_E0b[(size_t)NR * DD];
__device__ __align__(16) __nv_bfloat16 g_Zb[(size_t)NR * DD];
__device__ __align__(16) float g_Ef[(size_t)NR * DD];
__device__ __align__(16) __nv_bfloat16 g_Eb[(size_t)NR * DD];
__device__ __align__(16) float g_small[2304];
__device__ __align__(16) float g_G[3 * BB * DD];
__device__ __align__(16) __nv_bfloat16 g_Gb[3 * BB * DD];
__device__ int   g_cnt[NR];
__device__ int   g_rp[NR + 1];
__device__ int   g_off[NR];
__device__ int   g_bsum[1024];
__device__ __align__(16) ull g_epack[2 * NNZ_E];   // hi32 = val bits, lo32 = col

#define OFF_MU 0
#define OFF_MI 320
#define OFF_SU 640
#define OFF_SI 1152
#define OFF_SC 2176

// ------------------------------ helpers -------------------------------------
__device__ __forceinline__ float warp_sum(float v) {
    #pragma unroll
    for (int o = 16; o; o >>= 1) v += __shfl_xor_sync(0xffffffffu, v, o);
    return v;
}
__device__ __forceinline__ int warp_sum_i(int v) {
    #pragma unroll
    for (int o = 16; o; o >>= 1) v += __shfl_xor_sync(0xffffffffu, v, o);
    return v;
}
__device__ __forceinline__ uint32_t smem_u32(const void* p) {
    uint32_t a;
    asm("{ .reg .u64 t; cvta.to.shared.u64 t, %1; cvt.u32.u64 %0, t; }" : "=r"(a) : "l"(p));
    return a;
}
__device__ __forceinline__ void ldmx4(unsigned& r0, unsigned& r1,
                                      unsigned& r2, unsigned& r3, uint32_t addr) {
    asm volatile("ldmatrix.sync.aligned.m8n8.x4.shared.b16 {%0,%1,%2,%3}, [%4];"
                 : "=r"(r0), "=r"(r1), "=r"(r2), "=r"(r3) : "r"(addr));
}
__device__ __forceinline__ void mma16816(float* d, const unsigned* a, const unsigned* b) {
    asm volatile("mma.sync.aligned.m16n8k16.row.col.f32.bf16.bf16.f32 "
                 "{%0,%1,%2,%3}, {%4,%5,%6,%7}, {%8,%9}, {%0,%1,%2,%3};"
                 : "+f"(d[0]), "+f"(d[1]), "+f"(d[2]), "+f"(d[3])
                 : "r"(a[0]), "r"(a[1]), "r"(a[2]), "r"(a[3]), "r"(b[0]), "r"(b[1]));
}
__device__ __forceinline__ void unpack_edge(ull p, int& c, float& v) {
    c = (int)(unsigned)p;
    v = __uint_as_float((unsigned)(p >> 32));
}
// gather 4 bf16 (8B) and fma into 4 accumulators
__device__ __forceinline__ void gfma4(float* a, const __nv_bfloat16* X,
                                      int c, int lane, float v) {
    uint2 raw = *(const uint2*)(X + (size_t)c * DD + lane * 4);
    float2 lo = __bfloat1622float2(*(const __nv_bfloat162*)&raw.x);
    float2 hi = __bfloat1622float2(*(const __nv_bfloat162*)&raw.y);
    a[0] = fmaf(v, lo.x, a[0]); a[1] = fmaf(v, lo.y, a[1]);
    a[2] = fmaf(v, hi.x, a[2]); a[3] = fmaf(v, hi.y, a[3]);
}

// -------- fused: E0->bf16 conversion + degree histogram + api copies ---------
__global__ void conv_hist_copy_k(const float* __restrict__ Eu0,
                                 const float* __restrict__ Ei0,
                                 __nv_bfloat16* __restrict__ E0b,
                                 const int* __restrict__ rows,
                                 const int* __restrict__ cols,
                                 int* __restrict__ cnt,
                                 const float* __restrict__ mashup,
                                 const float* __restrict__ pos_api,
                                 const float* __restrict__ neg_api,
                                 float* __restrict__ o_mash,
                                 float* __restrict__ o_pos,
                                 float* __restrict__ o_neg) {
    size_t i = (size_t)blockIdx.x * blockDim.x + threadIdx.x;
    const size_t nu4 = (size_t)N_U * DD / 4;
    const size_t n4 = (size_t)NR * DD / 4;
    if (i < n4) {
        float4 v = (i < nu4) ? ((const float4*)Eu0)[i]
                             : ((const float4*)Ei0)[i - nu4];
        *(__nv_bfloat162*)(E0b + i * 4)     = __floats2bfloat162_rn(v.x, v.y);
        *(__nv_bfloat162*)(E0b + i * 4 + 2) = __floats2bfloat162_rn(v.z, v.w);
    }
    if (i < NNZ_E) atomicAdd(&cnt[__ldg(rows + i)], 1);
    else if (i < 2 * NNZ_E) atomicAdd(&cnt[N_U + __ldg(cols + (i - NNZ_E))], 1);
    if (i < 3 * EMB4) {
        const float* src; float* dst; size_t j;
        if (i < EMB4)            { src = mashup;  dst = o_mash; j = i; }
        else if (i < 2 * EMB4)   { src = pos_api; dst = o_pos;  j = i - EMB4; }
        else                     { src = neg_api; dst = o_neg;  j = i - 2 * EMB4; }
        float4 v = ((const float4*)src)[j];
        float* o = dst + j * 4;
        o[0] = v.x; o[1] = v.y; o[2] = v.z; o[3] = v.w;
    }
}

// ------------------------------ CSR build ------------------------------------
__global__ void scan1_k(const int* __restrict__ cnt, int* __restrict__ bsum,
                        float* __restrict__ Sm) {
    __shared__ int sh[8];
    int i = blockIdx.x * SCAN_BS + threadIdx.x;
    int v = (i < NR) ? cnt[i] : 0;
    v = warp_sum_i(v);
    if ((threadIdx.x & 31) == 0) sh[threadIdx.x >> 5] = v;
    __syncthreads();
    if (threadIdx.x == 0) {
        int t = 0;
        #pragma unroll
        for (int w = 0; w < 8; w++) t += sh[w];
        bsum[blockIdx.x] = t;
    }
    if (blockIdx.x == 0)
        for (int j = threadIdx.x; j < 2304; j += SCAN_BS) Sm[j] = 0.f;
}

__global__ void scan3_k(const int* __restrict__ cnt, const int* __restrict__ bsum,
                        int* __restrict__ rp, int* __restrict__ off) {
    __shared__ int sh[SCAN_BS];
    __shared__ int shp[8];
    int tid = threadIdx.x;
    int partial = 0;
    for (int j = tid; j < (int)blockIdx.x; j += SCAN_BS) partial += bsum[j];
    partial = warp_sum_i(partial);
    if ((tid & 31) == 0) shp[tid >> 5] = partial;
    __syncthreads();
    int pre = 0;
    #pragma unroll
    for (int w = 0; w < 8; w++) pre += shp[w];

    int i = blockIdx.x * SCAN_BS + tid;
    int v = (i < NR) ? cnt[i] : 0;
    sh[tid] = v;
    __syncthreads();
    for (int o = 1; o < SCAN_BS; o <<= 1) {
        int t = (tid >= o) ? sh[tid - o] : 0;
        __syncthreads();
        sh[tid] += t;
        __syncthreads();
    }
    int excl = sh[tid] - v + pre;
    if (i < NR) { rp[i] = excl; off[i] = excl; }
    if (i == NR - 1) rp[NR] = excl + v;
}

// scatter: 8 edges/thread, packed 8B stores, front-batched atomics (MLP=8)
__global__ void scatter_k(const int* __restrict__ rows, const int* __restrict__ cols,
                          const float* __restrict__ vals,
                          int* __restrict__ off, ull* __restrict__ epack) {
    const int E8 = (2 * NNZ_E) / 8;                // 250000
    int t = blockIdx.x * blockDim.x + threadIdx.x;
    if (t >= E8) return;
    int r[8], c[8]; unsigned vb[8];
    #pragma unroll
    for (int j = 0; j < 8; j++) {
        int idx = t + j * E8;                      // 0 .. 2*NNZ-1
        if (idx < NNZ_E) {
            r[j] = __ldg(rows + idx);
            c[j] = __ldg(cols + idx);
            vb[j] = __float_as_uint(__ldg(vals + idx));
        } else {
            int e = idx - NNZ_E;
            r[j] = N_U + __ldg(cols + e);
            c[j] = __ldg(rows + e);
            vb[j] = __float_as_uint(__ldg(vals + e));
        }
    }
    int slot[8];
    #pragma unroll
    for (int j = 0; j < 8; j++) slot[j] = atomicAdd(&off[r[j]], 1);
    #pragma unroll
    for (int j = 0; j < 8; j++)
        epack[slot[j]] = ((ull)vb[j] << 32) | (unsigned)c[j];
}

// ----------- CSR SpMM layer1: HALF-warp per row, LDG.64 bf16 gather -----------
__global__ void spmm_csr_k(const int* __restrict__ rp,
                           const ull* __restrict__ epack,
                           const __nv_bfloat16* __restrict__ E0b,
                           __nv_bfloat16* __restrict__ Zb) {
    int hw = (blockIdx.x * blockDim.x + threadIdx.x) >> 4;   // row id
    int lane = threadIdx.x & 15;
    if (hw >= NR) return;
    const __nv_bfloat16* X = (hw < N_U) ? (E0b + (size_t)N_U * DD) : E0b;
    int e = __ldg(rp + hw), e1 = __ldg(rp + hw + 1);
    float a[4] = {0.f, 0.f, 0.f, 0.f};
    for (; e + 3 < e1; e += 4) {
        ull p0 = __ldg(epack + e),     p1 = __ldg(epack + e + 1);
        ull p2 = __ldg(epack + e + 2), p3 = __ldg(epack + e + 3);
        int c0, c1, c2, c3; float v0, v1, v2, v3;
        unpack_edge(p0, c0, v0); unpack_edge(p1, c1, v1);
        unpack_edge(p2, c2, v2); unpack_edge(p3, c3, v3);
        gfma4(a, X, c0, lane, v0);
        gfma4(a, X, c1, lane, v1);
        gfma4(a, X, c2, lane, v2);
        gfma4(a, X, c3, lane, v3);
    }
    for (; e < e1; e++) {
        int c0; float v0; unpack_edge(__ldg(epack + e), c0, v0);
        gfma4(a, X, c0, lane, v0);
    }
    uint2 outp;
    *(__nv_bfloat162*)&outp.x = __floats2bfloat162_rn(a[0], a[1]);
    *(__nv_bfloat162*)&outp.y = __floats2bfloat162_rn(a[2], a[3]);
    *(uint2*)(Zb + (size_t)hw * DD + lane * 4) = outp;
}

// ---- CSR SpMM layer2 (half-warp) fused: Ef = E0+Z1+A@Z1 ; Eout ; bf16 Eb ----
__global__ void spmm_csr_out_k(const int* __restrict__ rp,
                               const ull* __restrict__ epack,
                               const __nv_bfloat16* __restrict__ Zb,
                               const float* __restrict__ Eu0,
                               const float* __restrict__ Ei0,
                               float* __restrict__ Ef,
                               float* __restrict__ Eout,    // misaligned d_out
                               __nv_bfloat16* __restrict__ Eb) {
    int hw = (blockIdx.x * blockDim.x + threadIdx.x) >> 4;
    int lane = threadIdx.x & 15;
    if (hw >= NR) return;
    const __nv_bfloat16* X = (hw < N_U) ? (Zb + (size_t)N_U * DD) : Zb;
    const float* E0row = (hw < N_U) ? (Eu0 + (size_t)hw * DD)
                                    : (Ei0 + (size_t)(hw - N_U) * DD);
    int e = __ldg(rp + hw), e1 = __ldg(rp + hw + 1);
    float a[4] = {0.f, 0.f, 0.f, 0.f};
    for (; e + 3 < e1; e += 4) {
        ull p0 = __ldg(epack + e),     p1 = __ldg(epack + e + 1);
        ull p2 = __ldg(epack + e + 2), p3 = __ldg(epack + e + 3);
        int c0, c1, c2, c3; float v0, v1, v2, v3;
        unpack_edge(p0, c0, v0); unpack_edge(p1, c1, v1);
        unpack_edge(p2, c2, v2); unpack_edge(p3, c3, v3);
        gfma4(a, X, c0, lane, v0);
        gfma4(a, X, c1, lane, v1);
        gfma4(a, X, c2, lane, v2);
        gfma4(a, X, c3, lane, v3);
    }
    for (; e < e1; e++) {
        int c0; float v0; unpack_edge(__ldg(epack + e), c0, v0);
        gfma4(a, X, c0, lane, v0);
    }
    size_t base = (size_t)hw * DD + lane * 4;
    float4 e0 = *(const float4*)(E0row + lane * 4);
    uint2 zraw = *(const uint2*)(Zb + base);
    float2 zlo = __bfloat1622float2(*(const __nv_bfloat162*)&zraw.x);
    float2 zhi = __bfloat1622float2(*(const __nv_bfloat162*)&zraw.y);
    float4 r;
    r.x = a[0] + e0.x + zlo.x;
    r.y = a[1] + e0.y + zlo.y;
    r.z = a[2] + e0.z + zhi.x;
    r.w = a[3] + e0.w + zhi.y;
    *(float4*)(Ef + base) = r;
    Eout[base] = r.x; Eout[base + 1] = r.y;
    Eout[base + 2] = r.z; Eout[base + 3] = r.w;
    uint2 outp;
    *(__nv_bfloat162*)&outp.x = __floats2bfloat162_rn(r.x, r.y);
    *(__nv_bfloat162*)&outp.y = __floats2bfloat162_rn(r.z, r.w);
    *(uint2*)(Eb + base) = outp;
}

// ------------- prep (slim): M = P @ (E0+Z1) ; reg = sum(E0^2) -----------------
__global__ void prep_slim(const float* __restrict__ Eu0,
                          const float* __restrict__ Ei0,
                          const __nv_bfloat16* __restrict__ Zb,
                          const float* __restrict__ Put,
                          const float* __restrict__ Pvt,
                          float* __restrict__ Mi,
                          float* __restrict__ Mu,
                          float* __restrict__ regAcc) {
    const bool isU = blockIdx.x < 2048;
    const int vbid = isU ? blockIdx.x : blockIdx.x - 2048;
    const int vgrid = isU ? 2048 : 1024;
    const int n_rows = isU ? N_U : N_I;
    const float* E0 = isU ? Eu0 : Ei0;
    const __nv_bfloat16* Z1 = isU ? Zb : (Zb + (size_t)N_U * DD);
    const float* P  = isU ? Put : Pvt;
    float* Macc = isU ? Mi : Mu;

    int d = threadIdx.x & 63;
    int grp = threadIdx.x >> 6;
    float m0 = 0, m1 = 0, m2 = 0, m3 = 0, m4 = 0, racc = 0;
    for (int r = vbid * 4 + grp; r < n_rows; r += vgrid * 4) {
        size_t off = (size_t)r * DD + d;
        float e0 = E0[off];
        float t  = e0 + __bfloat162float(Z1[off]);
        racc = fmaf(e0, e0, racc);
        m0 = fmaf(__ldg(P + r), t, m0);
        m1 = fmaf(__ldg(P + (size_t)n_rows + r), t, m1);
        m2 = fmaf(__ldg(P + 2 * (size_t)n_rows + r), t, m2);
        m3 = fmaf(__ldg(P + 3 * (size_t)n_rows + r), t, m3);
        m4 = fmaf(__ldg(P + 4 * (size_t)n_rows + r), t, m4);
    }
    __shared__ float sm[4][QQ][DD];
    sm[grp][0][d] = m0; sm[grp][1][d] = m1; sm[grp][2][d] = m2;
    sm[grp][3][d] = m3; sm[grp][4][d] = m4;
    __syncthreads();
    if (grp == 0) {
        #pragma unroll
        for (int q = 0; q < QQ; q++)
            atomicAdd(&Macc[q * DD + d],
                      sm[0][q][d] + sm[1][q][d] + sm[2][q][d] + sm[3][q][d]);
    }
    racc = warp_sum(racc);
    if ((threadIdx.x & 31) == 0) atomicAdd(regAcc, racc);
}

// ---------------- G selection (+ merged weight L2 reg, blocks >= 1536) --------
__global__ void gsel_kernel(const int* __restrict__ uids,
                            const int* __restrict__ pos,
                            const int* __restrict__ neg,
                            const float* __restrict__ Eu0,
                            const float* __restrict__ Ei0,
                            const float* __restrict__ mu_s,
                            const float* __restrict__ mi_s,
                            const float* __restrict__ Mu,
                            const float* __restrict__ Mi,
                            float* __restrict__ G,
                            __nv_bfloat16* __restrict__ Gb,
                            const float* __restrict__ W1,
                            const float* __restrict__ b1,
                            const float* __restrict__ W2,
                            const float* __restrict__ b2,
                            float* __restrict__ wacc) {
    int b = blockIdx.x, d = threadIdx.x;
    if (b >= 1536) {
        int t = (b - 1536) * 64 + d;
        float s = 0.f;
        for (int i = t; i < 768 * 64; i += 192 * 64) {
            float a = W1[i]; s = fmaf(a, a, s);
            float c = W2[i]; s = fmaf(c, c, s);
        }
        if (t < 64) {
            float a = b1[t]; s = fmaf(a, a, s);
            float c = b2[t]; s = fmaf(c, c, s);
        }
        s = warp_sum(s);
        if ((d & 31) == 0) atomicAdd(wacc, s);
        return;
    }
    const float* E0; const float* ms; const float* M; int id;
    if (b < 512)       { E0 = Eu0; ms = mu_s; M = Mu; id = uids[b]; }
    else if (b < 1024) { E0 = Ei0; ms = mi_s; M = Mi; id = pos[b - 512]; }
    else               { E0 = Ei0; ms = mi_s; M = Mi; id = neg[b - 1024]; }
    float v = E0[(size_t)id * DD + d];
    #pragma unroll
    for (int q = 0; q < QQ; q++)
        v = fmaf(ms[(size_t)id * QQ + q], M[q * DD + d], v);
    float v5 = 5.0f * v;
    G[b * DD + d] = v5;
    Gb[b * DD + d] = __float2bfloat16(v5);
}

// ----- tensor-core logits (+ merged small-loss blocks at the grid tail) -------
#define SMEM_MMA (2 * 128 * 144)
__global__ __launch_bounds__(256, 2)
void logits_mma(const __nv_bfloat16* __restrict__ Gbu,
                const __nv_bfloat16* __restrict__ Gbi,
                const __nv_bfloat16* __restrict__ Ebu,
                const __nv_bfloat16* __restrict__ Ebi,
                float* __restrict__ Su, float* __restrict__ Si,
                int ublocks, int gemm_blocks,
                const int* __restrict__ uids,
                const int* __restrict__ pos,
                const int* __restrict__ neg,
                const float* __restrict__ Eu,
                const float* __restrict__ Ei,
                const float* __restrict__ Gu,
                const float* __restrict__ Gi,
                const int* __restrict__ unpop,
                const int* __restrict__ popi,
                float* __restrict__ sc) {
    extern __shared__ char smc[];
    const int tid = threadIdx.x;

    if ((int)blockIdx.x >= gemm_blocks) {
        int gtid = ((int)blockIdx.x - gemm_blocks) * 256 + tid;
        int wid = gtid >> 5, lane = gtid & 31;
        if (wid < 512) {
            int b = wid, u = uids[b];
            float s = Gu[b * DD + lane] * Eu[(size_t)u * DD + lane]
                    + Gu[b * DD + 32 + lane] * Eu[(size_t)u * DD + 32 + lane];
            s = warp_sum(s);
            if (lane == 0) atomicAdd(&sc[1], fminf(fmaxf(s, -5.0f), 5.0f));
        } else if (wid < 1536) {
            int b = wid - 512;
            int id = (b < 512) ? pos[b] : neg[b - 512];
            float s = Gi[b * DD + lane] * Ei[(size_t)id * DD + lane]
                    + Gi[b * DD + 32 + lane] * Ei[(size_t)id * DD + 32 + lane];
            s = warp_sum(s);
            if (lane == 0) atomicAdd(&sc[2], fminf(fmaxf(s, -5.0f), 5.0f));
        } else if (wid < 2048) {
            int b = wid - 1536, u = uids[b], p = pos[b], nn = neg[b];
            float eu0 = Eu[(size_t)u * DD + lane], eu1 = Eu[(size_t)u * DD + 32 + lane];
            float sp = eu0 * Ei[(size_t)p * DD + lane]  + eu1 * Ei[(size_t)p * DD + 32 + lane];
            float sn = eu0 * Ei[(size_t)nn * DD + lane] + eu1 * Ei[(size_t)nn * DD + 32 + lane];
            sp = warp_sum(sp);
            sn = warp_sum(sn);
            if (lane == 0) {
                float x = sp - sn;
                float t = (x > 0.f) ? log1pf(expf(-x)) : (-x + log1pf(expf(x)));
                atomicAdd(&sc[3], t);
            }
        } else {
            int p = wid - 2048;
            if (p >= 64 * 8 * 32) return;
            int ig = p >> 8, rem = p & 255, ui = rem >> 5, pi = rem & 31;
            int a = unpop[ig * 8 + ui];
            int c = popi[ig * 32 + pi];
            float d0 = Ei[(size_t)a * DD + lane] - Ei[(size_t)c * DD + lane];
            float d1 = Ei[(size_t)a * DD + 32 + lane] - Ei[(size_t)c * DD + 32 + lane];
            float s = warp_sum(d0 * d0 + d1 * d1);
            if (lane == 0) atomicAdd(&sc[4], sqrtf(s));
        }
        return;
    }

    // ---------------- GEMM blocks ----------------
    const uint32_t sA = smem_u32(smc);
    const uint32_t sB = sA + 128 * 144;
    const bool isU = ((int)blockIdx.x < ublocks);
    const int bid = isU ? blockIdx.x : blockIdx.x - ublocks;
    const int Mtiles = isU ? 4 : 8;
    const int N = isU ? N_U : N_I;
    const __nv_bfloat16* Gb = isU ? Gbu : Gbi;
    const __nv_bfloat16* Eb = isU ? Ebu : Ebi;
    float* S = isU ? Su : Si;
    const int mt = bid % Mtiles;
    const long n0 = (long)(bid / Mtiles) * 128;

    #pragma unroll
    for (int it = 0; it < 4; it++) {
        int idx = it * 256 + tid;
        int row = idx >> 3, c = idx & 7;
        uint4 v = *(const uint4*)(Gb + ((size_t)(mt * 128 + row)) * DD + c * 8);
        *(uint4*)(smc + row * 144 + c * 16) = v;
    }
    #pragma unroll
    for (int it = 0; it < 4; it++) {
        int idx = it * 256 + tid;
        int row = idx >> 3, c = idx & 7;
        long n = n0 + row;
        uint4 v = make_uint4(0, 0, 0, 0);
        if (n < N) v = *(const uint4*)(Eb + n * DD + c * 8);
        *(uint4*)(smc + 128 * 144 + row * 144 + c * 16) = v;
    }
    __syncthreads();

    const int wid = tid >> 5, lane = tid & 31;
    const int wm = (wid & 3) * 32;
    const int wn = (wid >> 2) * 64;

    float d[2][8][4];
    #pragma unroll
    for (int mi = 0; mi < 2; mi++)
        #pragma unroll
        for (int ni = 0; ni < 8; ni++)
            #pragma unroll
            for (int j = 0; j < 4; j++) d[mi][ni][j] = 0.f;

    const int lrowA = (lane & 7) + ((lane & 8) ? 8 : 0);
    const int lcolA = (lane & 16) ? 8 : 0;
    const int lrowB = (lane & 7) + ((lane & 16) ? 8 : 0);
    const int lcolB = (lane & 8) ? 8 : 0;

    #pragma unroll
    for (int ks = 0; ks < 4; ks++) {
        const int k0 = ks * 16;
        unsigned a[2][4];
        #pragma unroll
        for (int mi = 0; mi < 2; mi++) {
            uint32_t addr = sA + (wm + mi * 16 + lrowA) * 144 + (k0 + lcolA) * 2;
            ldmx4(a[mi][0], a[mi][1], a[mi][2], a[mi][3], addr);
        }
        #pragma unroll
        for (int np = 0; np < 4; np++) {
            unsigned b[4];
            uint32_t addr = sB + (wn + np * 16 + lrowB) * 144 + (k0 + lcolB) * 2;
            ldmx4(b[0], b[1], b[2], b[3], addr);
            #pragma unroll
            for (int mi = 0; mi < 2; mi++) {
                mma16816(d[mi][np * 2 + 0], a[mi], b + 0);
                mma16816(d[mi][np * 2 + 1], a[mi], b + 2);
            }
        }
    }

    const bool full = (n0 + 128 <= N);
    const int r4 = lane >> 2;
    #pragma unroll
    for (int mi = 0; mi < 2; mi++) {
        float slo = 0.f, shi = 0.f;
        #pragma unroll
        for (int ni = 0; ni < 8; ni++) {
            if (full) {
                slo += __expf(d[mi][ni][0]) + __expf(d[mi][ni][1]);
                shi += __expf(d[mi][ni][2]) + __expf(d[mi][ni][3]);
            } else {
                long c = n0 + wn + ni * 8 + (lane & 3) * 2;
                if (c < N)     { slo += __expf(d[mi][ni][0]); shi += __expf(d[mi][ni][2]); }
                if (c + 1 < N) { slo += __expf(d[mi][ni][1]); shi += __expf(d[mi][ni][3]); }
            }
        }
        slo += __shfl_xor_sync(0xffffffffu, slo, 1);
        slo += __shfl_xor_sync(0xffffffffu, slo, 2);
        shi += __shfl_xor_sync(0xffffffffu, shi, 1);
        shi += __shfl_xor_sync(0xffffffffu, shi, 2);
        if ((lane & 3) == 0) {
            atomicAdd(&S[mt * 128 + wm + mi * 16 + r4], slo);
            atomicAdd(&S[mt * 128 + wm + mi * 16 + 8 + r4], shi);
        }
    }
}

// -------------------------------- finalize -----------------------------------
__global__ void finalize_kernel(const float* __restrict__ su,
                                const float* __restrict__ si,
                                const float* __restrict__ sc,
                                float* __restrict__ out) {
    __shared__ float s_lu[16], s_li[16];
    int tid = threadIdx.x;   // 512 threads
    float lu = logf(su[tid] + 1e-8f);
    float li = logf(si[tid] + 1e-8f) + logf(si[tid + 512] + 1e-8f);
    lu = warp_sum(lu);
    li = warp_sum(li);
    if ((tid & 31) == 0) { s_lu[tid >> 5] = lu; s_li[tid >> 5] = li; }
    __syncthreads();
    if (tid == 0) {
        float LU = 0.f, LI = 0.f;
        #pragma unroll
        for (int w = 0; w < 16; w++) { LU += s_lu[w]; LI += s_li[w]; }
        float neg_score = LU / 512.f + LI / 1024.f;
        float pos_score = sc[1] / 512.f + sc[2] / 1024.f;
        float loss_s = -pos_score + neg_score;
        float loss_r = sc[3] / 512.f;
        float loss_reg = 1e-7f * sc[0];
        float extra = sc[4] * (1.f / 32.f);
        float loss = loss_r + 0.2f * loss_s + loss_reg + 0.01f * extra;
        out[0] = loss;
        out[1] = loss_r;
        out[2] = 0.2f * loss_s;
    }
}

// ------------------------------- launcher ------------------------------------
extern "C" void kernel_launch(void* const* d_in, const int* in_sizes, int n_in,
                              void* d_out, int out_size) {
    const int*   uids     = (const int*)d_in[0];
    const int*   pos      = (const int*)d_in[1];
    const int*   neg      = (const int*)d_in[2];
    const int*   adj_rows = (const int*)d_in[3];
    const int*   adj_cols = (const int*)d_in[4];
    const float* adj_vals = (const float*)d_in[5];
    const float* E_u_0    = (const float*)d_in[6];
    const float* E_i_0    = (const float*)d_in[7];
    const float* u_mul_s  = (const float*)d_in[8];
    const float* vt       = (const float*)d_in[9];
    const float* v_mul_s  = (const float*)d_in[10];
    const float* ut       = (const float*)d_in[11];
    const float* W_api    = (const float*)d_in[12];
    const float* b_api    = (const float*)d_in[13];
    const float* W_mashup = (const float*)d_in[14];
    const float* b_mashup = (const float*)d_in[15];
    const float* pos_api  = (const float*)d_in[16];
    const float* neg_api  = (const float*)d_in[17];
    const float* mashup   = (const float*)d_in[18];
    const int*   unpop    = (const int*)d_in[19];
    const int*   popi     = (const int*)d_in[20];

    float* out = (float*)d_out;
    const size_t EMB = (size_t)EMBF;
    float* out_mashup = out + 3;
    float* out_posapi = out + 3 + EMB;
    float* out_negapi = out + 3 + 2 * EMB;
    float* Eu_out = out + 3 + 3 * EMB;

    float *Efb, *Sm, *G;
    __nv_bfloat16 *E0b, *Zbb, *Eb, *Gb;
    int *cnt, *rp, *off, *bsum;
    ull *epack;
    cudaGetSymbolAddress((void**)&E0b,  g_E0b);
    cudaGetSymbolAddress((void**)&Zbb,  g_Zb);
    cudaGetSymbolAddress((void**)&Efb,  g_Ef);
    cudaGetSymbolAddress((void**)&Eb,   g_Eb);
    cudaGetSymbolAddress((void**)&Sm,   g_small);
    cudaGetSymbolAddress((void**)&G,    g_G);
    cudaGetSymbolAddress((void**)&Gb,   g_Gb);
    cudaGetSymbolAddress((void**)&cnt,  g_cnt);
    cudaGetSymbolAddress((void**)&rp,   g_rp);
    cudaGetSymbolAddress((void**)&off,  g_off);
    cudaGetSymbolAddress((void**)&bsum, g_bsum);
    cudaGetSymbolAddress((void**)&epack, g_epack);

    float* Euf = Efb;
    float* Eif = Euf + (size_t)N_U * DD;
    __nv_bfloat16* Eub = Eb;
    __nv_bfloat16* Eib = Eub + (size_t)N_U * DD;
    float* Mu = Sm + OFF_MU;
    float* Mi = Sm + OFF_MI;
    float* su = Sm + OFF_SU;
    float* si = Sm + OFF_SI;
    float* sc = Sm + OFF_SC;
    float* Gu = G;
    float* Gi = G + (size_t)BB * DD;
    __nv_bfloat16* Gub = Gb;
    __nv_bfloat16* Gib = Gub + (size_t)BB * DD;

    cudaFuncSetAttribute(logits_mma,
                         cudaFuncAttributeMaxDynamicSharedMemorySize, SMEM_MMA);

    cudaMemsetAsync(cnt, 0, NR * 4);

    const size_t n4 = (size_t)NR * DD / 4;
    conv_hist_copy_k<<<(int)((n4 + 255) / 256), 256>>>(
        E_u_0, E_i_0, E0b, adj_rows, adj_cols, cnt,
        mashup, pos_api, neg_api, out_mashup, out_posapi, out_negapi);

    scan1_k<<<SCAN_NB, SCAN_BS>>>(cnt, bsum, Sm);
    scan3_k<<<SCAN_NB, SCAN_BS>>>(cnt, bsum, rp, off);
    scatter_k<<<((2 * NNZ_E / 8) + 255) / 256, 256>>>(adj_rows, adj_cols, adj_vals,
                                                      off, epack);

    const int csr_blocks = (NR * 16 + 255) / 256;   // half-warp per row
    spmm_csr_k<<<csr_blocks, 256>>>(rp, epack, E0b, Zbb);
    prep_slim<<<3072, 256>>>(E_u_0, E_i_0, Zbb, ut, vt, Mi, Mu, sc);
    spmm_csr_out_k<<<csr_blocks, 256>>>(rp, epack, Zbb, E_u_0, E_i_0,
                                        Efb, Eu_out, Eb);

    gsel_kernel<<<1536 + 192, 64>>>(uids, pos, neg, E_u_0, E_i_0,
                                    u_mul_s, v_mul_s, Mu, Mi, G, Gb,
                                    W_api, b_api, W_mashup, b_mashup, sc);

    const int ntu = (N_U + 127) / 128;   // 782
    const int nti = (N_I + 127) / 128;   // 391
    const int ublocks = 4 * ntu;
    const int gemm_blocks = ublocks + 8 * nti;
    logits_mma<<<gemm_blocks + 2304, 256, SMEM_MMA>>>(
        Gub, Gib, Eub, Eib, su, si, ublocks, gemm_blocks,
        uids, pos, neg, Euf, Eif, Gu, Gi, unpop, popi, sc);

    finalize_kernel<<<1, 512>>>(su, si, sc, out);
}